// round 1
// baseline (speedup 1.0000x reference)
#include <cuda_runtime.h>
#include <math.h>

#define Bb 8
#define Ll 9216
#define Cc 512
#define Mm (Bb*Ll)          // 73728
#define HEADS 8
#define DK 64
#define DV 64
#define HID 2048

// ---------------- scratch (device globals; no runtime allocation) -------------
__device__ float g_xn[(size_t)Mm*Cc];
__device__ float g_vn[(size_t)Mm*Cc];
__device__ float g_q [(size_t)Mm*Cc];
__device__ float g_k [(size_t)Mm*Cc];
__device__ float g_val[(size_t)Mm*Cc];
__device__ float g_h [(size_t)Mm*HID];
__device__ float g_ctx[Bb*HEADS*DK*DV];
__device__ float g_cmax[Bb*Cc];
__device__ float g_csum[Bb*Cc];

// ---------------- LayerNorm: one warp per row of 512 --------------------------
__global__ __launch_bounds__(256) void ln_kernel(const float* __restrict__ x,
                                                 const float* __restrict__ w,
                                                 const float* __restrict__ b,
                                                 float* __restrict__ y)
{
    int row = blockIdx.x * 8 + (threadIdx.x >> 5);
    int lane = threadIdx.x & 31;
    const float* xr = x + (size_t)row * Cc;
    float4 v[4];
    float s = 0.f, s2 = 0.f;
#pragma unroll
    for (int i = 0; i < 4; i++) {
        v[i] = *(const float4*)(xr + lane * 4 + i * 128);
        s  += v[i].x + v[i].y + v[i].z + v[i].w;
        s2 += v[i].x*v[i].x + v[i].y*v[i].y + v[i].z*v[i].z + v[i].w*v[i].w;
    }
#pragma unroll
    for (int o = 16; o; o >>= 1) {
        s  += __shfl_xor_sync(0xffffffffu, s,  o);
        s2 += __shfl_xor_sync(0xffffffffu, s2, o);
    }
    float mean = s * (1.f/512.f);
    float var  = s2 * (1.f/512.f) - mean*mean;
    float rstd = rsqrtf(var + 1e-5f);
    float* yr = y + (size_t)row * Cc;
#pragma unroll
    for (int i = 0; i < 4; i++) {
        int c = lane * 4 + i * 128;
        float4 wv = *(const float4*)(w + c);
        float4 bv = *(const float4*)(b + c);
        float4 o4;
        o4.x = (v[i].x - mean) * rstd * wv.x + bv.x;
        o4.y = (v[i].y - mean) * rstd * wv.y + bv.y;
        o4.z = (v[i].z - mean) * rstd * wv.z + bv.z;
        o4.w = (v[i].w - mean) * rstd * wv.w + bv.w;
        *(float4*)(yr + c) = o4;
    }
}

// -------- generic SGEMM: out[m,n] = sum_k A[m,k]*W[n,k] + bias[n] (+resid)(+gelu)
__global__ __launch_bounds__(256) void gemm_epi(const float* __restrict__ A,
                                                const float* __restrict__ Wt,
                                                const float* __restrict__ bias,
                                                const float* __restrict__ resid,
                                                float* __restrict__ out,
                                                int Nd, int Kd, int do_gelu)
{
    __shared__ float As[16][132];
    __shared__ float Bs[16][132];
    const int tid = threadIdx.x;
    const int bm = blockIdx.y * 128;
    const int bn = blockIdx.x * 128;
    const int tx = tid & 15;
    const int ty = tid >> 4;
    float acc[8][8];
#pragma unroll
    for (int i = 0; i < 8; i++)
#pragma unroll
        for (int j = 0; j < 8; j++) acc[i][j] = 0.f;

    for (int k0 = 0; k0 < Kd; k0 += 16) {
#pragma unroll
        for (int i = 0; i < 2; i++) {
            int idx = tid + i * 256;
            int r  = idx >> 2;
            int c4 = (idx & 3) << 2;
            float4 va = *(const float4*)(A  + (size_t)(bm + r) * Kd + k0 + c4);
            As[c4+0][r] = va.x; As[c4+1][r] = va.y; As[c4+2][r] = va.z; As[c4+3][r] = va.w;
            float4 vb = *(const float4*)(Wt + (size_t)(bn + r) * Kd + k0 + c4);
            Bs[c4+0][r] = vb.x; Bs[c4+1][r] = vb.y; Bs[c4+2][r] = vb.z; Bs[c4+3][r] = vb.w;
        }
        __syncthreads();
#pragma unroll
        for (int k = 0; k < 16; k++) {
            float ra[8], rb[8];
#pragma unroll
            for (int i = 0; i < 8; i++) ra[i] = As[k][ty*8 + i];
#pragma unroll
            for (int j = 0; j < 8; j++) rb[j] = Bs[k][tx*8 + j];
#pragma unroll
            for (int i = 0; i < 8; i++)
#pragma unroll
                for (int j = 0; j < 8; j++)
                    acc[i][j] += ra[i] * rb[j];
        }
        __syncthreads();
    }
#pragma unroll
    for (int i = 0; i < 8; i++) {
        int m = bm + ty*8 + i;
#pragma unroll
        for (int j = 0; j < 8; j++) {
            int n = bn + tx*8 + j;
            float v = acc[i][j] + bias[n];
            if (resid) v += resid[(size_t)m * Nd + n];
            if (do_gelu) v = 0.5f * v * (1.f + erff(v * 0.70710678118654752f));
            out[(size_t)m * Nd + n] = v;
        }
    }
}

// -------- column softmax stats over L (online max/sum) ------------------------
__global__ void ksm_stats(const float* __restrict__ k,
                          float* __restrict__ cmax, float* __restrict__ csum)
{
    int b  = blockIdx.x;
    int ch = blockIdx.y * 32 + threadIdx.x;
    float m = -1e30f, s = 0.f;
    for (int l = threadIdx.y; l < Ll; l += 8) {
        float v = k[((size_t)b * Ll + l) * Cc + ch];
        if (v > m) { s = s * expf(m - v) + 1.f; m = v; }
        else       { s += expf(v - m); }
    }
    __shared__ float sm[8][32], ss[8][32];
    sm[threadIdx.y][threadIdx.x] = m;
    ss[threadIdx.y][threadIdx.x] = s;
    __syncthreads();
    if (threadIdx.y == 0) {
        for (int i = 1; i < 8; i++) {
            float m2 = sm[i][threadIdx.x], s2 = ss[i][threadIdx.x];
            if (m2 > m) { s = s * expf(m - m2) + s2; m = m2; }
            else        { s += s2 * expf(m2 - m); }
        }
        cmax[b * Cc + ch] = m;
        csum[b * Cc + ch] = s;
    }
}

// -------- context[bh,kc,vc] = sum_l softmax_L(k)[l,kc] * val[l,vc] -------------
__global__ __launch_bounds__(256) void context_kernel(const float* __restrict__ k,
                                                      const float* __restrict__ val,
                                                      const float* __restrict__ cmax,
                                                      const float* __restrict__ csum,
                                                      float* __restrict__ ctx)
{
    int bh = blockIdx.x;
    int b = bh >> 3, h = bh & 7;
    int ch0 = h * 64;
    __shared__ float ks[16][64], vs[16][64];
    __shared__ float smax[64], ssum[64];
    int tid = threadIdx.x;
    int tx = tid & 15, ty = tid >> 4;
    if (tid < 64) { smax[tid] = cmax[b * Cc + ch0 + tid]; ssum[tid] = csum[b * Cc + ch0 + tid]; }
    __syncthreads();
    float acc[4][4];
#pragma unroll
    for (int i = 0; i < 4; i++)
#pragma unroll
        for (int j = 0; j < 4; j++) acc[i][j] = 0.f;

    for (int l0 = 0; l0 < Ll; l0 += 16) {
#pragma unroll
        for (int i = 0; i < 4; i++) {
            int idx = tid + i * 256;
            int r = idx >> 6;
            int c = idx & 63;
            size_t off = ((size_t)b * Ll + l0 + r) * Cc + ch0 + c;
            ks[r][c] = expf(k[off] - smax[c]) / ssum[c];
            vs[r][c] = val[off];
        }
        __syncthreads();
#pragma unroll
        for (int kk = 0; kk < 16; kk++) {
            float rk[4], rv[4];
#pragma unroll
            for (int i = 0; i < 4; i++) rk[i] = ks[kk][ty*4 + i];
#pragma unroll
            for (int j = 0; j < 4; j++) rv[j] = vs[kk][tx*4 + j];
#pragma unroll
            for (int i = 0; i < 4; i++)
#pragma unroll
                for (int j = 0; j < 4; j++)
                    acc[i][j] += rk[i] * rv[j];
        }
        __syncthreads();
    }
#pragma unroll
    for (int i = 0; i < 4; i++)
#pragma unroll
        for (int j = 0; j < 4; j++)
            ctx[((size_t)bh * 64 + ty*4 + i) * 64 + tx*4 + j] = acc[i][j];
}

// -------- per-token softmax over 64 q channels + 64x64 matvec against ctx ------
__global__ __launch_bounds__(256) void attend_kernel(const float* __restrict__ q,
                                                     const float* __restrict__ ctx,
                                                     float* __restrict__ att)
{
    int bh = blockIdx.x;
    int b = bh >> 3, h = bh & 7;
    __shared__ float c_s[64][65];
    int tid = threadIdx.x;
    for (int i = tid; i < 4096; i += 256)
        c_s[i >> 6][i & 63] = ctx[(size_t)bh * 4096 + i];
    __syncthreads();
    int warp = tid >> 5, lane = tid & 31;
    int l_base = blockIdx.y * 64 + warp * 8;
#pragma unroll 1
    for (int li = 0; li < 8; li++) {
        int l = l_base + li;
        size_t qoff = ((size_t)b * Ll + l) * Cc + h * 64;
        float q0 = q[qoff + lane];
        float q1 = q[qoff + 32 + lane];
        float m = fmaxf(q0, q1);
#pragma unroll
        for (int o = 16; o; o >>= 1) m = fmaxf(m, __shfl_xor_sync(0xffffffffu, m, o));
        float e0 = expf(q0 - m), e1 = expf(q1 - m);
        float s = e0 + e1;
#pragma unroll
        for (int o = 16; o; o >>= 1) s += __shfl_xor_sync(0xffffffffu, s, o);
        float inv = 1.f / s;
        e0 *= inv; e1 *= inv;
        float a0 = 0.f, a1 = 0.f;
#pragma unroll
        for (int kc = 0; kc < 32; kc++) {
            float qv = __shfl_sync(0xffffffffu, e0, kc);
            a0 += c_s[kc][lane]      * qv;
            a1 += c_s[kc][lane + 32] * qv;
        }
#pragma unroll
        for (int kc = 0; kc < 32; kc++) {
            float qv = __shfl_sync(0xffffffffu, e1, kc);
            a0 += c_s[kc + 32][lane]      * qv;
            a1 += c_s[kc + 32][lane + 32] * qv;
        }
        att[qoff + lane]      = a0;
        att[qoff + 32 + lane] = a1;
    }
}

// -------- torch .view scramble: x1.flat[b, c*L+l] = t[b,l,c] + x.flat ---------
__global__ void scramble_kernel(const float* __restrict__ t,
                                const float* __restrict__ x,
                                float* __restrict__ x1)
{
    __shared__ float tile[32][33];
    int b = blockIdx.z;
    int l0 = blockIdx.x * 32, c0 = blockIdx.y * 32;
    const float* tb = t + (size_t)b * Ll * Cc;
    for (int i = threadIdx.y; i < 32; i += 8)
        tile[i][threadIdx.x] = tb[(size_t)(l0 + i) * Cc + c0 + threadIdx.x];
    __syncthreads();
    float* ob = x1 + (size_t)b * Ll * Cc;
    const float* xb = x + (size_t)b * Ll * Cc;
    for (int i = threadIdx.y; i < 32; i += 8) {
        size_t flat = (size_t)(c0 + i) * Ll + l0 + threadIdx.x;
        ob[flat] = tile[threadIdx.x][i] + xb[flat];
    }
}

// ------------------------------- driver ---------------------------------------
extern "C" void kernel_launch(void* const* d_in, const int* in_sizes, int n_in,
                              void* d_out, int out_size)
{
    const float* x     = (const float*)d_in[0];
    const float* v     = (const float*)d_in[1];
    const float* ln1w  = (const float*)d_in[4];
    const float* ln1b  = (const float*)d_in[5];
    const float* lnvw  = (const float*)d_in[6];
    const float* lnvb  = (const float*)d_in[7];
    const float* ln2w  = (const float*)d_in[8];
    const float* ln2b  = (const float*)d_in[9];
    const float* wq    = (const float*)d_in[10];
    const float* bq    = (const float*)d_in[11];
    const float* wk    = (const float*)d_in[12];
    const float* bk    = (const float*)d_in[13];
    const float* wv    = (const float*)d_in[14];
    const float* bv    = (const float*)d_in[15];
    const float* wr    = (const float*)d_in[16];
    const float* br    = (const float*)d_in[17];
    const float* fc1w  = (const float*)d_in[18];
    const float* fc1b  = (const float*)d_in[19];
    const float* fc2w  = (const float*)d_in[20];
    const float* fc2b  = (const float*)d_in[21];
    float* out = (float*)d_out;

    float *p_xn, *p_vn, *p_q, *p_k, *p_val, *p_h, *p_ctx, *p_cmax, *p_csum;
    cudaGetSymbolAddress((void**)&p_xn,  g_xn);
    cudaGetSymbolAddress((void**)&p_vn,  g_vn);
    cudaGetSymbolAddress((void**)&p_q,   g_q);
    cudaGetSymbolAddress((void**)&p_k,   g_k);
    cudaGetSymbolAddress((void**)&p_val, g_val);
    cudaGetSymbolAddress((void**)&p_h,   g_h);
    cudaGetSymbolAddress((void**)&p_ctx, g_ctx);
    cudaGetSymbolAddress((void**)&p_cmax, g_cmax);
    cudaGetSymbolAddress((void**)&p_csum, g_csum);

    dim3 g512(Cc / 128, Mm / 128);     // (4, 576)
    dim3 g2048(HID / 128, Mm / 128);   // (16, 576)

    // LN1 on x and v
    ln_kernel<<<Mm / 8, 256>>>(x, ln1w, ln1b, p_xn);
    ln_kernel<<<Mm / 8, 256>>>(v, lnvw, lnvb, p_vn);

    // q/k/val projections
    gemm_epi<<<g512, 256>>>(p_xn, wq, bq, nullptr, p_q,   Cc, Cc, 0);
    gemm_epi<<<g512, 256>>>(p_vn, wk, bk, nullptr, p_k,   Cc, Cc, 0);
    gemm_epi<<<g512, 256>>>(p_vn, wv, bv, nullptr, p_val, Cc, Cc, 0);

    // softmax over L for k  (stats), then context = k_sm^T @ val per (b,h)
    ksm_stats<<<dim3(Bb, Cc / 32), dim3(32, 8)>>>(p_k, p_cmax, p_csum);
    context_kernel<<<Bb * HEADS, 256>>>(p_k, p_val, p_cmax, p_csum, p_ctx);

    // q softmax over head channels + attend; att written into g_k (k consumed)
    attend_kernel<<<dim3(Bb * HEADS, Ll / 64), 256>>>(p_q, p_ctx, p_k);

    // reprojection: t = att @ wr^T + br + xn   (into g_q)
    gemm_epi<<<g512, 256>>>(p_k, wr, br, p_xn, p_q, Cc, Cc, 0);

    // scramble (batched transpose) + shortcut -> x1 stored in d_out
    scramble_kernel<<<dim3(Ll / 32, Cc / 32, Bb), dim3(32, 8)>>>(p_q, x, out);

    // LN2 -> MLP with exact GELU, final residual fused into fc2 epilogue
    ln_kernel<<<Mm / 8, 256>>>(out, ln2w, ln2b, p_xn);
    gemm_epi<<<g2048, 256>>>(p_xn, fc1w, fc1b, nullptr, p_h, HID, Cc, 1);
    gemm_epi<<<g512, 256>>>(p_h, fc2w, fc2b, out, out, Cc, HID, 0);
}

// round 3
// speedup vs baseline: 1.9650x; 1.9650x over previous
#include <cuda_runtime.h>
#include <cuda_bf16.h>
#include <math.h>
#include <stdint.h>

#define Bb 8
#define Ll 9216
#define Cc 512
#define Mm (Bb*Ll)          // 73728
#define HEADS 8
#define HID 2048

// ---------------- scratch (device globals; no runtime allocation) -------------
__device__ __align__(16) float g_q  [(size_t)Mm*Cc];
__device__ __align__(16) float g_k  [(size_t)Mm*Cc];
__device__ __align__(16) float g_val[(size_t)Mm*Cc];
__device__ __align__(16) __nv_bfloat16 g_xnh[(size_t)Mm*Cc];
__device__ __align__(16) __nv_bfloat16 g_xnl[(size_t)Mm*Cc];
__device__ __align__(16) __nv_bfloat16 g_vnh[(size_t)Mm*Cc];
__device__ __align__(16) __nv_bfloat16 g_vnl[(size_t)Mm*Cc];
__device__ __align__(16) __nv_bfloat16 g_atth[(size_t)Mm*Cc];
__device__ __align__(16) __nv_bfloat16 g_attl[(size_t)Mm*Cc];
__device__ __align__(16) __nv_bfloat16 g_hh[(size_t)Mm*HID];
__device__ __align__(16) __nv_bfloat16 g_hl[(size_t)Mm*HID];
__device__ __align__(16) __nv_bfloat16 g_wqh[Cc*Cc], g_wql[Cc*Cc];
__device__ __align__(16) __nv_bfloat16 g_wkh[Cc*Cc], g_wkl[Cc*Cc];
__device__ __align__(16) __nv_bfloat16 g_wvh[Cc*Cc], g_wvl[Cc*Cc];
__device__ __align__(16) __nv_bfloat16 g_wrh[Cc*Cc], g_wrl[Cc*Cc];
__device__ __align__(16) __nv_bfloat16 g_f1h[HID*Cc], g_f1l[HID*Cc];
__device__ __align__(16) __nv_bfloat16 g_f2h[Cc*HID], g_f2l[Cc*HID];
__device__ float g_ctx[Bb*HEADS*64*64];
__device__ float g_cmax[Bb*Cc];
__device__ float g_csum[Bb*Cc];

// ---------------- small helpers ----------------
__device__ __forceinline__ unsigned short bfb(float x) {
    return __bfloat16_as_ushort(__float2bfloat16_rn(x));
}
__device__ __forceinline__ float bff(__nv_bfloat16 t) { return __bfloat162float(t); }
__device__ __forceinline__ uint32_t smem_u32(const void* p) {
    return (uint32_t)__cvta_generic_to_shared(p);
}
__device__ __forceinline__ void cp16(uint32_t dst, const void* src) {
    asm volatile("cp.async.cg.shared.global [%0], [%1], 16;" :: "r"(dst), "l"(src));
}
#define CP_COMMIT() asm volatile("cp.async.commit_group;" ::: "memory")
#define CP_WAIT(N)  asm volatile("cp.async.wait_group %0;" :: "n"(N) : "memory")

#define LDSM4(r0, r1, r2, r3, addr) \
    asm volatile("ldmatrix.sync.aligned.m8n8.x4.shared.b16 {%0,%1,%2,%3}, [%4];" \
                 : "=r"(r0), "=r"(r1), "=r"(r2), "=r"(r3) : "r"(addr))

#define MMA_BF16(d, a, b) \
    asm volatile("mma.sync.aligned.m16n8k16.row.col.f32.bf16.bf16.f32 " \
                 "{%0,%1,%2,%3}, {%4,%5,%6,%7}, {%8,%9}, {%0,%1,%2,%3};" \
                 : "+f"((d)[0]), "+f"((d)[1]), "+f"((d)[2]), "+f"((d)[3]) \
                 : "r"((a)[0]), "r"((a)[1]), "r"((a)[2]), "r"((a)[3]), \
                   "r"((b)[0]), "r"((b)[1]))

// ---------------- LayerNorm -> bf16 hi/lo split outputs -----------------------
__global__ __launch_bounds__(256) void ln_pair(const float* __restrict__ x,
                                               const float* __restrict__ w,
                                               const float* __restrict__ b,
                                               __nv_bfloat16* __restrict__ yh,
                                               __nv_bfloat16* __restrict__ yl)
{
    int row = blockIdx.x * 8 + (threadIdx.x >> 5);
    int lane = threadIdx.x & 31;
    const float* xr = x + (size_t)row * Cc;
    float4 v[4];
    float s = 0.f, s2 = 0.f;
#pragma unroll
    for (int i = 0; i < 4; i++) {
        v[i] = *(const float4*)(xr + lane * 4 + i * 128);
        s  += v[i].x + v[i].y + v[i].z + v[i].w;
        s2 += v[i].x*v[i].x + v[i].y*v[i].y + v[i].z*v[i].z + v[i].w*v[i].w;
    }
#pragma unroll
    for (int o = 16; o; o >>= 1) {
        s  += __shfl_xor_sync(0xffffffffu, s,  o);
        s2 += __shfl_xor_sync(0xffffffffu, s2, o);
    }
    float mean = s * (1.f/512.f);
    float var  = s2 * (1.f/512.f) - mean*mean;
    float rstd = rsqrtf(var + 1e-5f);
#pragma unroll
    for (int i = 0; i < 4; i++) {
        int c = lane * 4 + i * 128;
        float4 wv = *(const float4*)(w + c);
        float4 bv = *(const float4*)(b + c);
        float o0 = (v[i].x - mean) * rstd * wv.x + bv.x;
        float o1 = (v[i].y - mean) * rstd * wv.y + bv.y;
        float o2 = (v[i].z - mean) * rstd * wv.z + bv.z;
        float o3 = (v[i].w - mean) * rstd * wv.w + bv.w;
        ushort4 sh, sl;
        sh.x = bfb(o0); sl.x = bfb(o0 - bff(__ushort_as_bfloat16(sh.x)));
        sh.y = bfb(o1); sl.y = bfb(o1 - bff(__ushort_as_bfloat16(sh.y)));
        sh.z = bfb(o2); sl.z = bfb(o2 - bff(__ushort_as_bfloat16(sh.z)));
        sh.w = bfb(o3); sl.w = bfb(o3 - bff(__ushort_as_bfloat16(sh.w)));
        *(ushort4*)(yh + (size_t)row * Cc + c) = sh;
        *(ushort4*)(yl + (size_t)row * Cc + c) = sl;
    }
}

// ---------------- weight fp32 -> bf16 hi/lo -----------------------------------
__global__ void split_kernel(const float* __restrict__ w,
                             __nv_bfloat16* __restrict__ hi,
                             __nv_bfloat16* __restrict__ lo, int n)
{
    int i = blockIdx.x * 256 + threadIdx.x;
    if (i < n) {
        float x = w[i];
        __nv_bfloat16 h = __float2bfloat16_rn(x);
        hi[i] = h;
        lo[i] = __float2bfloat16_rn(x - __bfloat162float(h));
    }
}

// ------------- bf16 mma.sync GEMM, 3-term compensated --------------------------
// out[m,n] = sum_k A[m,k]*W[n,k] (+bias)(+resid)(+gelu); A,W as bf16 hi/lo pairs
#define TILEB 16384          // one 128x64 bf16 tile in bytes
#define STAGEB (4*TILEB)     // Ahi,Alo,Bhi,Blo
#define SMEM_SZ (2*STAGEB)   // double buffered = 131072

__global__ __launch_bounds__(256) void gemm_mma(
    const __nv_bfloat16* __restrict__ Ahi, const __nv_bfloat16* __restrict__ Alo,
    const __nv_bfloat16* __restrict__ Bhi, const __nv_bfloat16* __restrict__ Blo,
    const float* __restrict__ bias,
    const float* __restrict__ residf,
    const __nv_bfloat16* __restrict__ resph, const __nv_bfloat16* __restrict__ respl,
    float* __restrict__ outf,
    __nv_bfloat16* __restrict__ outh, __nv_bfloat16* __restrict__ outl,
    int Nd, int Kd, int do_gelu)
{
    extern __shared__ __align__(1024) char smarr[];
    const int tid = threadIdx.x;
    const int lane = tid & 31;
    const int wid = tid >> 5;
    const int bm = blockIdx.y * 128;
    const int bn = blockIdx.x * 128;
    const int wm = (wid >> 2) * 64;    // 0 or 64
    const int wn = (wid & 3) * 32;     // 0..96
    const uint32_t smb = smem_u32(smarr);

    const int cpc = tid & 7;           // chunk col 0..7
    const int cpr = tid >> 3;          // row base 0..31

    float acc[4][4][4];
#pragma unroll
    for (int i = 0; i < 4; i++)
#pragma unroll
        for (int j = 0; j < 4; j++)
#pragma unroll
            for (int r = 0; r < 4; r++) acc[i][j][r] = 0.f;

    const int nchunks = Kd >> 6;

    // ---- prefetch chunk 0 into stage 0
    {
        const int k0 = 0;
        uint32_t sb = smb;
#pragma unroll
        for (int p = 0; p < 4; p++) {
            int r = cpr + p * 32;
            int off = r * 128 + cpc * 16;
            int sw = off ^ ((off >> 3) & 0x70);
            size_t ga = (size_t)(bm + r) * Kd + k0 + cpc * 8;
            size_t gb = (size_t)(bn + r) * Kd + k0 + cpc * 8;
            cp16(sb + sw,             Ahi + ga);
            cp16(sb + TILEB + sw,     Alo + ga);
            cp16(sb + 2*TILEB + sw,   Bhi + gb);
            cp16(sb + 3*TILEB + sw,   Blo + gb);
        }
        CP_COMMIT();
    }

    const int lrow = (lane & 7) + ((lane >> 3) & 1) * 8;
    const int lhalf = lane >> 4;

    for (int kc = 0; kc < nchunks; kc++) {
        if (kc + 1 < nchunks) {
            const int k0 = (kc + 1) << 6;
            uint32_t sb = smb + ((kc + 1) & 1) * STAGEB;
#pragma unroll
            for (int p = 0; p < 4; p++) {
                int r = cpr + p * 32;
                int off = r * 128 + cpc * 16;
                int sw = off ^ ((off >> 3) & 0x70);
                size_t ga = (size_t)(bm + r) * Kd + k0 + cpc * 8;
                size_t gb = (size_t)(bn + r) * Kd + k0 + cpc * 8;
                cp16(sb + sw,             Ahi + ga);
                cp16(sb + TILEB + sw,     Alo + ga);
                cp16(sb + 2*TILEB + sw,   Bhi + gb);
                cp16(sb + 3*TILEB + sw,   Blo + gb);
            }
            CP_COMMIT();
            CP_WAIT(1);
        } else {
            CP_WAIT(0);
        }
        __syncthreads();

        uint32_t sb = smb + (kc & 1) * STAGEB;
#pragma unroll
        for (int ks = 0; ks < 4; ks++) {
            uint32_t ahi[4][4], alo[4][4];
#pragma unroll
            for (int mi = 0; mi < 4; mi++) {
                int row = wm + mi * 16 + lrow;
                int off = row * 128 + (ks * 2 + lhalf) * 16;
                int sw = off ^ ((off >> 3) & 0x70);
                LDSM4(ahi[mi][0], ahi[mi][1], ahi[mi][2], ahi[mi][3], sb + sw);
                LDSM4(alo[mi][0], alo[mi][1], alo[mi][2], alo[mi][3], sb + TILEB + sw);
            }
            uint32_t bhi[4][2], blo[4][2];
#pragma unroll
            for (int nj2 = 0; nj2 < 2; nj2++) {
                int row = wn + nj2 * 16 + lrow;
                int off = row * 128 + (ks * 2 + lhalf) * 16;
                int sw = off ^ ((off >> 3) & 0x70);
                uint32_t r0, r1, r2, r3;
                LDSM4(r0, r1, r2, r3, sb + 2*TILEB + sw);
                bhi[nj2*2+0][0] = r0; bhi[nj2*2+0][1] = r2;
                bhi[nj2*2+1][0] = r1; bhi[nj2*2+1][1] = r3;
                LDSM4(r0, r1, r2, r3, sb + 3*TILEB + sw);
                blo[nj2*2+0][0] = r0; blo[nj2*2+0][1] = r2;
                blo[nj2*2+1][0] = r1; blo[nj2*2+1][1] = r3;
            }
#pragma unroll
            for (int mi = 0; mi < 4; mi++)
#pragma unroll
                for (int nj = 0; nj < 4; nj++) {
                    MMA_BF16(acc[mi][nj], ahi[mi], bhi[nj]);
                    MMA_BF16(acc[mi][nj], ahi[mi], blo[nj]);
                    MMA_BF16(acc[mi][nj], alo[mi], bhi[nj]);
                }
        }
        __syncthreads();
    }

    // ---------------- epilogue ----------------
#pragma unroll
    for (int mi = 0; mi < 4; mi++)
#pragma unroll
        for (int nj = 0; nj < 4; nj++) {
            int n = bn + wn + nj * 8 + 2 * (lane & 3);
            float b0 = bias[n], b1 = bias[n + 1];
#pragma unroll
            for (int r = 0; r < 2; r++) {
                int m = bm + wm + mi * 16 + (lane >> 2) + r * 8;
                size_t idx = (size_t)m * Nd + n;
                float v0 = acc[mi][nj][r*2+0] + b0;
                float v1 = acc[mi][nj][r*2+1] + b1;
                if (residf) {
                    float2 rr = *(const float2*)(residf + idx);
                    v0 += rr.x; v1 += rr.y;
                }
                if (resph) {
                    uint32_t ph = *(const uint32_t*)((const unsigned short*)resph + idx);
                    uint32_t pl = *(const uint32_t*)((const unsigned short*)respl + idx);
                    v0 += bff(__ushort_as_bfloat16((unsigned short)(ph & 0xffff)))
                        + bff(__ushort_as_bfloat16((unsigned short)(pl & 0xffff)));
                    v1 += bff(__ushort_as_bfloat16((unsigned short)(ph >> 16)))
                        + bff(__ushort_as_bfloat16((unsigned short)(pl >> 16)));
                }
                if (do_gelu) {
                    v0 = 0.5f * v0 * (1.f + erff(v0 * 0.70710678118654752f));
                    v1 = 0.5f * v1 * (1.f + erff(v1 * 0.70710678118654752f));
                }
                if (outf) *(float2*)(outf + idx) = make_float2(v0, v1);
                if (outh) {
                    unsigned short h0 = bfb(v0), h1 = bfb(v1);
                    float r0f = v0 - bff(__ushort_as_bfloat16(h0));
                    float r1f = v1 - bff(__ushort_as_bfloat16(h1));
                    *(uint32_t*)((unsigned short*)outh + idx) =
                        (uint32_t)h0 | ((uint32_t)h1 << 16);
                    *(uint32_t*)((unsigned short*)outl + idx) =
                        (uint32_t)bfb(r0f) | ((uint32_t)bfb(r1f) << 16);
                }
            }
        }
}

// -------- column softmax stats over L (online max/sum) ------------------------
__global__ void ksm_stats(const float* __restrict__ k,
                          float* __restrict__ cmax, float* __restrict__ csum)
{
    int b  = blockIdx.x;
    int ch = blockIdx.y * 32 + threadIdx.x;
    float m = -1e30f, s = 0.f;
    for (int l = threadIdx.y; l < Ll; l += 8) {
        float v = k[((size_t)b * Ll + l) * Cc + ch];
        if (v > m) { s = s * expf(m - v) + 1.f; m = v; }
        else       { s += expf(v - m); }
    }
    __shared__ float sm[8][32], ss[8][32];
    sm[threadIdx.y][threadIdx.x] = m;
    ss[threadIdx.y][threadIdx.x] = s;
    __syncthreads();
    if (threadIdx.y == 0) {
        for (int i = 1; i < 8; i++) {
            float m2 = sm[i][threadIdx.x], s2 = ss[i][threadIdx.x];
            if (m2 > m) { s = s * expf(m - m2) + s2; m = m2; }
            else        { s += s2 * expf(m2 - m); }
        }
        cmax[b * Cc + ch] = m;
        csum[b * Cc + ch] = s;
    }
}

// -------- context[bh,kc,vc] = sum_l softmax_L(k)[l,kc] * val[l,vc] -------------
__global__ __launch_bounds__(256) void context_kernel(const float* __restrict__ k,
                                                      const float* __restrict__ val,
                                                      const float* __restrict__ cmax,
                                                      const float* __restrict__ csum,
                                                      float* __restrict__ ctx)
{
    int bh = blockIdx.x;
    int b = bh >> 3, h = bh & 7;
    int ch0 = h * 64;
    __shared__ float ks[16][64], vs[16][64];
    __shared__ float smax[64], ssum[64];
    int tid = threadIdx.x;
    int tx = tid & 15, ty = tid >> 4;
    if (tid < 64) { smax[tid] = cmax[b * Cc + ch0 + tid]; ssum[tid] = csum[b * Cc + ch0 + tid]; }
    __syncthreads();
    float acc[4][4];
#pragma unroll
    for (int i = 0; i < 4; i++)
#pragma unroll
        for (int j = 0; j < 4; j++) acc[i][j] = 0.f;

    for (int l0 = 0; l0 < Ll; l0 += 16) {
#pragma unroll
        for (int i = 0; i < 4; i++) {
            int idx = tid + i * 256;
            int r = idx >> 6;
            int c = idx & 63;
            size_t off = ((size_t)b * Ll + l0 + r) * Cc + ch0 + c;
            ks[r][c] = expf(k[off] - smax[c]) / ssum[c];
            vs[r][c] = val[off];
        }
        __syncthreads();
#pragma unroll
        for (int kk = 0; kk < 16; kk++) {
            float rk[4], rv[4];
#pragma unroll
            for (int i = 0; i < 4; i++) rk[i] = ks[kk][ty*4 + i];
#pragma unroll
            for (int j = 0; j < 4; j++) rv[j] = vs[kk][tx*4 + j];
#pragma unroll
            for (int i = 0; i < 4; i++)
#pragma unroll
                for (int j = 0; j < 4; j++)
                    acc[i][j] += rk[i] * rv[j];
        }
        __syncthreads();
    }
#pragma unroll
    for (int i = 0; i < 4; i++)
#pragma unroll
        for (int j = 0; j < 4; j++)
            ctx[((size_t)bh * 64 + ty*4 + i) * 64 + tx*4 + j] = acc[i][j];
}

// -------- per-token softmax over 64 q channels + 64x64 matvec, split output ----
__global__ __launch_bounds__(256) void attend_kernel(const float* __restrict__ q,
                                                     const float* __restrict__ ctx,
                                                     __nv_bfloat16* __restrict__ ah,
                                                     __nv_bfloat16* __restrict__ al)
{
    int bh = blockIdx.x;
    int b = bh >> 3, h = bh & 7;
    __shared__ float c_s[64][65];
    int tid = threadIdx.x;
    for (int i = tid; i < 4096; i += 256)
        c_s[i >> 6][i & 63] = ctx[(size_t)bh * 4096 + i];
    __syncthreads();
    int warp = tid >> 5, lane = tid & 31;
    int l_base = blockIdx.y * 64 + warp * 8;
#pragma unroll 1
    for (int li = 0; li < 8; li++) {
        int l = l_base + li;
        size_t qoff = ((size_t)b * Ll + l) * Cc + h * 64;
        float q0 = q[qoff + lane];
        float q1 = q[qoff + 32 + lane];
        float m = fmaxf(q0, q1);
#pragma unroll
        for (int o = 16; o; o >>= 1) m = fmaxf(m, __shfl_xor_sync(0xffffffffu, m, o));
        float e0 = expf(q0 - m), e1 = expf(q1 - m);
        float s = e0 + e1;
#pragma unroll
        for (int o = 16; o; o >>= 1) s += __shfl_xor_sync(0xffffffffu, s, o);
        float inv = 1.f / s;
        e0 *= inv; e1 *= inv;
        float a0 = 0.f, a1 = 0.f;
#pragma unroll
        for (int kc = 0; kc < 32; kc++) {
            float qv = __shfl_sync(0xffffffffu, e0, kc);
            a0 += c_s[kc][lane]      * qv;
            a1 += c_s[kc][lane + 32] * qv;
        }
#pragma unroll
        for (int kc = 0; kc < 32; kc++) {
            float qv = __shfl_sync(0xffffffffu, e1, kc);
            a0 += c_s[kc + 32][lane]      * qv;
            a1 += c_s[kc + 32][lane + 32] * qv;
        }
        __nv_bfloat16 h0 = __float2bfloat16_rn(a0);
        __nv_bfloat16 h1 = __float2bfloat16_rn(a1);
        ah[qoff + lane]      = h0;
        ah[qoff + 32 + lane] = h1;
        al[qoff + lane]      = __float2bfloat16_rn(a0 - __bfloat162float(h0));
        al[qoff + 32 + lane] = __float2bfloat16_rn(a1 - __bfloat162float(h1));
    }
}

// -------- torch .view scramble: x1.flat[b, c*L+l] = t[b,l,c] + x.flat ---------
__global__ void scramble_kernel(const float* __restrict__ t,
                                const float* __restrict__ x,
                                float* __restrict__ x1)
{
    __shared__ float tile[32][33];
    int b = blockIdx.z;
    int l0 = blockIdx.x * 32, c0 = blockIdx.y * 32;
    const float* tb = t + (size_t)b * Ll * Cc;
    for (int i = threadIdx.y; i < 32; i += 8)
        tile[i][threadIdx.x] = tb[(size_t)(l0 + i) * Cc + c0 + threadIdx.x];
    __syncthreads();
    float* ob = x1 + (size_t)b * Ll * Cc;
    const float* xb = x + (size_t)b * Ll * Cc;
    for (int i = threadIdx.y; i < 32; i += 8) {
        size_t flat = (size_t)(c0 + i) * Ll + l0 + threadIdx.x;
        ob[flat] = tile[threadIdx.x][i] + xb[flat];
    }
}

// ------------------------------- driver ---------------------------------------
extern "C" void kernel_launch(void* const* d_in, const int* in_sizes, int n_in,
                              void* d_out, int out_size)
{
    const float* x     = (const float*)d_in[0];
    const float* v     = (const float*)d_in[1];
    const float* ln1w  = (const float*)d_in[4];
    const float* ln1b  = (const float*)d_in[5];
    const float* lnvw  = (const float*)d_in[6];
    const float* lnvb  = (const float*)d_in[7];
    const float* ln2w  = (const float*)d_in[8];
    const float* ln2b  = (const float*)d_in[9];
    const float* wq    = (const float*)d_in[10];
    const float* bq    = (const float*)d_in[11];
    const float* wk    = (const float*)d_in[12];
    const float* bk    = (const float*)d_in[13];
    const float* wv    = (const float*)d_in[14];
    const float* bv    = (const float*)d_in[15];
    const float* wr    = (const float*)d_in[16];
    const float* br    = (const float*)d_in[17];
    const float* fc1w  = (const float*)d_in[18];
    const float* fc1b  = (const float*)d_in[19];
    const float* fc2w  = (const float*)d_in[20];
    const float* fc2b  = (const float*)d_in[21];
    float* out = (float*)d_out;

    float *p_q, *p_k, *p_val, *p_ctx, *p_cmax, *p_csum;
    __nv_bfloat16 *p_xnh, *p_xnl, *p_vnh, *p_vnl, *p_ath, *p_atl, *p_hh, *p_hl;
    __nv_bfloat16 *p_wqh, *p_wql, *p_wkh, *p_wkl, *p_wvh, *p_wvl, *p_wrh, *p_wrl;
    __nv_bfloat16 *p_f1h, *p_f1l, *p_f2h, *p_f2l;
    cudaGetSymbolAddress((void**)&p_q,   g_q);
    cudaGetSymbolAddress((void**)&p_k,   g_k);
    cudaGetSymbolAddress((void**)&p_val, g_val);
    cudaGetSymbolAddress((void**)&p_ctx, g_ctx);
    cudaGetSymbolAddress((void**)&p_cmax, g_cmax);
    cudaGetSymbolAddress((void**)&p_csum, g_csum);
    cudaGetSymbolAddress((void**)&p_xnh, g_xnh);
    cudaGetSymbolAddress((void**)&p_xnl, g_xnl);
    cudaGetSymbolAddress((void**)&p_vnh, g_vnh);
    cudaGetSymbolAddress((void**)&p_vnl, g_vnl);
    cudaGetSymbolAddress((void**)&p_ath, g_atth);
    cudaGetSymbolAddress((void**)&p_atl, g_attl);
    cudaGetSymbolAddress((void**)&p_hh,  g_hh);
    cudaGetSymbolAddress((void**)&p_hl,  g_hl);
    cudaGetSymbolAddress((void**)&p_wqh, g_wqh); cudaGetSymbolAddress((void**)&p_wql, g_wql);
    cudaGetSymbolAddress((void**)&p_wkh, g_wkh); cudaGetSymbolAddress((void**)&p_wkl, g_wkl);
    cudaGetSymbolAddress((void**)&p_wvh, g_wvh); cudaGetSymbolAddress((void**)&p_wvl, g_wvl);
    cudaGetSymbolAddress((void**)&p_wrh, g_wrh); cudaGetSymbolAddress((void**)&p_wrl, g_wrl);
    cudaGetSymbolAddress((void**)&p_f1h, g_f1h); cudaGetSymbolAddress((void**)&p_f1l, g_f1l);
    cudaGetSymbolAddress((void**)&p_f2h, g_f2h); cudaGetSymbolAddress((void**)&p_f2l, g_f2l);

    cudaFuncSetAttribute(gemm_mma, cudaFuncAttributeMaxDynamicSharedMemorySize, SMEM_SZ);

    dim3 g512(Cc / 128, Mm / 128);     // (4, 576)
    dim3 g2048(HID / 128, Mm / 128);   // (16, 576)

    // LN1 on x and v -> bf16 pairs
    ln_pair<<<Mm / 8, 256>>>(x, ln1w, ln1b, p_xnh, p_xnl);
    ln_pair<<<Mm / 8, 256>>>(v, lnvw, lnvb, p_vnh, p_vnl);

    // weight splits
    split_kernel<<<(Cc*Cc + 255)/256, 256>>>(wq, p_wqh, p_wql, Cc*Cc);
    split_kernel<<<(Cc*Cc + 255)/256, 256>>>(wk, p_wkh, p_wkl, Cc*Cc);
    split_kernel<<<(Cc*Cc + 255)/256, 256>>>(wv, p_wvh, p_wvl, Cc*Cc);
    split_kernel<<<(Cc*Cc + 255)/256, 256>>>(wr, p_wrh, p_wrl, Cc*Cc);
    split_kernel<<<(HID*Cc + 255)/256, 256>>>(fc1w, p_f1h, p_f1l, HID*Cc);
    split_kernel<<<(Cc*HID + 255)/256, 256>>>(fc2w, p_f2h, p_f2l, Cc*HID);

    // q/k/val projections (tensor cores)
    gemm_mma<<<g512, 256, SMEM_SZ>>>(p_xnh, p_xnl, p_wqh, p_wql, bq,
                                     nullptr, nullptr, nullptr, p_q, nullptr, nullptr, Cc, Cc, 0);
    gemm_mma<<<g512, 256, SMEM_SZ>>>(p_vnh, p_vnl, p_wkh, p_wkl, bk,
                                     nullptr, nullptr, nullptr, p_k, nullptr, nullptr, Cc, Cc, 0);
    gemm_mma<<<g512, 256, SMEM_SZ>>>(p_vnh, p_vnl, p_wvh, p_wvl, bv,
                                     nullptr, nullptr, nullptr, p_val, nullptr, nullptr, Cc, Cc, 0);

    // attention core
    ksm_stats<<<dim3(Bb, Cc / 32), dim3(32, 8)>>>(p_k, p_cmax, p_csum);
    context_kernel<<<Bb * HEADS, 256>>>(p_k, p_val, p_cmax, p_csum, p_ctx);
    attend_kernel<<<dim3(Bb * HEADS, Ll / 64), 256>>>(p_q, p_ctx, p_ath, p_atl);

    // reprojection: t = att @ wr^T + br + xn  -> fp32 in g_q
    gemm_mma<<<g512, 256, SMEM_SZ>>>(p_ath, p_atl, p_wrh, p_wrl, br,
                                     nullptr, p_xnh, p_xnl, p_q, nullptr, nullptr, Cc, Cc, 0);

    // scramble (batched transpose) + shortcut -> x1 in d_out
    scramble_kernel<<<dim3(Ll / 32, Cc / 32, Bb), dim3(32, 8)>>>(p_q, x, out);

    // LN2 -> pairs (reuse xn pair buffers)
    ln_pair<<<Mm / 8, 256>>>(out, ln2w, ln2b, p_xnh, p_xnl);

    // MLP: fc1 (+exact GELU, split output), fc2 (+residual from d_out)
    gemm_mma<<<g2048, 256, SMEM_SZ>>>(p_xnh, p_xnl, p_f1h, p_f1l, fc1b,
                                      nullptr, nullptr, nullptr, nullptr, p_hh, p_hl, HID, Cc, 1);
    gemm_mma<<<g512, 256, SMEM_SZ>>>(p_hh, p_hl, p_f2h, p_f2l, fc2b,
                                     out, nullptr, nullptr, out, nullptr, nullptr, Cc, HID, 0);
}

// round 4
// speedup vs baseline: 3.5599x; 1.8116x over previous
#include <cuda_runtime.h>
#include <cuda_fp16.h>
#include <math.h>
#include <stdint.h>

#define Bb 8
#define Ll 9216
#define Cc 512
#define Mm (Bb*Ll)          // 73728
#define HEADS 8
#define HID 2048

// ---------------- scratch (device globals; no runtime allocation) -------------
__device__ __align__(16) float g_q  [(size_t)Mm*Cc];
__device__ __align__(16) float g_k  [(size_t)Mm*Cc];
__device__ __align__(16) float g_val[(size_t)Mm*Cc];
__device__ __align__(16) __half g_xnh[(size_t)Mm*Cc];
__device__ __align__(16) __half g_xnl[(size_t)Mm*Cc];
__device__ __align__(16) __half g_vnh[(size_t)Mm*Cc];
__device__ __align__(16) __half g_vnl[(size_t)Mm*Cc];
__device__ __align__(16) __half g_atth[(size_t)Mm*Cc];
__device__ __align__(16) __half g_attl[(size_t)Mm*Cc];
__device__ __align__(16) __half g_hh[(size_t)Mm*HID];
__device__ __align__(16) __half g_hl[(size_t)Mm*HID];
__device__ __align__(16) __half g_wq16[Cc*Cc];
__device__ __align__(16) __half g_wk16[Cc*Cc];
__device__ __align__(16) __half g_wv16[Cc*Cc];
__device__ __align__(16) __half g_wr16[Cc*Cc];
__device__ __align__(16) __half g_f116[HID*Cc];
__device__ __align__(16) __half g_f216[Cc*HID];
__device__ float g_ctx[Bb*HEADS*64*64];
__device__ float g_cmax[Bb*Cc];
__device__ float g_csum[Bb*Cc];

// ---------------- small helpers ----------------
__device__ __forceinline__ unsigned short hfb(float x) {
    return __half_as_ushort(__float2half_rn(x));
}
__device__ __forceinline__ float hff(__half t) { return __half2float(t); }
__device__ __forceinline__ uint32_t smem_u32(const void* p) {
    return (uint32_t)__cvta_generic_to_shared(p);
}
__device__ __forceinline__ void cp16(uint32_t dst, const void* src) {
    asm volatile("cp.async.cg.shared.global [%0], [%1], 16;" :: "r"(dst), "l"(src));
}
#define CP_COMMIT() asm volatile("cp.async.commit_group;" ::: "memory")
#define CP_WAIT(N)  asm volatile("cp.async.wait_group %0;" :: "n"(N) : "memory")

#define LDSM4(r0, r1, r2, r3, addr) \
    asm volatile("ldmatrix.sync.aligned.m8n8.x4.shared.b16 {%0,%1,%2,%3}, [%4];" \
                 : "=r"(r0), "=r"(r1), "=r"(r2), "=r"(r3) : "r"(addr))

#define MMA_F16(d, a, b) \
    asm volatile("mma.sync.aligned.m16n8k16.row.col.f32.f16.f16.f32 " \
                 "{%0,%1,%2,%3}, {%4,%5,%6,%7}, {%8,%9}, {%0,%1,%2,%3};" \
                 : "+f"((d)[0]), "+f"((d)[1]), "+f"((d)[2]), "+f"((d)[3]) \
                 : "r"((a)[0]), "r"((a)[1]), "r"((a)[2]), "r"((a)[3]), \
                   "r"((b)[0]), "r"((b)[1]))

// ---------------- LayerNorm -> fp16 hi/lo split outputs -----------------------
__global__ __launch_bounds__(256) void ln_pair(const float* __restrict__ x,
                                               const float* __restrict__ w,
                                               const float* __restrict__ b,
                                               __half* __restrict__ yh,
                                               __half* __restrict__ yl)
{
    int row = blockIdx.x * 8 + (threadIdx.x >> 5);
    int lane = threadIdx.x & 31;
    const float* xr = x + (size_t)row * Cc;
    float4 v[4];
    float s = 0.f, s2 = 0.f;
#pragma unroll
    for (int i = 0; i < 4; i++) {
        v[i] = *(const float4*)(xr + lane * 4 + i * 128);
        s  += v[i].x + v[i].y + v[i].z + v[i].w;
        s2 += v[i].x*v[i].x + v[i].y*v[i].y + v[i].z*v[i].z + v[i].w*v[i].w;
    }
#pragma unroll
    for (int o = 16; o; o >>= 1) {
        s  += __shfl_xor_sync(0xffffffffu, s,  o);
        s2 += __shfl_xor_sync(0xffffffffu, s2, o);
    }
    float mean = s * (1.f/512.f);
    float var  = s2 * (1.f/512.f) - mean*mean;
    float rstd = rsqrtf(var + 1e-5f);
#pragma unroll
    for (int i = 0; i < 4; i++) {
        int c = lane * 4 + i * 128;
        float4 wv = *(const float4*)(w + c);
        float4 bv = *(const float4*)(b + c);
        float o0 = (v[i].x - mean) * rstd * wv.x + bv.x;
        float o1 = (v[i].y - mean) * rstd * wv.y + bv.y;
        float o2 = (v[i].z - mean) * rstd * wv.z + bv.z;
        float o3 = (v[i].w - mean) * rstd * wv.w + bv.w;
        ushort4 sh, sl;
        sh.x = hfb(o0); sl.x = hfb(o0 - hff(__ushort_as_half(sh.x)));
        sh.y = hfb(o1); sl.y = hfb(o1 - hff(__ushort_as_half(sh.y)));
        sh.z = hfb(o2); sl.z = hfb(o2 - hff(__ushort_as_half(sh.z)));
        sh.w = hfb(o3); sl.w = hfb(o3 - hff(__ushort_as_half(sh.w)));
        *(ushort4*)(yh + (size_t)row * Cc + c) = sh;
        *(ushort4*)(yl + (size_t)row * Cc + c) = sl;
    }
}

// ---------------- weight fp32 -> fp16 -----------------------------------------
__global__ void convert_kernel(const float* __restrict__ w,
                               __half* __restrict__ o, int n)
{
    int i = blockIdx.x * 256 + threadIdx.x;
    if (i < n) o[i] = __float2half_rn(w[i]);
}

// ------------- fp16 mma.sync GEMM, 2-term compensated --------------------------
// out[m,n] = sum_k A[m,k]*W[n,k] (+bias)(+resid)(+gelu); A as fp16 hi/lo pair,
// W rounded to fp16.
#define TILEB 16384          // one 128x64 fp16 tile in bytes
#define STAGEB (3*TILEB)     // Ahi, Alo, B
#define SMEM_SZ (2*STAGEB)   // double buffered = 98304

__global__ __launch_bounds__(256, 2) void gemm_mma(
    const __half* __restrict__ Ahi, const __half* __restrict__ Alo,
    const __half* __restrict__ Bw,
    const float* __restrict__ bias,
    const float* __restrict__ residf,
    const __half* __restrict__ resph, const __half* __restrict__ respl,
    float* __restrict__ outf,
    __half* __restrict__ outh, __half* __restrict__ outl,
    int Nd, int Kd, int do_gelu)
{
    extern __shared__ __align__(1024) char smarr[];
    const int tid = threadIdx.x;
    const int lane = tid & 31;
    const int wid = tid >> 5;
    const int bm = blockIdx.y * 128;
    const int bn = blockIdx.x * 128;
    const int wm = (wid >> 2) * 64;    // 0 or 64
    const int wn = (wid & 3) * 32;     // 0..96
    const uint32_t smb = smem_u32(smarr);

    const int cpc = tid & 7;           // chunk col 0..7
    const int cpr = tid >> 3;          // row base 0..31

    float acc[4][4][4];
#pragma unroll
    for (int i = 0; i < 4; i++)
#pragma unroll
        for (int j = 0; j < 4; j++)
#pragma unroll
            for (int r = 0; r < 4; r++) acc[i][j][r] = 0.f;

    const int nchunks = Kd >> 6;

    // ---- prefetch chunk 0 into stage 0
    {
        uint32_t sb = smb;
#pragma unroll
        for (int p = 0; p < 4; p++) {
            int r = cpr + p * 32;
            int off = r * 128 + cpc * 16;
            int sw = off ^ ((off >> 3) & 0x70);
            size_t ga = (size_t)(bm + r) * Kd + cpc * 8;
            size_t gb = (size_t)(bn + r) * Kd + cpc * 8;
            cp16(sb + sw,           Ahi + ga);
            cp16(sb + TILEB + sw,   Alo + ga);
            cp16(sb + 2*TILEB + sw, Bw  + gb);
        }
        CP_COMMIT();
    }

    const int lrow = (lane & 7) + ((lane >> 3) & 1) * 8;
    const int lhalf = lane >> 4;

    for (int kc = 0; kc < nchunks; kc++) {
        if (kc + 1 < nchunks) {
            const int k0 = (kc + 1) << 6;
            uint32_t sb = smb + ((kc + 1) & 1) * STAGEB;
#pragma unroll
            for (int p = 0; p < 4; p++) {
                int r = cpr + p * 32;
                int off = r * 128 + cpc * 16;
                int sw = off ^ ((off >> 3) & 0x70);
                size_t ga = (size_t)(bm + r) * Kd + k0 + cpc * 8;
                size_t gb = (size_t)(bn + r) * Kd + k0 + cpc * 8;
                cp16(sb + sw,           Ahi + ga);
                cp16(sb + TILEB + sw,   Alo + ga);
                cp16(sb + 2*TILEB + sw, Bw  + gb);
            }
            CP_COMMIT();
            CP_WAIT(1);
        } else {
            CP_WAIT(0);
        }
        __syncthreads();

        uint32_t sb = smb + (kc & 1) * STAGEB;
#pragma unroll
        for (int ks = 0; ks < 4; ks++) {
            uint32_t ahi[4][4], alo[4][4];
#pragma unroll
            for (int mi = 0; mi < 4; mi++) {
                int row = wm + mi * 16 + lrow;
                int off = row * 128 + (ks * 2 + lhalf) * 16;
                int sw = off ^ ((off >> 3) & 0x70);
                LDSM4(ahi[mi][0], ahi[mi][1], ahi[mi][2], ahi[mi][3], sb + sw);
                LDSM4(alo[mi][0], alo[mi][1], alo[mi][2], alo[mi][3], sb + TILEB + sw);
            }
            uint32_t bw[4][2];
#pragma unroll
            for (int nj2 = 0; nj2 < 2; nj2++) {
                int row = wn + nj2 * 16 + lrow;
                int off = row * 128 + (ks * 2 + lhalf) * 16;
                int sw = off ^ ((off >> 3) & 0x70);
                uint32_t r0, r1, r2, r3;
                LDSM4(r0, r1, r2, r3, sb + 2*TILEB + sw);
                bw[nj2*2+0][0] = r0; bw[nj2*2+0][1] = r2;
                bw[nj2*2+1][0] = r1; bw[nj2*2+1][1] = r3;
            }
#pragma unroll
            for (int mi = 0; mi < 4; mi++)
#pragma unroll
                for (int nj = 0; nj < 4; nj++) {
                    MMA_F16(acc[mi][nj], ahi[mi], bw[nj]);
                    MMA_F16(acc[mi][nj], alo[mi], bw[nj]);
                }
        }
        __syncthreads();
    }

    // ---------------- epilogue ----------------
#pragma unroll
    for (int mi = 0; mi < 4; mi++)
#pragma unroll
        for (int nj = 0; nj < 4; nj++) {
            int n = bn + wn + nj * 8 + 2 * (lane & 3);
            float b0 = bias[n], b1 = bias[n + 1];
#pragma unroll
            for (int r = 0; r < 2; r++) {
                int m = bm + wm + mi * 16 + (lane >> 2) + r * 8;
                size_t idx = (size_t)m * Nd + n;
                float v0 = acc[mi][nj][r*2+0] + b0;
                float v1 = acc[mi][nj][r*2+1] + b1;
                if (residf) {
                    float2 rr = *(const float2*)(residf + idx);
                    v0 += rr.x; v1 += rr.y;
                }
                if (resph) {
                    uint32_t ph = *(const uint32_t*)((const unsigned short*)resph + idx);
                    uint32_t pl = *(const uint32_t*)((const unsigned short*)respl + idx);
                    v0 += hff(__ushort_as_half((unsigned short)(ph & 0xffff)))
                        + hff(__ushort_as_half((unsigned short)(pl & 0xffff)));
                    v1 += hff(__ushort_as_half((unsigned short)(ph >> 16)))
                        + hff(__ushort_as_half((unsigned short)(pl >> 16)));
                }
                if (do_gelu) {
                    v0 = 0.5f * v0 * (1.f + erff(v0 * 0.70710678118654752f));
                    v1 = 0.5f * v1 * (1.f + erff(v1 * 0.70710678118654752f));
                }
                if (outf) *(float2*)(outf + idx) = make_float2(v0, v1);
                if (outh) {
                    unsigned short h0 = hfb(v0), h1 = hfb(v1);
                    float r0f = v0 - hff(__ushort_as_half(h0));
                    float r1f = v1 - hff(__ushort_as_half(h1));
                    *(uint32_t*)((unsigned short*)outh + idx) =
                        (uint32_t)h0 | ((uint32_t)h1 << 16);
                    *(uint32_t*)((unsigned short*)outl + idx) =
                        (uint32_t)hfb(r0f) | ((uint32_t)hfb(r1f) << 16);
                }
            }
        }
}

// -------- column softmax stats over L (online max/sum) ------------------------
__global__ void ksm_stats(const float* __restrict__ k,
                          float* __restrict__ cmax, float* __restrict__ csum)
{
    int b  = blockIdx.x;
    int ch = blockIdx.y * 32 + threadIdx.x;
    float m = -1e30f, s = 0.f;
    for (int l = threadIdx.y; l < Ll; l += 8) {
        float v = k[((size_t)b * Ll + l) * Cc + ch];
        if (v > m) { s = s * expf(m - v) + 1.f; m = v; }
        else       { s += expf(v - m); }
    }
    __shared__ float sm[8][32], ss[8][32];
    sm[threadIdx.y][threadIdx.x] = m;
    ss[threadIdx.y][threadIdx.x] = s;
    __syncthreads();
    if (threadIdx.y == 0) {
        for (int i = 1; i < 8; i++) {
            float m2 = sm[i][threadIdx.x], s2 = ss[i][threadIdx.x];
            if (m2 > m) { s = s * expf(m - m2) + s2; m = m2; }
            else        { s += s2 * expf(m2 - m); }
        }
        cmax[b * Cc + ch] = m;
        csum[b * Cc + ch] = s;
    }
}

// -------- context partial: atomicAdd over L segments ---------------------------
__global__ __launch_bounds__(256) void context_kernel(const float* __restrict__ k,
                                                      const float* __restrict__ val,
                                                      const float* __restrict__ cmax,
                                                      const float* __restrict__ csum,
                                                      float* __restrict__ ctx)
{
    int bh = blockIdx.x;
    int b = bh >> 3, h = bh & 7;
    int ch0 = h * 64;
    int seg = blockIdx.y;
    const int SEG = Ll / 8;            // 1152
    __shared__ float ks[16][64], vs[16][64];
    __shared__ float smax[64], ssum[64];
    int tid = threadIdx.x;
    int tx = tid & 15, ty = tid >> 4;
    if (tid < 64) { smax[tid] = cmax[b * Cc + ch0 + tid]; ssum[tid] = csum[b * Cc + ch0 + tid]; }
    __syncthreads();
    float acc[4][4];
#pragma unroll
    for (int i = 0; i < 4; i++)
#pragma unroll
        for (int j = 0; j < 4; j++) acc[i][j] = 0.f;

    for (int l0 = seg * SEG; l0 < (seg + 1) * SEG; l0 += 16) {
#pragma unroll
        for (int i = 0; i < 4; i++) {
            int idx = tid + i * 256;
            int r = idx >> 6;
            int c = idx & 63;
            size_t off = ((size_t)b * Ll + l0 + r) * Cc + ch0 + c;
            ks[r][c] = expf(k[off] - smax[c]) / ssum[c];
            vs[r][c] = val[off];
        }
        __syncthreads();
#pragma unroll
        for (int kk = 0; kk < 16; kk++) {
            float rk[4], rv[4];
#pragma unroll
            for (int i = 0; i < 4; i++) rk[i] = ks[kk][ty*4 + i];
#pragma unroll
            for (int j = 0; j < 4; j++) rv[j] = vs[kk][tx*4 + j];
#pragma unroll
            for (int i = 0; i < 4; i++)
#pragma unroll
                for (int j = 0; j < 4; j++)
                    acc[i][j] += rk[i] * rv[j];
        }
        __syncthreads();
    }
#pragma unroll
    for (int i = 0; i < 4; i++)
#pragma unroll
        for (int j = 0; j < 4; j++)
            atomicAdd(&ctx[((size_t)bh * 64 + ty*4 + i) * 64 + tx*4 + j], acc[i][j]);
}

// -------- per-token softmax over 64 q channels + 64x64 matvec, split output ----
__global__ __launch_bounds__(256) void attend_kernel(const float* __restrict__ q,
                                                     const float* __restrict__ ctx,
                                                     __half* __restrict__ ah,
                                                     __half* __restrict__ al)
{
    int bh = blockIdx.x;
    int b = bh >> 3, h = bh & 7;
    __shared__ float c_s[64][65];
    int tid = threadIdx.x;
    for (int i = tid; i < 4096; i += 256)
        c_s[i >> 6][i & 63] = ctx[(size_t)bh * 4096 + i];
    __syncthreads();
    int warp = tid >> 5, lane = tid & 31;
    int l_base = blockIdx.y * 64 + warp * 8;
#pragma unroll 1
    for (int li = 0; li < 8; li++) {
        int l = l_base + li;
        size_t qoff = ((size_t)b * Ll + l) * Cc + h * 64;
        float q0 = q[qoff + lane];
        float q1 = q[qoff + 32 + lane];
        float m = fmaxf(q0, q1);
#pragma unroll
        for (int o = 16; o; o >>= 1) m = fmaxf(m, __shfl_xor_sync(0xffffffffu, m, o));
        float e0 = expf(q0 - m), e1 = expf(q1 - m);
        float s = e0 + e1;
#pragma unroll
        for (int o = 16; o; o >>= 1) s += __shfl_xor_sync(0xffffffffu, s, o);
        float inv = 1.f / s;
        e0 *= inv; e1 *= inv;
        float a0 = 0.f, a1 = 0.f;
#pragma unroll
        for (int kc = 0; kc < 32; kc++) {
            float qv = __shfl_sync(0xffffffffu, e0, kc);
            a0 += c_s[kc][lane]      * qv;
            a1 += c_s[kc][lane + 32] * qv;
        }
#pragma unroll
        for (int kc = 0; kc < 32; kc++) {
            float qv = __shfl_sync(0xffffffffu, e1, kc);
            a0 += c_s[kc + 32][lane]      * qv;
            a1 += c_s[kc + 32][lane + 32] * qv;
        }
        __half h0 = __float2half_rn(a0);
        __half h1 = __float2half_rn(a1);
        ah[qoff + lane]      = h0;
        ah[qoff + 32 + lane] = h1;
        al[qoff + lane]      = __float2half_rn(a0 - __half2float(h0));
        al[qoff + 32 + lane] = __float2half_rn(a1 - __half2float(h1));
    }
}

// -------- torch .view scramble: x1.flat[b, c*L+l] = t[b,l,c] + x.flat ---------
__global__ void scramble_kernel(const float* __restrict__ t,
                                const float* __restrict__ x,
                                float* __restrict__ x1)
{
    __shared__ float tile[32][33];
    int b = blockIdx.z;
    int l0 = blockIdx.x * 32, c0 = blockIdx.y * 32;
    const float* tb = t + (size_t)b * Ll * Cc;
    for (int i = threadIdx.y; i < 32; i += 8)
        tile[i][threadIdx.x] = tb[(size_t)(l0 + i) * Cc + c0 + threadIdx.x];
    __syncthreads();
    float* ob = x1 + (size_t)b * Ll * Cc;
    const float* xb = x + (size_t)b * Ll * Cc;
    for (int i = threadIdx.y; i < 32; i += 8) {
        size_t flat = (size_t)(c0 + i) * Ll + l0 + threadIdx.x;
        ob[flat] = tile[threadIdx.x][i] + xb[flat];
    }
}

// ------------------------------- driver ---------------------------------------
extern "C" void kernel_launch(void* const* d_in, const int* in_sizes, int n_in,
                              void* d_out, int out_size)
{
    const float* x     = (const float*)d_in[0];
    const float* v     = (const float*)d_in[1];
    const float* ln1w  = (const float*)d_in[4];
    const float* ln1b  = (const float*)d_in[5];
    const float* lnvw  = (const float*)d_in[6];
    const float* lnvb  = (const float*)d_in[7];
    const float* ln2w  = (const float*)d_in[8];
    const float* ln2b  = (const float*)d_in[9];
    const float* wq    = (const float*)d_in[10];
    const float* bq    = (const float*)d_in[11];
    const float* wk    = (const float*)d_in[12];
    const float* bk    = (const float*)d_in[13];
    const float* wv    = (const float*)d_in[14];
    const float* bv    = (const float*)d_in[15];
    const float* wr    = (const float*)d_in[16];
    const float* br    = (const float*)d_in[17];
    const float* fc1w  = (const float*)d_in[18];
    const float* fc1b  = (const float*)d_in[19];
    const float* fc2w  = (const float*)d_in[20];
    const float* fc2b  = (const float*)d_in[21];
    float* out = (float*)d_out;

    float *p_q, *p_k, *p_val, *p_ctx, *p_cmax, *p_csum;
    __half *p_xnh, *p_xnl, *p_vnh, *p_vnl, *p_ath, *p_atl, *p_hh, *p_hl;
    __half *p_wq, *p_wk, *p_wv, *p_wr, *p_f1, *p_f2;
    cudaGetSymbolAddress((void**)&p_q,   g_q);
    cudaGetSymbolAddress((void**)&p_k,   g_k);
    cudaGetSymbolAddress((void**)&p_val, g_val);
    cudaGetSymbolAddress((void**)&p_ctx, g_ctx);
    cudaGetSymbolAddress((void**)&p_cmax, g_cmax);
    cudaGetSymbolAddress((void**)&p_csum, g_csum);
    cudaGetSymbolAddress((void**)&p_xnh, g_xnh);
    cudaGetSymbolAddress((void**)&p_xnl, g_xnl);
    cudaGetSymbolAddress((void**)&p_vnh, g_vnh);
    cudaGetSymbolAddress((void**)&p_vnl, g_vnl);
    cudaGetSymbolAddress((void**)&p_ath, g_atth);
    cudaGetSymbolAddress((void**)&p_atl, g_attl);
    cudaGetSymbolAddress((void**)&p_hh,  g_hh);
    cudaGetSymbolAddress((void**)&p_hl,  g_hl);
    cudaGetSymbolAddress((void**)&p_wq, g_wq16);
    cudaGetSymbolAddress((void**)&p_wk, g_wk16);
    cudaGetSymbolAddress((void**)&p_wv, g_wv16);
    cudaGetSymbolAddress((void**)&p_wr, g_wr16);
    cudaGetSymbolAddress((void**)&p_f1, g_f116);
    cudaGetSymbolAddress((void**)&p_f2, g_f216);

    cudaFuncSetAttribute(gemm_mma, cudaFuncAttributeMaxDynamicSharedMemorySize, SMEM_SZ);

    dim3 g512(Cc / 128, Mm / 128);     // (4, 576)
    dim3 g2048(HID / 128, Mm / 128);   // (16, 576)

    // weight converts + LN1 pairs
    convert_kernel<<<(Cc*Cc + 255)/256, 256>>>(wq, p_wq, Cc*Cc);
    convert_kernel<<<(Cc*Cc + 255)/256, 256>>>(wk, p_wk, Cc*Cc);
    convert_kernel<<<(Cc*Cc + 255)/256, 256>>>(wv, p_wv, Cc*Cc);
    convert_kernel<<<(Cc*Cc + 255)/256, 256>>>(wr, p_wr, Cc*Cc);
    convert_kernel<<<(HID*Cc + 255)/256, 256>>>(fc1w, p_f1, HID*Cc);
    convert_kernel<<<(Cc*HID + 255)/256, 256>>>(fc2w, p_f2, Cc*HID);
    ln_pair<<<Mm / 8, 256>>>(x, ln1w, ln1b, p_xnh, p_xnl);
    ln_pair<<<Mm / 8, 256>>>(v, lnvw, lnvb, p_vnh, p_vnl);

    // q/k/val projections (tensor cores)
    gemm_mma<<<g512, 256, SMEM_SZ>>>(p_xnh, p_xnl, p_wq, bq,
                                     nullptr, nullptr, nullptr, p_q, nullptr, nullptr, Cc, Cc, 0);
    gemm_mma<<<g512, 256, SMEM_SZ>>>(p_vnh, p_vnl, p_wk, bk,
                                     nullptr, nullptr, nullptr, p_k, nullptr, nullptr, Cc, Cc, 0);
    gemm_mma<<<g512, 256, SMEM_SZ>>>(p_vnh, p_vnl, p_wv, bv,
                                     nullptr, nullptr, nullptr, p_val, nullptr, nullptr, Cc, Cc, 0);

    // attention core
    ksm_stats<<<dim3(Bb, Cc / 32), dim3(32, 8)>>>(p_k, p_cmax, p_csum);
    cudaMemsetAsync(p_ctx, 0, (size_t)Bb*HEADS*64*64*sizeof(float));
    context_kernel<<<dim3(Bb * HEADS, 8), 256>>>(p_k, p_val, p_cmax, p_csum, p_ctx);
    attend_kernel<<<dim3(Bb * HEADS, Ll / 64), 256>>>(p_q, p_ctx, p_ath, p_atl);

    // reprojection: t = att @ wr^T + br + xn  -> fp32 in g_q
    gemm_mma<<<g512, 256, SMEM_SZ>>>(p_ath, p_atl, p_wr, br,
                                     nullptr, p_xnh, p_xnl, p_q, nullptr, nullptr, Cc, Cc, 0);

    // scramble (batched transpose) + shortcut -> x1 in d_out
    scramble_kernel<<<dim3(Ll / 32, Cc / 32, Bb), dim3(32, 8)>>>(p_q, x, out);

    // LN2 -> pairs (reuse xn pair buffers)
    ln_pair<<<Mm / 8, 256>>>(out, ln2w, ln2b, p_xnh, p_xnl);

    // MLP: fc1 (+exact GELU, split output), fc2 (+residual from d_out)
    gemm_mma<<<g2048, 256, SMEM_SZ>>>(p_xnh, p_xnl, p_f1, fc1b,
                                      nullptr, nullptr, nullptr, nullptr, p_hh, p_hl, HID, Cc, 1);
    gemm_mma<<<g512, 256, SMEM_SZ>>>(p_hh, p_hl, p_f2, fc2b,
                                     out, nullptr, nullptr, out, nullptr, nullptr, Cc, HID, 0);
}

// round 5
// speedup vs baseline: 5.0729x; 1.4250x over previous
#include <cuda_runtime.h>
#include <cuda_fp16.h>
#include <math.h>
#include <stdint.h>

#define Bb 8
#define Ll 9216
#define Cc 512
#define Mm (Bb*Ll)          // 73728
#define HEADS 8
#define HID 2048

// ---------------- scratch (device globals; no runtime allocation) -------------
__device__ __align__(16) float g_q  [(size_t)Mm*Cc];
__device__ __align__(16) float g_k  [(size_t)Mm*Cc];
__device__ __align__(16) float g_val[(size_t)Mm*Cc];
__device__ __align__(16) __half g_xn[(size_t)Mm*Cc];
__device__ __align__(16) __half g_vn[(size_t)Mm*Cc];
__device__ __align__(16) __half g_att[(size_t)Mm*Cc];
__device__ __align__(16) __half g_h [(size_t)Mm*HID];
__device__ __align__(16) __half g_wq16[Cc*Cc];
__device__ __align__(16) __half g_wk16[Cc*Cc];
__device__ __align__(16) __half g_wv16[Cc*Cc];
__device__ __align__(16) __half g_wr16[Cc*Cc];
__device__ __align__(16) __half g_f116[HID*Cc];
__device__ __align__(16) __half g_f216[Cc*HID];
__device__ float g_ctx[Bb*HEADS*64*64];
__device__ float g_cmax[Bb*Cc];
__device__ float g_csum[Bb*Cc];

// ---------------- small helpers ----------------
__device__ __forceinline__ uint32_t smem_u32(const void* p) {
    return (uint32_t)__cvta_generic_to_shared(p);
}
__device__ __forceinline__ void cp16(uint32_t dst, const void* src) {
    asm volatile("cp.async.cg.shared.global [%0], [%1], 16;" :: "r"(dst), "l"(src));
}
#define CP_COMMIT() asm volatile("cp.async.commit_group;" ::: "memory")
#define CP_WAIT(N)  asm volatile("cp.async.wait_group %0;" :: "n"(N) : "memory")

#define LDSM4(r0, r1, r2, r3, addr) \
    asm volatile("ldmatrix.sync.aligned.m8n8.x4.shared.b16 {%0,%1,%2,%3}, [%4];" \
                 : "=r"(r0), "=r"(r1), "=r"(r2), "=r"(r3) : "r"(addr))

#define MMA_F16(d, a, b) \
    asm volatile("mma.sync.aligned.m16n8k16.row.col.f32.f16.f16.f32 " \
                 "{%0,%1,%2,%3}, {%4,%5,%6,%7}, {%8,%9}, {%0,%1,%2,%3};" \
                 : "+f"((d)[0]), "+f"((d)[1]), "+f"((d)[2]), "+f"((d)[3]) \
                 : "r"((a)[0]), "r"((a)[1]), "r"((a)[2]), "r"((a)[3]), \
                   "r"((b)[0]), "r"((b)[1]))

// ---------------- LayerNorm -> fp16 output ------------------------------------
__global__ __launch_bounds__(256) void ln_half(const float* __restrict__ x,
                                               const float* __restrict__ w,
                                               const float* __restrict__ b,
                                               __half* __restrict__ y)
{
    int row = blockIdx.x * 8 + (threadIdx.x >> 5);
    int lane = threadIdx.x & 31;
    const float* xr = x + (size_t)row * Cc;
    float4 v[4];
    float s = 0.f, s2 = 0.f;
#pragma unroll
    for (int i = 0; i < 4; i++) {
        v[i] = *(const float4*)(xr + lane * 4 + i * 128);
        s  += v[i].x + v[i].y + v[i].z + v[i].w;
        s2 += v[i].x*v[i].x + v[i].y*v[i].y + v[i].z*v[i].z + v[i].w*v[i].w;
    }
#pragma unroll
    for (int o = 16; o; o >>= 1) {
        s  += __shfl_xor_sync(0xffffffffu, s,  o);
        s2 += __shfl_xor_sync(0xffffffffu, s2, o);
    }
    float mean = s * (1.f/512.f);
    float var  = s2 * (1.f/512.f) - mean*mean;
    float rstd = rsqrtf(var + 1e-5f);
#pragma unroll
    for (int i = 0; i < 4; i++) {
        int c = lane * 4 + i * 128;
        float4 wv = *(const float4*)(w + c);
        float4 bv = *(const float4*)(b + c);
        ushort4 sh;
        sh.x = __half_as_ushort(__float2half_rn((v[i].x - mean) * rstd * wv.x + bv.x));
        sh.y = __half_as_ushort(__float2half_rn((v[i].y - mean) * rstd * wv.y + bv.y));
        sh.z = __half_as_ushort(__float2half_rn((v[i].z - mean) * rstd * wv.z + bv.z));
        sh.w = __half_as_ushort(__float2half_rn((v[i].w - mean) * rstd * wv.w + bv.w));
        *(ushort4*)(y + (size_t)row * Cc + c) = sh;
    }
}

// ---------------- weight fp32 -> fp16 -----------------------------------------
__global__ void convert_kernel(const float* __restrict__ w,
                               __half* __restrict__ o, int n)
{
    int i = blockIdx.x * 256 + threadIdx.x;
    if (i < n) o[i] = __float2half_rn(w[i]);
}

// ------------- fp16 mma.sync GEMM ---------------------------------------------
// out[m,n] = sum_k A[m,k]*W[n,k] (+bias)(+residf fp32)(+resph fp16)(+gelu)
#define TILEB 16384          // one 128x64 fp16 tile in bytes
#define STAGEB (2*TILEB)     // A, B
#define SMEM_SZ (2*STAGEB)   // double buffered = 65536

__global__ __launch_bounds__(256, 2) void gemm_mma(
    const __half* __restrict__ Aa,
    const __half* __restrict__ Bw,
    const float* __restrict__ bias,
    const float* __restrict__ residf,
    const __half* __restrict__ resph,
    float* __restrict__ outf,
    __half* __restrict__ outh,
    int Nd, int Kd, int do_gelu)
{
    extern __shared__ __align__(1024) char smarr[];
    const int tid = threadIdx.x;
    const int lane = tid & 31;
    const int wid = tid >> 5;
    const int bm = blockIdx.y * 128;
    const int bn = blockIdx.x * 128;
    const int wm = (wid >> 2) * 64;    // 0 or 64
    const int wn = (wid & 3) * 32;     // 0..96
    const uint32_t smb = smem_u32(smarr);

    const int cpc = tid & 7;           // chunk col 0..7
    const int cpr = tid >> 3;          // row base 0..31

    float acc[4][4][4];
#pragma unroll
    for (int i = 0; i < 4; i++)
#pragma unroll
        for (int j = 0; j < 4; j++)
#pragma unroll
            for (int r = 0; r < 4; r++) acc[i][j][r] = 0.f;

    const int nchunks = Kd >> 6;

    // ---- prefetch chunk 0 into stage 0
    {
        uint32_t sb = smb;
#pragma unroll
        for (int p = 0; p < 4; p++) {
            int r = cpr + p * 32;
            int off = r * 128 + cpc * 16;
            int sw = off ^ ((off >> 3) & 0x70);
            cp16(sb + sw,           Aa + (size_t)(bm + r) * Kd + cpc * 8);
            cp16(sb + TILEB + sw,   Bw + (size_t)(bn + r) * Kd + cpc * 8);
        }
        CP_COMMIT();
    }

    const int lrow = (lane & 7) + ((lane >> 3) & 1) * 8;
    const int lhalf = lane >> 4;

    for (int kc = 0; kc < nchunks; kc++) {
        if (kc + 1 < nchunks) {
            const int k0 = (kc + 1) << 6;
            uint32_t sb = smb + ((kc + 1) & 1) * STAGEB;
#pragma unroll
            for (int p = 0; p < 4; p++) {
                int r = cpr + p * 32;
                int off = r * 128 + cpc * 16;
                int sw = off ^ ((off >> 3) & 0x70);
                cp16(sb + sw,           Aa + (size_t)(bm + r) * Kd + k0 + cpc * 8);
                cp16(sb + TILEB + sw,   Bw + (size_t)(bn + r) * Kd + k0 + cpc * 8);
            }
            CP_COMMIT();
            CP_WAIT(1);
        } else {
            CP_WAIT(0);
        }
        __syncthreads();

        uint32_t sb = smb + (kc & 1) * STAGEB;
#pragma unroll
        for (int ks = 0; ks < 4; ks++) {
            uint32_t af[4][4];
#pragma unroll
            for (int mi = 0; mi < 4; mi++) {
                int row = wm + mi * 16 + lrow;
                int off = row * 128 + (ks * 2 + lhalf) * 16;
                int sw = off ^ ((off >> 3) & 0x70);
                LDSM4(af[mi][0], af[mi][1], af[mi][2], af[mi][3], sb + sw);
            }
            uint32_t bw[4][2];
#pragma unroll
            for (int nj2 = 0; nj2 < 2; nj2++) {
                int row = wn + nj2 * 16 + lrow;
                int off = row * 128 + (ks * 2 + lhalf) * 16;
                int sw = off ^ ((off >> 3) & 0x70);
                uint32_t r0, r1, r2, r3;
                LDSM4(r0, r1, r2, r3, sb + TILEB + sw);
                bw[nj2*2+0][0] = r0; bw[nj2*2+0][1] = r2;
                bw[nj2*2+1][0] = r1; bw[nj2*2+1][1] = r3;
            }
#pragma unroll
            for (int mi = 0; mi < 4; mi++)
#pragma unroll
                for (int nj = 0; nj < 4; nj++)
                    MMA_F16(acc[mi][nj], af[mi], bw[nj]);
        }
        __syncthreads();
    }

    // ---------------- epilogue ----------------
#pragma unroll
    for (int mi = 0; mi < 4; mi++)
#pragma unroll
        for (int nj = 0; nj < 4; nj++) {
            int n = bn + wn + nj * 8 + 2 * (lane & 3);
            float b0 = bias[n], b1 = bias[n + 1];
#pragma unroll
            for (int r = 0; r < 2; r++) {
                int m = bm + wm + mi * 16 + (lane >> 2) + r * 8;
                size_t idx = (size_t)m * Nd + n;
                float v0 = acc[mi][nj][r*2+0] + b0;
                float v1 = acc[mi][nj][r*2+1] + b1;
                if (residf) {
                    float2 rr = *(const float2*)(residf + idx);
                    v0 += rr.x; v1 += rr.y;
                }
                if (resph) {
                    uint32_t ph = *(const uint32_t*)((const unsigned short*)resph + idx);
                    v0 += __half2float(__ushort_as_half((unsigned short)(ph & 0xffff)));
                    v1 += __half2float(__ushort_as_half((unsigned short)(ph >> 16)));
                }
                if (do_gelu) {
                    v0 = 0.5f * v0 * (1.f + erff(v0 * 0.70710678118654752f));
                    v1 = 0.5f * v1 * (1.f + erff(v1 * 0.70710678118654752f));
                }
                if (outf) *(float2*)(outf + idx) = make_float2(v0, v1);
                if (outh) {
                    unsigned short h0 = __half_as_ushort(__float2half_rn(v0));
                    unsigned short h1 = __half_as_ushort(__float2half_rn(v1));
                    *(uint32_t*)((unsigned short*)outh + idx) =
                        (uint32_t)h0 | ((uint32_t)h1 << 16);
                }
            }
        }
}

// -------- column softmax stats over L (online max/sum) ------------------------
__global__ void ksm_stats(const float* __restrict__ k,
                          float* __restrict__ cmax, float* __restrict__ csum)
{
    int b  = blockIdx.x;
    int ch = blockIdx.y * 32 + threadIdx.x;
    float m = -1e30f, s = 0.f;
    for (int l = threadIdx.y; l < Ll; l += 8) {
        float v = k[((size_t)b * Ll + l) * Cc + ch];
        if (v > m) { s = s * expf(m - v) + 1.f; m = v; }
        else       { s += expf(v - m); }
    }
    __shared__ float sm[8][32], ss[8][32];
    sm[threadIdx.y][threadIdx.x] = m;
    ss[threadIdx.y][threadIdx.x] = s;
    __syncthreads();
    if (threadIdx.y == 0) {
        for (int i = 1; i < 8; i++) {
            float m2 = sm[i][threadIdx.x], s2 = ss[i][threadIdx.x];
            if (m2 > m) { s = s * expf(m - m2) + s2; m = m2; }
            else        { s += s2 * expf(m2 - m); }
        }
        cmax[b * Cc + ch] = m;
        csum[b * Cc + ch] = s;
    }
}

// -------- context partial: atomicAdd over L segments ---------------------------
__global__ __launch_bounds__(256) void context_kernel(const float* __restrict__ k,
                                                      const float* __restrict__ val,
                                                      const float* __restrict__ cmax,
                                                      const float* __restrict__ csum,
                                                      float* __restrict__ ctx)
{
    int bh = blockIdx.x;
    int b = bh >> 3, h = bh & 7;
    int ch0 = h * 64;
    int seg = blockIdx.y;
    const int SEG = Ll / 8;            // 1152
    __shared__ float ks[16][64], vs[16][64];
    __shared__ float smax[64], ssum[64];
    int tid = threadIdx.x;
    int tx = tid & 15, ty = tid >> 4;
    if (tid < 64) { smax[tid] = cmax[b * Cc + ch0 + tid]; ssum[tid] = csum[b * Cc + ch0 + tid]; }
    __syncthreads();
    float acc[4][4];
#pragma unroll
    for (int i = 0; i < 4; i++)
#pragma unroll
        for (int j = 0; j < 4; j++) acc[i][j] = 0.f;

    for (int l0 = seg * SEG; l0 < (seg + 1) * SEG; l0 += 16) {
#pragma unroll
        for (int i = 0; i < 4; i++) {
            int idx = tid + i * 256;
            int r = idx >> 6;
            int c = idx & 63;
            size_t off = ((size_t)b * Ll + l0 + r) * Cc + ch0 + c;
            ks[r][c] = expf(k[off] - smax[c]) / ssum[c];
            vs[r][c] = val[off];
        }
        __syncthreads();
#pragma unroll
        for (int kk = 0; kk < 16; kk++) {
            float rk[4], rv[4];
#pragma unroll
            for (int i = 0; i < 4; i++) rk[i] = ks[kk][ty*4 + i];
#pragma unroll
            for (int j = 0; j < 4; j++) rv[j] = vs[kk][tx*4 + j];
#pragma unroll
            for (int i = 0; i < 4; i++)
#pragma unroll
                for (int j = 0; j < 4; j++)
                    acc[i][j] += rk[i] * rv[j];
        }
        __syncthreads();
    }
#pragma unroll
    for (int i = 0; i < 4; i++)
#pragma unroll
        for (int j = 0; j < 4; j++)
            atomicAdd(&ctx[((size_t)bh * 64 + ty*4 + i) * 64 + tx*4 + j], acc[i][j]);
}

// -------- per-token softmax over 64 q channels + 64x64 matvec ------------------
__global__ __launch_bounds__(256) void attend_kernel(const float* __restrict__ q,
                                                     const float* __restrict__ ctx,
                                                     __half* __restrict__ ah)
{
    int bh = blockIdx.x;
    int b = bh >> 3, h = bh & 7;
    __shared__ float c_s[64][65];
    int tid = threadIdx.x;
    for (int i = tid; i < 4096; i += 256)
        c_s[i >> 6][i & 63] = ctx[(size_t)bh * 4096 + i];
    __syncthreads();
    int warp = tid >> 5, lane = tid & 31;
    int l_base = blockIdx.y * 64 + warp * 8;
#pragma unroll 1
    for (int li = 0; li < 8; li++) {
        int l = l_base + li;
        size_t qoff = ((size_t)b * Ll + l) * Cc + h * 64;
        float q0 = q[qoff + lane];
        float q1 = q[qoff + 32 + lane];
        float m = fmaxf(q0, q1);
#pragma unroll
        for (int o = 16; o; o >>= 1) m = fmaxf(m, __shfl_xor_sync(0xffffffffu, m, o));
        float e0 = expf(q0 - m), e1 = expf(q1 - m);
        float s = e0 + e1;
#pragma unroll
        for (int o = 16; o; o >>= 1) s += __shfl_xor_sync(0xffffffffu, s, o);
        float inv = 1.f / s;
        e0 *= inv; e1 *= inv;
        float a0 = 0.f, a1 = 0.f;
#pragma unroll
        for (int kc = 0; kc < 32; kc++) {
            float qv = __shfl_sync(0xffffffffu, e0, kc);
            a0 += c_s[kc][lane]      * qv;
            a1 += c_s[kc][lane + 32] * qv;
        }
#pragma unroll
        for (int kc = 0; kc < 32; kc++) {
            float qv = __shfl_sync(0xffffffffu, e1, kc);
            a0 += c_s[kc + 32][lane]      * qv;
            a1 += c_s[kc + 32][lane + 32] * qv;
        }
        ah[qoff + lane]      = __float2half_rn(a0);
        ah[qoff + 32 + lane] = __float2half_rn(a1);
    }
}

// -------- torch .view scramble: x1.flat[b, c*L+l] = t[b,l,c] + x.flat ---------
__global__ void scramble_kernel(const float* __restrict__ t,
                                const float* __restrict__ x,
                                float* __restrict__ x1)
{
    __shared__ float tile[32][33];
    int b = blockIdx.z;
    int l0 = blockIdx.x * 32, c0 = blockIdx.y * 32;
    const float* tb = t + (size_t)b * Ll * Cc;
    for (int i = threadIdx.y; i < 32; i += 8)
        tile[i][threadIdx.x] = tb[(size_t)(l0 + i) * Cc + c0 + threadIdx.x];
    __syncthreads();
    float* ob = x1 + (size_t)b * Ll * Cc;
    const float* xb = x + (size_t)b * Ll * Cc;
    for (int i = threadIdx.y; i < 32; i += 8) {
        size_t flat = (size_t)(c0 + i) * Ll + l0 + threadIdx.x;
        ob[flat] = tile[threadIdx.x][i] + xb[flat];
    }
}

// ------------------------------- driver ---------------------------------------
extern "C" void kernel_launch(void* const* d_in, const int* in_sizes, int n_in,
                              void* d_out, int out_size)
{
    const float* x     = (const float*)d_in[0];
    const float* v     = (const float*)d_in[1];
    const float* ln1w  = (const float*)d_in[4];
    const float* ln1b  = (const float*)d_in[5];
    const float* lnvw  = (const float*)d_in[6];
    const float* lnvb  = (const float*)d_in[7];
    const float* ln2w  = (const float*)d_in[8];
    const float* ln2b  = (const float*)d_in[9];
    const float* wq    = (const float*)d_in[10];
    const float* bq    = (const float*)d_in[11];
    const float* wk    = (const float*)d_in[12];
    const float* bk    = (const float*)d_in[13];
    const float* wv    = (const float*)d_in[14];
    const float* bv    = (const float*)d_in[15];
    const float* wr    = (const float*)d_in[16];
    const float* br    = (const float*)d_in[17];
    const float* fc1w  = (const float*)d_in[18];
    const float* fc1b  = (const float*)d_in[19];
    const float* fc2w  = (const float*)d_in[20];
    const float* fc2b  = (const float*)d_in[21];
    float* out = (float*)d_out;

    float *p_q, *p_k, *p_val, *p_ctx, *p_cmax, *p_csum;
    __half *p_xn, *p_vn, *p_att, *p_h;
    __half *p_wq, *p_wk, *p_wv, *p_wr, *p_f1, *p_f2;
    cudaGetSymbolAddress((void**)&p_q,   g_q);
    cudaGetSymbolAddress((void**)&p_k,   g_k);
    cudaGetSymbolAddress((void**)&p_val, g_val);
    cudaGetSymbolAddress((void**)&p_ctx, g_ctx);
    cudaGetSymbolAddress((void**)&p_cmax, g_cmax);
    cudaGetSymbolAddress((void**)&p_csum, g_csum);
    cudaGetSymbolAddress((void**)&p_xn,  g_xn);
    cudaGetSymbolAddress((void**)&p_vn,  g_vn);
    cudaGetSymbolAddress((void**)&p_att, g_att);
    cudaGetSymbolAddress((void**)&p_h,   g_h);
    cudaGetSymbolAddress((void**)&p_wq, g_wq16);
    cudaGetSymbolAddress((void**)&p_wk, g_wk16);
    cudaGetSymbolAddress((void**)&p_wv, g_wv16);
    cudaGetSymbolAddress((void**)&p_wr, g_wr16);
    cudaGetSymbolAddress((void**)&p_f1, g_f116);
    cudaGetSymbolAddress((void**)&p_f2, g_f216);

    cudaFuncSetAttribute(gemm_mma, cudaFuncAttributeMaxDynamicSharedMemorySize, SMEM_SZ);

    dim3 g512(Cc / 128, Mm / 128);     // (4, 576)
    dim3 g2048(HID / 128, Mm / 128);   // (16, 576)

    // weight converts + LN1
    convert_kernel<<<(Cc*Cc + 255)/256, 256>>>(wq, p_wq, Cc*Cc);
    convert_kernel<<<(Cc*Cc + 255)/256, 256>>>(wk, p_wk, Cc*Cc);
    convert_kernel<<<(Cc*Cc + 255)/256, 256>>>(wv, p_wv, Cc*Cc);
    convert_kernel<<<(Cc*Cc + 255)/256, 256>>>(wr, p_wr, Cc*Cc);
    convert_kernel<<<(HID*Cc + 255)/256, 256>>>(fc1w, p_f1, HID*Cc);
    convert_kernel<<<(Cc*HID + 255)/256, 256>>>(fc2w, p_f2, Cc*HID);
    ln_half<<<Mm / 8, 256>>>(x, ln1w, ln1b, p_xn);
    ln_half<<<Mm / 8, 256>>>(v, lnvw, lnvb, p_vn);

    // q/k/val projections
    gemm_mma<<<g512, 256, SMEM_SZ>>>(p_xn, p_wq, bq, nullptr, nullptr,
                                     p_q, nullptr, Cc, Cc, 0);
    gemm_mma<<<g512, 256, SMEM_SZ>>>(p_vn, p_wk, bk, nullptr, nullptr,
                                     p_k, nullptr, Cc, Cc, 0);
    gemm_mma<<<g512, 256, SMEM_SZ>>>(p_vn, p_wv, bv, nullptr, nullptr,
                                     p_val, nullptr, Cc, Cc, 0);

    // attention core
    ksm_stats<<<dim3(Bb, Cc / 32), dim3(32, 8)>>>(p_k, p_cmax, p_csum);
    cudaMemsetAsync(p_ctx, 0, (size_t)Bb*HEADS*64*64*sizeof(float));
    context_kernel<<<dim3(Bb * HEADS, 8), 256>>>(p_k, p_val, p_cmax, p_csum, p_ctx);
    attend_kernel<<<dim3(Bb * HEADS, Ll / 64), 256>>>(p_q, p_ctx, p_att);

    // reprojection: t = att @ wr^T + br + xn  -> fp32 in g_q
    gemm_mma<<<g512, 256, SMEM_SZ>>>(p_att, p_wr, br, nullptr, p_xn,
                                     p_q, nullptr, Cc, Cc, 0);

    // scramble (batched transpose) + shortcut -> x1 in d_out
    scramble_kernel<<<dim3(Ll / 32, Cc / 32, Bb), dim3(32, 8)>>>(p_q, x, out);

    // LN2 -> fp16 (reuse xn buffer)
    ln_half<<<Mm / 8, 256>>>(out, ln2w, ln2b, p_xn);

    // MLP: fc1 (+exact GELU, fp16 out), fc2 (+residual from d_out)
    gemm_mma<<<g2048, 256, SMEM_SZ>>>(p_xn, p_f1, fc1b, nullptr, nullptr,
                                      nullptr, p_h, HID, Cc, 1);
    gemm_mma<<<g512, 256, SMEM_SZ>>>(p_h, p_f2, fc2b, out, nullptr,
                                     out, nullptr, Cc, HID, 0);
}

// round 6
// speedup vs baseline: 5.3418x; 1.0530x over previous
#include <cuda_runtime.h>
#include <cuda_fp16.h>
#include <math.h>
#include <stdint.h>

#define Bb 8
#define Ll 9216
#define Cc 512
#define Mm (Bb*Ll)          // 73728
#define HEADS 8
#define HID 2048

// ---------------- scratch (device globals; no runtime allocation) -------------
__device__ __align__(16) float g_t  [(size_t)Mm*Cc];        // reproj output (fp32)
__device__ __align__(16) __half g_q16[(size_t)Mm*Cc];
__device__ __align__(16) __half g_kv16[(size_t)Mm*1024];    // k | val fused
__device__ __align__(16) __half g_xn[(size_t)Mm*Cc];
__device__ __align__(16) __half g_vn[(size_t)Mm*Cc];
__device__ __align__(16) __half g_att[(size_t)Mm*Cc];
__device__ __align__(16) __half g_h [(size_t)Mm*HID];
__device__ __align__(16) __half g_wq16[Cc*Cc];
__device__ __align__(16) __half g_wkv16[2*Cc*Cc];           // wk | wv fused
__device__ __align__(16) __half g_wr16[Cc*Cc];
__device__ __align__(16) __half g_f116[HID*Cc];
__device__ __align__(16) __half g_f216[Cc*HID];
__device__ float g_bkv[1024];
__device__ float g_ctx[Bb*HEADS*64*64];
__device__ float g_cmax[Bb*Cc];
__device__ float g_csum[Bb*Cc];

// ---------------- small helpers ----------------
__device__ __forceinline__ uint32_t smem_u32(const void* p) {
    return (uint32_t)__cvta_generic_to_shared(p);
}
__device__ __forceinline__ void cp16(uint32_t dst, const void* src) {
    asm volatile("cp.async.cg.shared.global [%0], [%1], 16;" :: "r"(dst), "l"(src));
}
#define CP_COMMIT() asm volatile("cp.async.commit_group;" ::: "memory")
#define CP_WAIT(N)  asm volatile("cp.async.wait_group %0;" :: "n"(N) : "memory")

#define LDSM4(r0, r1, r2, r3, addr) \
    asm volatile("ldmatrix.sync.aligned.m8n8.x4.shared.b16 {%0,%1,%2,%3}, [%4];" \
                 : "=r"(r0), "=r"(r1), "=r"(r2), "=r"(r3) : "r"(addr))

#define MMA_F16(d, a, b) \
    asm volatile("mma.sync.aligned.m16n8k16.row.col.f32.f16.f16.f32 " \
                 "{%0,%1,%2,%3}, {%4,%5,%6,%7}, {%8,%9}, {%0,%1,%2,%3};" \
                 : "+f"((d)[0]), "+f"((d)[1]), "+f"((d)[2]), "+f"((d)[3]) \
                 : "r"((a)[0]), "r"((a)[1]), "r"((a)[2]), "r"((a)[3]), \
                   "r"((b)[0]), "r"((b)[1]))

// ---------------- LayerNorm -> fp16 output ------------------------------------
__global__ __launch_bounds__(256) void ln_half(const float* __restrict__ x,
                                               const float* __restrict__ w,
                                               const float* __restrict__ b,
                                               __half* __restrict__ y)
{
    int row = blockIdx.x * 8 + (threadIdx.x >> 5);
    int lane = threadIdx.x & 31;
    const float* xr = x + (size_t)row * Cc;
    float4 v[4];
    float s = 0.f, s2 = 0.f;
#pragma unroll
    for (int i = 0; i < 4; i++) {
        v[i] = *(const float4*)(xr + lane * 4 + i * 128);
        s  += v[i].x + v[i].y + v[i].z + v[i].w;
        s2 += v[i].x*v[i].x + v[i].y*v[i].y + v[i].z*v[i].z + v[i].w*v[i].w;
    }
#pragma unroll
    for (int o = 16; o; o >>= 1) {
        s  += __shfl_xor_sync(0xffffffffu, s,  o);
        s2 += __shfl_xor_sync(0xffffffffu, s2, o);
    }
    float mean = s * (1.f/512.f);
    float var  = s2 * (1.f/512.f) - mean*mean;
    float rstd = rsqrtf(var + 1e-5f);
#pragma unroll
    for (int i = 0; i < 4; i++) {
        int c = lane * 4 + i * 128;
        float4 wv = *(const float4*)(w + c);
        float4 bv = *(const float4*)(b + c);
        ushort4 sh;
        sh.x = __half_as_ushort(__float2half_rn((v[i].x - mean) * rstd * wv.x + bv.x));
        sh.y = __half_as_ushort(__float2half_rn((v[i].y - mean) * rstd * wv.y + bv.y));
        sh.z = __half_as_ushort(__float2half_rn((v[i].z - mean) * rstd * wv.z + bv.z));
        sh.w = __half_as_ushort(__float2half_rn((v[i].w - mean) * rstd * wv.w + bv.w));
        *(ushort4*)(y + (size_t)row * Cc + c) = sh;
    }
}

// ---------------- weight fp32 -> fp16 ; bias concat ----------------------------
__global__ void convert_kernel(const float* __restrict__ w,
                               __half* __restrict__ o, int n)
{
    int i = blockIdx.x * 256 + threadIdx.x;
    if (i < n) o[i] = __float2half_rn(w[i]);
}
__global__ void concat_bias(const float* __restrict__ bk,
                            const float* __restrict__ bv,
                            float* __restrict__ o)
{
    int i = blockIdx.x * 256 + threadIdx.x;
    if (i < 512) o[i] = bk[i];
    else if (i < 1024) o[i] = bv[i - 512];
}

// ------------- fp16 mma.sync GEMM, 3-stage cp.async pipeline -------------------
// out[m,n] = sum_k A[m,k]*W[n,k] (+bias)(+residf fp32)(+resph fp16)(+gelu)
#define TILEB 16384          // one 128x64 fp16 tile in bytes
#define STAGEB (2*TILEB)     // A, B
#define NSTAGE 3
#define SMEM_SZ (NSTAGE*STAGEB)   // 98304

__global__ __launch_bounds__(256, 2) void gemm_mma(
    const __half* __restrict__ Aa,
    const __half* __restrict__ Bw,
    const float* __restrict__ bias,
    const float* __restrict__ residf,
    const __half* __restrict__ resph,
    float* __restrict__ outf,
    __half* __restrict__ outh,
    int Nd, int Kd, int do_gelu)
{
    extern __shared__ __align__(1024) char smarr[];
    const int tid = threadIdx.x;
    const int lane = tid & 31;
    const int wid = tid >> 5;
    const int bm = blockIdx.y * 128;
    const int bn = blockIdx.x * 128;
    const int wm = (wid >> 2) * 64;
    const int wn = (wid & 3) * 32;
    const uint32_t smb = smem_u32(smarr);

    const int cpc = tid & 7;
    const int cpr = tid >> 3;

    float acc[4][4][4];
#pragma unroll
    for (int i = 0; i < 4; i++)
#pragma unroll
        for (int j = 0; j < 4; j++)
#pragma unroll
            for (int r = 0; r < 4; r++) acc[i][j][r] = 0.f;

    const int nchunks = Kd >> 6;

    // ---- prologue: stages 0,1
#pragma unroll
    for (int st = 0; st < 2; st++) {
        const int k0 = st << 6;
        uint32_t sb = smb + st * STAGEB;
#pragma unroll
        for (int p = 0; p < 4; p++) {
            int r = cpr + p * 32;
            int off = r * 128 + cpc * 16;
            int sw = off ^ ((off >> 3) & 0x70);
            cp16(sb + sw,         Aa + (size_t)(bm + r) * Kd + k0 + cpc * 8);
            cp16(sb + TILEB + sw, Bw + (size_t)(bn + r) * Kd + k0 + cpc * 8);
        }
        CP_COMMIT();
    }

    const int lrow = (lane & 7) + ((lane >> 3) & 1) * 8;
    const int lhalf = lane >> 4;

    int stage = 0;
    for (int kc = 0; kc < nchunks; kc++) {
        if (kc + 1 < nchunks) { CP_WAIT(1); } else { CP_WAIT(0); }
        __syncthreads();

        // issue loads for chunk kc+2 into stage (stage+2)%3
        if (kc + 2 < nchunks) {
            const int k0 = (kc + 2) << 6;
            int st2 = stage + 2; if (st2 >= NSTAGE) st2 -= NSTAGE;
            uint32_t sb = smb + st2 * STAGEB;
#pragma unroll
            for (int p = 0; p < 4; p++) {
                int r = cpr + p * 32;
                int off = r * 128 + cpc * 16;
                int sw = off ^ ((off >> 3) & 0x70);
                cp16(sb + sw,         Aa + (size_t)(bm + r) * Kd + k0 + cpc * 8);
                cp16(sb + TILEB + sw, Bw + (size_t)(bn + r) * Kd + k0 + cpc * 8);
            }
            CP_COMMIT();
        }

        uint32_t sb = smb + stage * STAGEB;
#pragma unroll
        for (int ks = 0; ks < 4; ks++) {
            uint32_t af[4][4];
#pragma unroll
            for (int mi = 0; mi < 4; mi++) {
                int row = wm + mi * 16 + lrow;
                int off = row * 128 + (ks * 2 + lhalf) * 16;
                int sw = off ^ ((off >> 3) & 0x70);
                LDSM4(af[mi][0], af[mi][1], af[mi][2], af[mi][3], sb + sw);
            }
            uint32_t bw[4][2];
#pragma unroll
            for (int nj2 = 0; nj2 < 2; nj2++) {
                int row = wn + nj2 * 16 + lrow;
                int off = row * 128 + (ks * 2 + lhalf) * 16;
                int sw = off ^ ((off >> 3) & 0x70);
                uint32_t r0, r1, r2, r3;
                LDSM4(r0, r1, r2, r3, sb + TILEB + sw);
                bw[nj2*2+0][0] = r0; bw[nj2*2+0][1] = r2;
                bw[nj2*2+1][0] = r1; bw[nj2*2+1][1] = r3;
            }
#pragma unroll
            for (int mi = 0; mi < 4; mi++)
#pragma unroll
                for (int nj = 0; nj < 4; nj++)
                    MMA_F16(acc[mi][nj], af[mi], bw[nj]);
        }
        if (++stage >= NSTAGE) stage = 0;
    }

    // ---------------- epilogue ----------------
#pragma unroll
    for (int mi = 0; mi < 4; mi++)
#pragma unroll
        for (int nj = 0; nj < 4; nj++) {
            int n = bn + wn + nj * 8 + 2 * (lane & 3);
            float b0 = bias[n], b1 = bias[n + 1];
#pragma unroll
            for (int r = 0; r < 2; r++) {
                int m = bm + wm + mi * 16 + (lane >> 2) + r * 8;
                size_t idx = (size_t)m * Nd + n;
                float v0 = acc[mi][nj][r*2+0] + b0;
                float v1 = acc[mi][nj][r*2+1] + b1;
                if (residf) {
                    float2 rr = *(const float2*)(residf + idx);
                    v0 += rr.x; v1 += rr.y;
                }
                if (resph) {
                    uint32_t ph = *(const uint32_t*)((const unsigned short*)resph + idx);
                    v0 += __half2float(__ushort_as_half((unsigned short)(ph & 0xffff)));
                    v1 += __half2float(__ushort_as_half((unsigned short)(ph >> 16)));
                }
                if (do_gelu) {
                    v0 = 0.5f * v0 * (1.f + erff(v0 * 0.70710678118654752f));
                    v1 = 0.5f * v1 * (1.f + erff(v1 * 0.70710678118654752f));
                }
                if (outf) *(float2*)(outf + idx) = make_float2(v0, v1);
                if (outh) {
                    unsigned short h0 = __half_as_ushort(__float2half_rn(v0));
                    unsigned short h1 = __half_as_ushort(__float2half_rn(v1));
                    *(uint32_t*)((unsigned short*)outh + idx) =
                        (uint32_t)h0 | ((uint32_t)h1 << 16);
                }
            }
        }
}

// -------- column softmax stats over L (k = cols 0..511 of fused kv, fp16) ------
__global__ void ksm_stats(const __half* __restrict__ kv,
                          float* __restrict__ cmax, float* __restrict__ csum)
{
    int b  = blockIdx.x;
    int ch = blockIdx.y * 32 + threadIdx.x;
    float m = -1e30f, s = 0.f;
    for (int l = threadIdx.y; l < Ll; l += 8) {
        float v = __half2float(kv[((size_t)b * Ll + l) * 1024 + ch]);
        if (v > m) { s = s * expf(m - v) + 1.f; m = v; }
        else       { s += expf(v - m); }
    }
    __shared__ float sm[8][32], ss[8][32];
    sm[threadIdx.y][threadIdx.x] = m;
    ss[threadIdx.y][threadIdx.x] = s;
    __syncthreads();
    if (threadIdx.y == 0) {
        for (int i = 1; i < 8; i++) {
            float m2 = sm[i][threadIdx.x], s2 = ss[i][threadIdx.x];
            if (m2 > m) { s = s * expf(m - m2) + s2; m = m2; }
            else        { s += s2 * expf(m2 - m); }
        }
        cmax[b * Cc + ch] = m;
        csum[b * Cc + ch] = s;
    }
}

// -------- context partial: atomicAdd over L segments (fp16 kv) -----------------
__global__ __launch_bounds__(256) void context_kernel(const __half* __restrict__ kv,
                                                      const float* __restrict__ cmax,
                                                      const float* __restrict__ csum,
                                                      float* __restrict__ ctx)
{
    int bh = blockIdx.x;
    int b = bh >> 3, h = bh & 7;
    int ch0 = h * 64;
    int seg = blockIdx.y;
    const int SEG = Ll / 8;            // 1152
    __shared__ float ks[16][64], vs[16][64];
    __shared__ float smax[64], ssum[64];
    int tid = threadIdx.x;
    int tx = tid & 15, ty = tid >> 4;
    if (tid < 64) { smax[tid] = cmax[b * Cc + ch0 + tid]; ssum[tid] = csum[b * Cc + ch0 + tid]; }
    __syncthreads();
    float acc[4][4];
#pragma unroll
    for (int i = 0; i < 4; i++)
#pragma unroll
        for (int j = 0; j < 4; j++) acc[i][j] = 0.f;

    for (int l0 = seg * SEG; l0 < (seg + 1) * SEG; l0 += 16) {
#pragma unroll
        for (int i = 0; i < 4; i++) {
            int idx = tid + i * 256;
            int r = idx >> 6;
            int c = idx & 63;
            size_t off = ((size_t)b * Ll + l0 + r) * 1024 + ch0 + c;
            ks[r][c] = expf(__half2float(kv[off]) - smax[c]) / ssum[c];
            vs[r][c] = __half2float(kv[off + 512]);
        }
        __syncthreads();
#pragma unroll
        for (int kk = 0; kk < 16; kk++) {
            float rk[4], rv[4];
#pragma unroll
            for (int i = 0; i < 4; i++) rk[i] = ks[kk][ty*4 + i];
#pragma unroll
            for (int j = 0; j < 4; j++) rv[j] = vs[kk][tx*4 + j];
#pragma unroll
            for (int i = 0; i < 4; i++)
#pragma unroll
                for (int j = 0; j < 4; j++)
                    acc[i][j] += rk[i] * rv[j];
        }
        __syncthreads();
    }
#pragma unroll
    for (int i = 0; i < 4; i++)
#pragma unroll
        for (int j = 0; j < 4; j++)
            atomicAdd(&ctx[((size_t)bh * 64 + ty*4 + i) * 64 + tx*4 + j], acc[i][j]);
}

// -------- per-token softmax over 64 q channels + 64x64 matvec (fp16 q) ---------
__global__ __launch_bounds__(256) void attend_kernel(const __half* __restrict__ q,
                                                     const float* __restrict__ ctx,
                                                     __half* __restrict__ ah)
{
    int bh = blockIdx.x;
    int b = bh >> 3, h = bh & 7;
    __shared__ float c_s[64][65];
    int tid = threadIdx.x;
    for (int i = tid; i < 4096; i += 256)
        c_s[i >> 6][i & 63] = ctx[(size_t)bh * 4096 + i];
    __syncthreads();
    int warp = tid >> 5, lane = tid & 31;
    int l_base = blockIdx.y * 64 + warp * 8;
#pragma unroll 1
    for (int li = 0; li < 8; li++) {
        int l = l_base + li;
        size_t qoff = ((size_t)b * Ll + l) * Cc + h * 64;
        float q0 = __half2float(q[qoff + lane]);
        float q1 = __half2float(q[qoff + 32 + lane]);
        float m = fmaxf(q0, q1);
#pragma unroll
        for (int o = 16; o; o >>= 1) m = fmaxf(m, __shfl_xor_sync(0xffffffffu, m, o));
        float e0 = expf(q0 - m), e1 = expf(q1 - m);
        float s = e0 + e1;
#pragma unroll
        for (int o = 16; o; o >>= 1) s += __shfl_xor_sync(0xffffffffu, s, o);
        float inv = 1.f / s;
        e0 *= inv; e1 *= inv;
        float a0 = 0.f, a1 = 0.f;
#pragma unroll
        for (int kc = 0; kc < 32; kc++) {
            float qv = __shfl_sync(0xffffffffu, e0, kc);
            a0 += c_s[kc][lane]      * qv;
            a1 += c_s[kc][lane + 32] * qv;
        }
#pragma unroll
        for (int kc = 0; kc < 32; kc++) {
            float qv = __shfl_sync(0xffffffffu, e1, kc);
            a0 += c_s[kc + 32][lane]      * qv;
            a1 += c_s[kc + 32][lane + 32] * qv;
        }
        ah[qoff + lane]      = __float2half_rn(a0);
        ah[qoff + 32 + lane] = __float2half_rn(a1);
    }
}

// -------- torch .view scramble: x1.flat[b, c*L+l] = t[b,l,c] + x.flat ---------
__global__ void scramble_kernel(const float* __restrict__ t,
                                const float* __restrict__ x,
                                float* __restrict__ x1)
{
    __shared__ float tile[32][33];
    int b = blockIdx.z;
    int l0 = blockIdx.x * 32, c0 = blockIdx.y * 32;
    const float* tb = t + (size_t)b * Ll * Cc;
    for (int i = threadIdx.y; i < 32; i += 8)
        tile[i][threadIdx.x] = tb[(size_t)(l0 + i) * Cc + c0 + threadIdx.x];
    __syncthreads();
    float* ob = x1 + (size_t)b * Ll * Cc;
    const float* xb = x + (size_t)b * Ll * Cc;
    for (int i = threadIdx.y; i < 32; i += 8) {
        size_t flat = (size_t)(c0 + i) * Ll + l0 + threadIdx.x;
        ob[flat] = tile[threadIdx.x][i] + xb[flat];
    }
}

// ------------------------------- driver ---------------------------------------
extern "C" void kernel_launch(void* const* d_in, const int* in_sizes, int n_in,
                              void* d_out, int out_size)
{
    const float* x     = (const float*)d_in[0];
    const float* v     = (const float*)d_in[1];
    const float* ln1w  = (const float*)d_in[4];
    const float* ln1b  = (const float*)d_in[5];
    const float* lnvw  = (const float*)d_in[6];
    const float* lnvb  = (const float*)d_in[7];
    const float* ln2w  = (const float*)d_in[8];
    const float* ln2b  = (const float*)d_in[9];
    const float* wq    = (const float*)d_in[10];
    const float* bq    = (const float*)d_in[11];
    const float* wk    = (const float*)d_in[12];
    const float* bk    = (const float*)d_in[13];
    const float* wv    = (const float*)d_in[14];
    const float* bv    = (const float*)d_in[15];
    const float* wr    = (const float*)d_in[16];
    const float* br    = (const float*)d_in[17];
    const float* fc1w  = (const float*)d_in[18];
    const float* fc1b  = (const float*)d_in[19];
    const float* fc2w  = (const float*)d_in[20];
    const float* fc2b  = (const float*)d_in[21];
    float* out = (float*)d_out;

    float *p_t, *p_ctx, *p_cmax, *p_csum, *p_bkv;
    __half *p_q16, *p_kv16, *p_xn, *p_vn, *p_att, *p_h;
    __half *p_wq, *p_wkv, *p_wr, *p_f1, *p_f2;
    cudaGetSymbolAddress((void**)&p_t,   g_t);
    cudaGetSymbolAddress((void**)&p_ctx, g_ctx);
    cudaGetSymbolAddress((void**)&p_cmax, g_cmax);
    cudaGetSymbolAddress((void**)&p_csum, g_csum);
    cudaGetSymbolAddress((void**)&p_bkv, g_bkv);
    cudaGetSymbolAddress((void**)&p_q16, g_q16);
    cudaGetSymbolAddress((void**)&p_kv16, g_kv16);
    cudaGetSymbolAddress((void**)&p_xn,  g_xn);
    cudaGetSymbolAddress((void**)&p_vn,  g_vn);
    cudaGetSymbolAddress((void**)&p_att, g_att);
    cudaGetSymbolAddress((void**)&p_h,   g_h);
    cudaGetSymbolAddress((void**)&p_wq,  g_wq16);
    cudaGetSymbolAddress((void**)&p_wkv, g_wkv16);
    cudaGetSymbolAddress((void**)&p_wr,  g_wr16);
    cudaGetSymbolAddress((void**)&p_f1,  g_f116);
    cudaGetSymbolAddress((void**)&p_f2,  g_f216);

    cudaFuncSetAttribute(gemm_mma, cudaFuncAttributeMaxDynamicSharedMemorySize, SMEM_SZ);

    dim3 g512(Cc / 128, Mm / 128);     // (4, 576)
    dim3 g1024(1024 / 128, Mm / 128);  // (8, 576)
    dim3 g2048(HID / 128, Mm / 128);   // (16, 576)

    // weight converts + bias concat + LN1
    convert_kernel<<<(Cc*Cc + 255)/256, 256>>>(wq, p_wq, Cc*Cc);
    convert_kernel<<<(Cc*Cc + 255)/256, 256>>>(wk, p_wkv, Cc*Cc);
    convert_kernel<<<(Cc*Cc + 255)/256, 256>>>(wv, p_wkv + Cc*Cc, Cc*Cc);
    convert_kernel<<<(Cc*Cc + 255)/256, 256>>>(wr, p_wr, Cc*Cc);
    convert_kernel<<<(HID*Cc + 255)/256, 256>>>(fc1w, p_f1, HID*Cc);
    convert_kernel<<<(Cc*HID + 255)/256, 256>>>(fc2w, p_f2, Cc*HID);
    concat_bias<<<4, 256>>>(bk, bv, p_bkv);
    ln_half<<<Mm / 8, 256>>>(x, ln1w, ln1b, p_xn);
    ln_half<<<Mm / 8, 256>>>(v, lnvw, lnvb, p_vn);

    // projections: q (fp16 out), fused k|v (fp16 out, Nd=1024)
    gemm_mma<<<g512, 256, SMEM_SZ>>>(p_xn, p_wq, bq, nullptr, nullptr,
                                     nullptr, p_q16, Cc, Cc, 0);
    gemm_mma<<<g1024, 256, SMEM_SZ>>>(p_vn, p_wkv, p_bkv, nullptr, nullptr,
                                      nullptr, p_kv16, 1024, Cc, 0);

    // attention core
    ksm_stats<<<dim3(Bb, Cc / 32), dim3(32, 8)>>>(p_kv16, p_cmax, p_csum);
    cudaMemsetAsync(p_ctx, 0, (size_t)Bb*HEADS*64*64*sizeof(float));
    context_kernel<<<dim3(Bb * HEADS, 8), 256>>>(p_kv16, p_cmax, p_csum, p_ctx);
    attend_kernel<<<dim3(Bb * HEADS, Ll / 64), 256>>>(p_q16, p_ctx, p_att);

    // reprojection: t = att @ wr^T + br + xn  -> fp32
    gemm_mma<<<g512, 256, SMEM_SZ>>>(p_att, p_wr, br, nullptr, p_xn,
                                     p_t, nullptr, Cc, Cc, 0);

    // scramble (batched transpose) + shortcut -> x1 in d_out
    scramble_kernel<<<dim3(Ll / 32, Cc / 32, Bb), dim3(32, 8)>>>(p_t, x, out);

    // LN2 -> fp16 (reuse xn buffer)
    ln_half<<<Mm / 8, 256>>>(out, ln2w, ln2b, p_xn);

    // MLP: fc1 (+exact GELU, fp16 out), fc2 (+residual from d_out)
    gemm_mma<<<g2048, 256, SMEM_SZ>>>(p_xn, p_f1, fc1b, nullptr, nullptr,
                                      nullptr, p_h, HID, Cc, 1);
    gemm_mma<<<g512, 256, SMEM_SZ>>>(p_h, p_f2, fc2b, out, nullptr,
                                     out, nullptr, Cc, HID, 0);
}

// round 7
// speedup vs baseline: 6.3728x; 1.1930x over previous
#include <cuda_runtime.h>
#include <cuda_fp16.h>
#include <math.h>
#include <stdint.h>

#define Bb 8
#define Ll 9216
#define Cc 512
#define Mm (Bb*Ll)          // 73728
#define HEADS 8
#define HID 2048

// ---------------- scratch (device globals; no runtime allocation) -------------
__device__ __align__(16) __half g_q16[(size_t)Mm*Cc];
__device__ __align__(16) __half g_kv16[(size_t)Mm*1024];    // k | val fused
__device__ __align__(16) __half g_xn[(size_t)Mm*Cc];
__device__ __align__(16) __half g_vn[(size_t)Mm*Cc];
__device__ __align__(16) __half g_att[(size_t)Mm*Cc];
__device__ __align__(16) __half g_h [(size_t)Mm*HID];
__device__ __align__(16) __half g_wq16[Cc*Cc];
__device__ __align__(16) __half g_wkv16[2*Cc*Cc];           // wk | wv fused
__device__ __align__(16) __half g_wr16[Cc*Cc];
__device__ __align__(16) __half g_f116[HID*Cc];
__device__ __align__(16) __half g_f216[Cc*HID];
__device__ float g_bkv[1024];
__device__ float g_ctx[Bb*HEADS*64*64];
__device__ __align__(16) __half g_ctxT[Bb*HEADS*64*64];
__device__ float g_cmax[Bb*Cc];
__device__ float g_csum[Bb*Cc];

// ---------------- small helpers ----------------
__device__ __forceinline__ uint32_t smem_u32(const void* p) {
    return (uint32_t)__cvta_generic_to_shared(p);
}
__device__ __forceinline__ void cp16(uint32_t dst, const void* src) {
    asm volatile("cp.async.cg.shared.global [%0], [%1], 16;" :: "r"(dst), "l"(src));
}
#define CP_COMMIT() asm volatile("cp.async.commit_group;" ::: "memory")
#define CP_WAIT(N)  asm volatile("cp.async.wait_group %0;" :: "n"(N) : "memory")

#define LDSM4(r0, r1, r2, r3, addr) \
    asm volatile("ldmatrix.sync.aligned.m8n8.x4.shared.b16 {%0,%1,%2,%3}, [%4];" \
                 : "=r"(r0), "=r"(r1), "=r"(r2), "=r"(r3) : "r"(addr))

#define MMA_F16(d, a, b) \
    asm volatile("mma.sync.aligned.m16n8k16.row.col.f32.f16.f16.f32 " \
                 "{%0,%1,%2,%3}, {%4,%5,%6,%7}, {%8,%9}, {%0,%1,%2,%3};" \
                 : "+f"((d)[0]), "+f"((d)[1]), "+f"((d)[2]), "+f"((d)[3]) \
                 : "r"((a)[0]), "r"((a)[1]), "r"((a)[2]), "r"((a)[3]), \
                   "r"((b)[0]), "r"((b)[1]))

// ---------------- LayerNorm -> fp16 output ------------------------------------
__global__ __launch_bounds__(256) void ln_half(const float* __restrict__ x,
                                               const float* __restrict__ w,
                                               const float* __restrict__ b,
                                               __half* __restrict__ y)
{
    int row = blockIdx.x * 8 + (threadIdx.x >> 5);
    int lane = threadIdx.x & 31;
    const float* xr = x + (size_t)row * Cc;
    float4 v[4];
    float s = 0.f, s2 = 0.f;
#pragma unroll
    for (int i = 0; i < 4; i++) {
        v[i] = *(const float4*)(xr + lane * 4 + i * 128);
        s  += v[i].x + v[i].y + v[i].z + v[i].w;
        s2 += v[i].x*v[i].x + v[i].y*v[i].y + v[i].z*v[i].z + v[i].w*v[i].w;
    }
#pragma unroll
    for (int o = 16; o; o >>= 1) {
        s  += __shfl_xor_sync(0xffffffffu, s,  o);
        s2 += __shfl_xor_sync(0xffffffffu, s2, o);
    }
    float mean = s * (1.f/512.f);
    float var  = s2 * (1.f/512.f) - mean*mean;
    float rstd = rsqrtf(var + 1e-5f);
#pragma unroll
    for (int i = 0; i < 4; i++) {
        int c = lane * 4 + i * 128;
        float4 wv = *(const float4*)(w + c);
        float4 bv = *(const float4*)(b + c);
        ushort4 sh;
        sh.x = __half_as_ushort(__float2half_rn((v[i].x - mean) * rstd * wv.x + bv.x));
        sh.y = __half_as_ushort(__float2half_rn((v[i].y - mean) * rstd * wv.y + bv.y));
        sh.z = __half_as_ushort(__float2half_rn((v[i].z - mean) * rstd * wv.z + bv.z));
        sh.w = __half_as_ushort(__float2half_rn((v[i].w - mean) * rstd * wv.w + bv.w));
        *(ushort4*)(y + (size_t)row * Cc + c) = sh;
    }
}

// ---------------- weight fp32 -> fp16 ; bias concat ----------------------------
__global__ void convert_kernel(const float* __restrict__ w,
                               __half* __restrict__ o, int n)
{
    int i = blockIdx.x * 256 + threadIdx.x;
    if (i < n) o[i] = __float2half_rn(w[i]);
}
__global__ void concat_bias(const float* __restrict__ bk,
                            const float* __restrict__ bv,
                            float* __restrict__ o)
{
    int i = blockIdx.x * 256 + threadIdx.x;
    if (i < 512) o[i] = bk[i];
    else if (i < 1024) o[i] = bv[i - 512];
}

// ------------- fp16 mma.sync GEMM, 3-stage cp.async pipeline -------------------
#define TILEB 16384
#define STAGEB (2*TILEB)
#define NSTAGE 3
#define SMEM_SZ (NSTAGE*STAGEB)   // 98304; also >= 128*132*4 for scram tile

__global__ __launch_bounds__(256, 2) void gemm_mma(
    const __half* __restrict__ Aa,
    const __half* __restrict__ Bw,
    const float* __restrict__ bias,
    const float* __restrict__ residf,
    const __half* __restrict__ resph,
    float* __restrict__ outf,
    __half* __restrict__ outh,
    const float* __restrict__ xin,   // scramble-mode shortcut input
    int Nd, int Kd, int do_gelu, int scram)
{
    extern __shared__ __align__(1024) char smarr[];
    const int tid = threadIdx.x;
    const int lane = tid & 31;
    const int wid = tid >> 5;
    const int bm = blockIdx.y * 128;
    const int bn = blockIdx.x * 128;
    const int wm = (wid >> 2) * 64;
    const int wn = (wid & 3) * 32;
    const uint32_t smb = smem_u32(smarr);

    const int cpc = tid & 7;
    const int cpr = tid >> 3;

    float acc[4][4][4];
#pragma unroll
    for (int i = 0; i < 4; i++)
#pragma unroll
        for (int j = 0; j < 4; j++)
#pragma unroll
            for (int r = 0; r < 4; r++) acc[i][j][r] = 0.f;

    const int nchunks = Kd >> 6;

#pragma unroll
    for (int st = 0; st < 2; st++) {
        const int k0 = st << 6;
        uint32_t sb = smb + st * STAGEB;
#pragma unroll
        for (int p = 0; p < 4; p++) {
            int r = cpr + p * 32;
            int off = r * 128 + cpc * 16;
            int sw = off ^ ((off >> 3) & 0x70);
            cp16(sb + sw,         Aa + (size_t)(bm + r) * Kd + k0 + cpc * 8);
            cp16(sb + TILEB + sw, Bw + (size_t)(bn + r) * Kd + k0 + cpc * 8);
        }
        CP_COMMIT();
    }

    const int lrow = (lane & 7) + ((lane >> 3) & 1) * 8;
    const int lhalf = lane >> 4;

    int stage = 0;
    for (int kc = 0; kc < nchunks; kc++) {
        if (kc + 1 < nchunks) { CP_WAIT(1); } else { CP_WAIT(0); }
        __syncthreads();

        if (kc + 2 < nchunks) {
            const int k0 = (kc + 2) << 6;
            int st2 = stage + 2; if (st2 >= NSTAGE) st2 -= NSTAGE;
            uint32_t sb = smb + st2 * STAGEB;
#pragma unroll
            for (int p = 0; p < 4; p++) {
                int r = cpr + p * 32;
                int off = r * 128 + cpc * 16;
                int sw = off ^ ((off >> 3) & 0x70);
                cp16(sb + sw,         Aa + (size_t)(bm + r) * Kd + k0 + cpc * 8);
                cp16(sb + TILEB + sw, Bw + (size_t)(bn + r) * Kd + k0 + cpc * 8);
            }
            CP_COMMIT();
        }

        uint32_t sb = smb + stage * STAGEB;
#pragma unroll
        for (int ks = 0; ks < 4; ks++) {
            uint32_t af[4][4];
#pragma unroll
            for (int mi = 0; mi < 4; mi++) {
                int row = wm + mi * 16 + lrow;
                int off = row * 128 + (ks * 2 + lhalf) * 16;
                int sw = off ^ ((off >> 3) & 0x70);
                LDSM4(af[mi][0], af[mi][1], af[mi][2], af[mi][3], sb + sw);
            }
            uint32_t bw[4][2];
#pragma unroll
            for (int nj2 = 0; nj2 < 2; nj2++) {
                int row = wn + nj2 * 16 + lrow;
                int off = row * 128 + (ks * 2 + lhalf) * 16;
                int sw = off ^ ((off >> 3) & 0x70);
                uint32_t r0, r1, r2, r3;
                LDSM4(r0, r1, r2, r3, sb + TILEB + sw);
                bw[nj2*2+0][0] = r0; bw[nj2*2+0][1] = r2;
                bw[nj2*2+1][0] = r1; bw[nj2*2+1][1] = r3;
            }
#pragma unroll
            for (int mi = 0; mi < 4; mi++)
#pragma unroll
                for (int nj = 0; nj < 4; nj++)
                    MMA_F16(acc[mi][nj], af[mi], bw[nj]);
        }
        if (++stage >= NSTAGE) stage = 0;
    }

    if (!scram) {
        // ---------------- normal epilogue ----------------
#pragma unroll
        for (int mi = 0; mi < 4; mi++)
#pragma unroll
            for (int nj = 0; nj < 4; nj++) {
                int n = bn + wn + nj * 8 + 2 * (lane & 3);
                float b0 = bias[n], b1 = bias[n + 1];
#pragma unroll
                for (int r = 0; r < 2; r++) {
                    int m = bm + wm + mi * 16 + (lane >> 2) + r * 8;
                    size_t idx = (size_t)m * Nd + n;
                    float v0 = acc[mi][nj][r*2+0] + b0;
                    float v1 = acc[mi][nj][r*2+1] + b1;
                    if (residf) {
                        float2 rr = *(const float2*)(residf + idx);
                        v0 += rr.x; v1 += rr.y;
                    }
                    if (resph) {
                        uint32_t ph = *(const uint32_t*)((const unsigned short*)resph + idx);
                        v0 += __half2float(__ushort_as_half((unsigned short)(ph & 0xffff)));
                        v1 += __half2float(__ushort_as_half((unsigned short)(ph >> 16)));
                    }
                    if (do_gelu) {
                        v0 = 0.5f * v0 * (1.f + erff(v0 * 0.70710678118654752f));
                        v1 = 0.5f * v1 * (1.f + erff(v1 * 0.70710678118654752f));
                    }
                    if (outf) *(float2*)(outf + idx) = make_float2(v0, v1);
                    if (outh) {
                        unsigned short h0 = __half_as_ushort(__float2half_rn(v0));
                        unsigned short h1 = __half_as_ushort(__float2half_rn(v1));
                        *(uint32_t*)((unsigned short*)outh + idx) =
                            (uint32_t)h0 | ((uint32_t)h1 << 16);
                    }
                }
            }
    } else {
        // ------- scramble epilogue: x1.flat[b, (bn+n)*Ll + l] = v + x.flat ------
        __syncthreads();                         // smem stages no longer needed
        float (*tile)[132] = (float(*)[132])smarr;
#pragma unroll
        for (int mi = 0; mi < 4; mi++)
#pragma unroll
            for (int nj = 0; nj < 4; nj++) {
                int nl = wn + nj * 8 + 2 * (lane & 3);
                float b0 = bias[bn + nl], b1 = bias[bn + nl + 1];
#pragma unroll
                for (int r = 0; r < 2; r++) {
                    int ml = wm + mi * 16 + (lane >> 2) + r * 8;
                    size_t idx = (size_t)(bm + ml) * Nd + bn + nl;
                    uint32_t ph = *(const uint32_t*)((const unsigned short*)resph + idx);
                    float v0 = acc[mi][nj][r*2+0] + b0
                             + __half2float(__ushort_as_half((unsigned short)(ph & 0xffff)));
                    float v1 = acc[mi][nj][r*2+1] + b1
                             + __half2float(__ushort_as_half((unsigned short)(ph >> 16)));
                    tile[nl][ml]     = v0;
                    tile[nl + 1][ml] = v1;
                }
            }
        __syncthreads();
        const int b = bm / Ll;
        const int l0 = bm % Ll;
        const int c = tid >> 1;
        const int part = tid & 1;
        size_t base = (size_t)b * Cc * Ll + (size_t)(bn + c) * Ll + l0 + part * 64;
        const float* xb = xin + base;
        float* ob = outf + base;
#pragma unroll
        for (int j = 0; j < 16; j++) {
            float4 t4 = *(const float4*)&tile[c][part * 64 + j * 4];
            float4 x4 = *(const float4*)(xb + j * 4);
            t4.x += x4.x; t4.y += x4.y; t4.z += x4.z; t4.w += x4.w;
            *(float4*)(ob + j * 4) = t4;
        }
    }
}

// -------- column softmax stats over L (k = cols 0..511 of fused kv, fp16) ------
__global__ void ksm_stats(const __half* __restrict__ kv,
                          float* __restrict__ cmax, float* __restrict__ csum)
{
    int b  = blockIdx.x;
    int ch = blockIdx.y * 32 + threadIdx.x;
    float m = -1e30f, s = 0.f;
    for (int l = threadIdx.y; l < Ll; l += 8) {
        float v = __half2float(kv[((size_t)b * Ll + l) * 1024 + ch]);
        if (v > m) { s = s * expf(m - v) + 1.f; m = v; }
        else       { s += expf(v - m); }
    }
    __shared__ float sm[8][32], ss[8][32];
    sm[threadIdx.y][threadIdx.x] = m;
    ss[threadIdx.y][threadIdx.x] = s;
    __syncthreads();
    if (threadIdx.y == 0) {
        for (int i = 1; i < 8; i++) {
            float m2 = sm[i][threadIdx.x], s2 = ss[i][threadIdx.x];
            if (m2 > m) { s = s * expf(m - m2) + s2; m = m2; }
            else        { s += s2 * expf(m2 - m); }
        }
        cmax[b * Cc + ch] = m;
        csum[b * Cc + ch] = s;
    }
}

// -------- context partial: atomicAdd over L segments (fp16 kv) -----------------
__global__ __launch_bounds__(256) void context_kernel(const __half* __restrict__ kv,
                                                      const float* __restrict__ cmax,
                                                      const float* __restrict__ csum,
                                                      float* __restrict__ ctx)
{
    int bh = blockIdx.x;
    int b = bh >> 3, h = bh & 7;
    int ch0 = h * 64;
    int seg = blockIdx.y;
    const int SEG = Ll / 8;
    __shared__ float ks[16][64], vs[16][64];
    __shared__ float smax[64], ssum[64];
    int tid = threadIdx.x;
    int tx = tid & 15, ty = tid >> 4;
    if (tid < 64) { smax[tid] = cmax[b * Cc + ch0 + tid]; ssum[tid] = csum[b * Cc + ch0 + tid]; }
    __syncthreads();
    float acc[4][4];
#pragma unroll
    for (int i = 0; i < 4; i++)
#pragma unroll
        for (int j = 0; j < 4; j++) acc[i][j] = 0.f;

    for (int l0 = seg * SEG; l0 < (seg + 1) * SEG; l0 += 16) {
#pragma unroll
        for (int i = 0; i < 4; i++) {
            int idx = tid + i * 256;
            int r = idx >> 6;
            int c = idx & 63;
            size_t off = ((size_t)b * Ll + l0 + r) * 1024 + ch0 + c;
            ks[r][c] = expf(__half2float(kv[off]) - smax[c]) / ssum[c];
            vs[r][c] = __half2float(kv[off + 512]);
        }
        __syncthreads();
#pragma unroll
        for (int kk = 0; kk < 16; kk++) {
            float rk[4], rv[4];
#pragma unroll
            for (int i = 0; i < 4; i++) rk[i] = ks[kk][ty*4 + i];
#pragma unroll
            for (int j = 0; j < 4; j++) rv[j] = vs[kk][tx*4 + j];
#pragma unroll
            for (int i = 0; i < 4; i++)
#pragma unroll
                for (int j = 0; j < 4; j++)
                    acc[i][j] += rk[i] * rv[j];
        }
        __syncthreads();
    }
#pragma unroll
    for (int i = 0; i < 4; i++)
#pragma unroll
        for (int j = 0; j < 4; j++)
            atomicAdd(&ctx[((size_t)bh * 64 + ty*4 + i) * 64 + tx*4 + j], acc[i][j]);
}

// -------- ctx fp32 [kc][vc] -> fp16 transposed [vc][kc] ------------------------
__global__ void ctx_cvt(const float* __restrict__ ctx, __half* __restrict__ ctxT)
{
    int bh = blockIdx.x;
    for (int i = threadIdx.x; i < 4096; i += 256) {
        int vc = i >> 6, kc = i & 63;
        ctxT[(size_t)bh * 4096 + i] =
            __float2half_rn(ctx[(size_t)bh * 4096 + kc * 64 + vc]);
    }
}

// -------- attend: in-smem q softmax + [128x64] @ ctxT[64x64] via mma -----------
__global__ __launch_bounds__(256) void attend_gemm(const __half* __restrict__ q,
                                                   const __half* __restrict__ ctxT,
                                                   __half* __restrict__ att)
{
    __shared__ __align__(1024) char sm[16384 + 8192];
    const int tid = threadIdx.x;
    const int lane = tid & 31;
    const int wid = tid >> 5;
    const int bh = blockIdx.y;
    const int b = bh >> 3, h = bh & 7;
    const int lt = blockIdx.x * 128;
    const uint32_t smb = smem_u32(sm);

    // load q tile (A: 128 rows x 64 ch) and ctxT (B: 64 x 64), SW swizzled
#pragma unroll
    for (int p = 0; p < 4; p++) {
        int idx = tid + p * 256;
        int r = idx >> 3, c16 = idx & 7;
        int off = r * 128 + c16 * 16;
        int sw = off ^ ((off >> 3) & 0x70);
        cp16(smb + sw, q + (size_t)(b * Ll + lt + r) * 512 + h * 64 + c16 * 8);
    }
#pragma unroll
    for (int p = 0; p < 2; p++) {
        int idx = tid + p * 256;
        int r = idx >> 3, c16 = idx & 7;
        int off = r * 128 + c16 * 16;
        int sw = off ^ ((off >> 3) & 0x70);
        cp16(smb + 16384 + sw, ctxT + (size_t)bh * 4096 + r * 64 + c16 * 8);
    }
    CP_COMMIT(); CP_WAIT(0);
    __syncthreads();

    // per-row softmax of A in-place (128 threads, one row each)
    if (tid < 128) {
        float vals[64];
#pragma unroll
        for (int c16 = 0; c16 < 8; c16++) {
            int off = tid * 128 + c16 * 16;
            int sw = off ^ ((off >> 3) & 0x70);
            uint4 u = *(const uint4*)(sm + sw);
            const __half* hp = (const __half*)&u;
#pragma unroll
            for (int t = 0; t < 8; t++) vals[c16*8 + t] = __half2float(hp[t]);
        }
        float m = vals[0];
#pragma unroll
        for (int i = 1; i < 64; i++) m = fmaxf(m, vals[i]);
        float s = 0.f;
#pragma unroll
        for (int i = 0; i < 64; i++) { vals[i] = expf(vals[i] - m); s += vals[i]; }
        float inv = 1.f / s;
#pragma unroll
        for (int c16 = 0; c16 < 8; c16++) {
            int off = tid * 128 + c16 * 16;
            int sw = off ^ ((off >> 3) & 0x70);
            __half hv[8];
#pragma unroll
            for (int t = 0; t < 8; t++) hv[t] = __float2half_rn(vals[c16*8 + t] * inv);
            *(uint4*)(sm + sw) = *(const uint4*)hv;
        }
    }
    __syncthreads();

    // mma: warp tile 32x32; 8 warps cover 128x64
    const int wm = (wid >> 1) * 32;
    const int wn = (wid & 1) * 32;
    const int lrow = (lane & 7) + ((lane >> 3) & 1) * 8;
    const int lhalf = lane >> 4;
    float acc[2][4][4];
#pragma unroll
    for (int i = 0; i < 2; i++)
#pragma unroll
        for (int j = 0; j < 4; j++)
#pragma unroll
            for (int r = 0; r < 4; r++) acc[i][j][r] = 0.f;

#pragma unroll
    for (int ks = 0; ks < 4; ks++) {
        uint32_t af[2][4];
#pragma unroll
        for (int mi = 0; mi < 2; mi++) {
            int row = wm + mi * 16 + lrow;
            int off = row * 128 + (ks * 2 + lhalf) * 16;
            int sw = off ^ ((off >> 3) & 0x70);
            LDSM4(af[mi][0], af[mi][1], af[mi][2], af[mi][3], smb + sw);
        }
        uint32_t bw[4][2];
#pragma unroll
        for (int nj2 = 0; nj2 < 2; nj2++) {
            int row = wn + nj2 * 16 + lrow;
            int off = row * 128 + (ks * 2 + lhalf) * 16;
            int sw = off ^ ((off >> 3) & 0x70);
            uint32_t r0, r1, r2, r3;
            LDSM4(r0, r1, r2, r3, smb + 16384 + sw);
            bw[nj2*2+0][0] = r0; bw[nj2*2+0][1] = r2;
            bw[nj2*2+1][0] = r1; bw[nj2*2+1][1] = r3;
        }
#pragma unroll
        for (int mi = 0; mi < 2; mi++)
#pragma unroll
            for (int nj = 0; nj < 4; nj++)
                MMA_F16(acc[mi][nj], af[mi], bw[nj]);
    }

#pragma unroll
    for (int mi = 0; mi < 2; mi++)
#pragma unroll
        for (int nj = 0; nj < 4; nj++) {
            int n = wn + nj * 8 + 2 * (lane & 3);
#pragma unroll
            for (int r = 0; r < 2; r++) {
                int m = wm + mi * 16 + (lane >> 2) + r * 8;
                size_t o = (size_t)(b * Ll + lt + m) * 512 + h * 64 + n;
                unsigned short h0 = __half_as_ushort(__float2half_rn(acc[mi][nj][r*2+0]));
                unsigned short h1 = __half_as_ushort(__float2half_rn(acc[mi][nj][r*2+1]));
                *(uint32_t*)((unsigned short*)att + o) = (uint32_t)h0 | ((uint32_t)h1 << 16);
            }
        }
}

// ------------------------------- driver ---------------------------------------
extern "C" void kernel_launch(void* const* d_in, const int* in_sizes, int n_in,
                              void* d_out, int out_size)
{
    const float* x     = (const float*)d_in[0];
    const float* v     = (const float*)d_in[1];
    const float* ln1w  = (const float*)d_in[4];
    const float* ln1b  = (const float*)d_in[5];
    const float* lnvw  = (const float*)d_in[6];
    const float* lnvb  = (const float*)d_in[7];
    const float* ln2w  = (const float*)d_in[8];
    const float* ln2b  = (const float*)d_in[9];
    const float* wq    = (const float*)d_in[10];
    const float* bq    = (const float*)d_in[11];
    const float* wk    = (const float*)d_in[12];
    const float* bk    = (const float*)d_in[13];
    const float* wv    = (const float*)d_in[14];
    const float* bv    = (const float*)d_in[15];
    const float* wr    = (const float*)d_in[16];
    const float* br    = (const float*)d_in[17];
    const float* fc1w  = (const float*)d_in[18];
    const float* fc1b  = (const float*)d_in[19];
    const float* fc2w  = (const float*)d_in[20];
    const float* fc2b  = (const float*)d_in[21];
    float* out = (float*)d_out;

    float *p_ctx, *p_cmax, *p_csum, *p_bkv;
    __half *p_q16, *p_kv16, *p_xn, *p_vn, *p_att, *p_h, *p_ctxT;
    __half *p_wq, *p_wkv, *p_wr, *p_f1, *p_f2;
    cudaGetSymbolAddress((void**)&p_ctx, g_ctx);
    cudaGetSymbolAddress((void**)&p_ctxT, g_ctxT);
    cudaGetSymbolAddress((void**)&p_cmax, g_cmax);
    cudaGetSymbolAddress((void**)&p_csum, g_csum);
    cudaGetSymbolAddress((void**)&p_bkv, g_bkv);
    cudaGetSymbolAddress((void**)&p_q16, g_q16);
    cudaGetSymbolAddress((void**)&p_kv16, g_kv16);
    cudaGetSymbolAddress((void**)&p_xn,  g_xn);
    cudaGetSymbolAddress((void**)&p_vn,  g_vn);
    cudaGetSymbolAddress((void**)&p_att, g_att);
    cudaGetSymbolAddress((void**)&p_h,   g_h);
    cudaGetSymbolAddress((void**)&p_wq,  g_wq16);
    cudaGetSymbolAddress((void**)&p_wkv, g_wkv16);
    cudaGetSymbolAddress((void**)&p_wr,  g_wr16);
    cudaGetSymbolAddress((void**)&p_f1,  g_f116);
    cudaGetSymbolAddress((void**)&p_f2,  g_f216);

    cudaFuncSetAttribute(gemm_mma, cudaFuncAttributeMaxDynamicSharedMemorySize, SMEM_SZ);

    dim3 g512(Cc / 128, Mm / 128);     // (4, 576)
    dim3 g1024(1024 / 128, Mm / 128);  // (8, 576)
    dim3 g2048(HID / 128, Mm / 128);   // (16, 576)

    convert_kernel<<<(Cc*Cc + 255)/256, 256>>>(wq, p_wq, Cc*Cc);
    convert_kernel<<<(Cc*Cc + 255)/256, 256>>>(wk, p_wkv, Cc*Cc);
    convert_kernel<<<(Cc*Cc + 255)/256, 256>>>(wv, p_wkv + Cc*Cc, Cc*Cc);
    convert_kernel<<<(Cc*Cc + 255)/256, 256>>>(wr, p_wr, Cc*Cc);
    convert_kernel<<<(HID*Cc + 255)/256, 256>>>(fc1w, p_f1, HID*Cc);
    convert_kernel<<<(Cc*HID + 255)/256, 256>>>(fc2w, p_f2, Cc*HID);
    concat_bias<<<4, 256>>>(bk, bv, p_bkv);
    ln_half<<<Mm / 8, 256>>>(x, ln1w, ln1b, p_xn);
    ln_half<<<Mm / 8, 256>>>(v, lnvw, lnvb, p_vn);

    // projections: q (fp16 out), fused k|v (fp16 out, Nd=1024)
    gemm_mma<<<g512, 256, SMEM_SZ>>>(p_xn, p_wq, bq, nullptr, nullptr,
                                     nullptr, p_q16, nullptr, Cc, Cc, 0, 0);
    gemm_mma<<<g1024, 256, SMEM_SZ>>>(p_vn, p_wkv, p_bkv, nullptr, nullptr,
                                      nullptr, p_kv16, nullptr, 1024, Cc, 0, 0);

    // attention core
    ksm_stats<<<dim3(Bb, Cc / 32), dim3(32, 8)>>>(p_kv16, p_cmax, p_csum);
    cudaMemsetAsync(p_ctx, 0, (size_t)Bb*HEADS*64*64*sizeof(float));
    context_kernel<<<dim3(Bb * HEADS, 8), 256>>>(p_kv16, p_cmax, p_csum, p_ctx);
    ctx_cvt<<<Bb * HEADS, 256>>>(p_ctx, p_ctxT);
    attend_gemm<<<dim3(Ll / 128, Bb * HEADS), 256>>>(p_q16, p_ctxT, p_att);

    // reprojection + scramble + shortcut fused -> x1 in d_out
    gemm_mma<<<g512, 256, SMEM_SZ>>>(p_att, p_wr, br, nullptr, p_xn,
                                     out, nullptr, x, Cc, Cc, 0, 1);

    // LN2 -> fp16 (reuse xn buffer)
    ln_half<<<Mm / 8, 256>>>(out, ln2w, ln2b, p_xn);

    // MLP: fc1 (+exact GELU, fp16 out), fc2 (+residual from d_out)
    gemm_mma<<<g2048, 256, SMEM_SZ>>>(p_xn, p_f1, fc1b, nullptr, nullptr,
                                      nullptr, p_h, nullptr, HID, Cc, 1, 0);
    gemm_mma<<<g512, 256, SMEM_SZ>>>(p_h, p_f2, fc2b, out, nullptr,
                                     out, nullptr, nullptr, Cc, HID, 0, 0);
}

// round 8
// speedup vs baseline: 6.8374x; 1.0729x over previous
#include <cuda_runtime.h>
#include <cuda_fp16.h>
#include <math.h>
#include <stdint.h>

#define Bb 8
#define Ll 9216
#define Cc 512
#define Mm (Bb*Ll)          // 73728
#define HEADS 8
#define HID 2048

// ---------------- scratch (device globals; no runtime allocation) -------------
__device__ __align__(16) __half g_q16[(size_t)Mm*Cc];
__device__ __align__(16) __half g_kv16[(size_t)Mm*1024];    // k | val fused; k half becomes expk
__device__ __align__(16) __half g_xn[(size_t)Mm*Cc];
__device__ __align__(16) __half g_vn[(size_t)Mm*Cc];
__device__ __align__(16) __half g_att[(size_t)Mm*Cc];
__device__ __align__(16) __half g_h [(size_t)Mm*HID];
__device__ __align__(16) __half g_wq16[Cc*Cc];
__device__ __align__(16) __half g_wkv16[2*Cc*Cc];           // wk | wv fused
__device__ __align__(16) __half g_wr16[Cc*Cc];
__device__ __align__(16) __half g_f116[HID*Cc];
__device__ __align__(16) __half g_f216[Cc*HID];
__device__ float g_bkv[1024];
__device__ float g_ctx[Bb*HEADS*64*64];
__device__ __align__(16) __half g_ctxT[Bb*HEADS*64*64];
__device__ float g_cmax[Bb*Cc];
__device__ float g_csum[Bb*Cc];

// ---------------- small helpers ----------------
__device__ __forceinline__ uint32_t smem_u32(const void* p) {
    return (uint32_t)__cvta_generic_to_shared(p);
}
__device__ __forceinline__ void cp16(uint32_t dst, const void* src) {
    asm volatile("cp.async.cg.shared.global [%0], [%1], 16;" :: "r"(dst), "l"(src));
}
#define CP_COMMIT() asm volatile("cp.async.commit_group;" ::: "memory")
#define CP_WAIT(N)  asm volatile("cp.async.wait_group %0;" :: "n"(N) : "memory")

#define LDSM4(r0, r1, r2, r3, addr) \
    asm volatile("ldmatrix.sync.aligned.m8n8.x4.shared.b16 {%0,%1,%2,%3}, [%4];" \
                 : "=r"(r0), "=r"(r1), "=r"(r2), "=r"(r3) : "r"(addr))

#define MMA_F16(d, a, b) \
    asm volatile("mma.sync.aligned.m16n8k16.row.col.f32.f16.f16.f32 " \
                 "{%0,%1,%2,%3}, {%4,%5,%6,%7}, {%8,%9}, {%0,%1,%2,%3};" \
                 : "+f"((d)[0]), "+f"((d)[1]), "+f"((d)[2]), "+f"((d)[3]) \
                 : "r"((a)[0]), "r"((a)[1]), "r"((a)[2]), "r"((a)[3]), \
                   "r"((b)[0]), "r"((b)[1]))

// ---------------- LayerNorm -> fp16 output ------------------------------------
__global__ __launch_bounds__(256) void ln_half(const float* __restrict__ x,
                                               const float* __restrict__ w,
                                               const float* __restrict__ b,
                                               __half* __restrict__ y)
{
    int row = blockIdx.x * 8 + (threadIdx.x >> 5);
    int lane = threadIdx.x & 31;
    const float* xr = x + (size_t)row * Cc;
    float4 v[4];
    float s = 0.f, s2 = 0.f;
#pragma unroll
    for (int i = 0; i < 4; i++) {
        v[i] = *(const float4*)(xr + lane * 4 + i * 128);
        s  += v[i].x + v[i].y + v[i].z + v[i].w;
        s2 += v[i].x*v[i].x + v[i].y*v[i].y + v[i].z*v[i].z + v[i].w*v[i].w;
    }
#pragma unroll
    for (int o = 16; o; o >>= 1) {
        s  += __shfl_xor_sync(0xffffffffu, s,  o);
        s2 += __shfl_xor_sync(0xffffffffu, s2, o);
    }
    float mean = s * (1.f/512.f);
    float var  = s2 * (1.f/512.f) - mean*mean;
    float rstd = rsqrtf(var + 1e-5f);
#pragma unroll
    for (int i = 0; i < 4; i++) {
        int c = lane * 4 + i * 128;
        float4 wv = *(const float4*)(w + c);
        float4 bv = *(const float4*)(b + c);
        ushort4 sh;
        sh.x = __half_as_ushort(__float2half_rn((v[i].x - mean) * rstd * wv.x + bv.x));
        sh.y = __half_as_ushort(__float2half_rn((v[i].y - mean) * rstd * wv.y + bv.y));
        sh.z = __half_as_ushort(__float2half_rn((v[i].z - mean) * rstd * wv.z + bv.z));
        sh.w = __half_as_ushort(__float2half_rn((v[i].w - mean) * rstd * wv.w + bv.w));
        *(ushort4*)(y + (size_t)row * Cc + c) = sh;
    }
}

// ---------------- weight fp32 -> fp16 ; bias concat ----------------------------
__global__ void convert_kernel(const float* __restrict__ w,
                               __half* __restrict__ o, int n)
{
    int i = blockIdx.x * 256 + threadIdx.x;
    if (i < n) o[i] = __float2half_rn(w[i]);
}
__global__ void concat_bias(const float* __restrict__ bk,
                            const float* __restrict__ bv,
                            float* __restrict__ o)
{
    int i = blockIdx.x * 256 + threadIdx.x;
    if (i < 512) o[i] = bk[i];
    else if (i < 1024) o[i] = bv[i - 512];
}

// ------------- fp16 mma.sync GEMM, 3-stage cp.async pipeline -------------------
#define TILEB 16384
#define STAGEB (2*TILEB)
#define NSTAGE 3
#define SMEM_SZ (NSTAGE*STAGEB)   // 98304; also >= 128*132*4 for scram tile

__global__ __launch_bounds__(256, 2) void gemm_mma(
    const __half* __restrict__ Aa,
    const __half* __restrict__ Bw,
    const float* __restrict__ bias,
    const float* __restrict__ residf,
    const __half* __restrict__ resph,
    float* __restrict__ outf,
    __half* __restrict__ outh,
    const float* __restrict__ xin,   // scramble-mode shortcut input
    int Nd, int Kd, int do_gelu, int scram)
{
    extern __shared__ __align__(1024) char smarr[];
    const int tid = threadIdx.x;
    const int lane = tid & 31;
    const int wid = tid >> 5;
    const int bm = blockIdx.y * 128;
    const int bn = blockIdx.x * 128;
    const int wm = (wid >> 2) * 64;
    const int wn = (wid & 3) * 32;
    const uint32_t smb = smem_u32(smarr);

    const int cpc = tid & 7;
    const int cpr = tid >> 3;

    float acc[4][4][4];
#pragma unroll
    for (int i = 0; i < 4; i++)
#pragma unroll
        for (int j = 0; j < 4; j++)
#pragma unroll
            for (int r = 0; r < 4; r++) acc[i][j][r] = 0.f;

    const int nchunks = Kd >> 6;

#pragma unroll
    for (int st = 0; st < 2; st++) {
        const int k0 = st << 6;
        uint32_t sb = smb + st * STAGEB;
#pragma unroll
        for (int p = 0; p < 4; p++) {
            int r = cpr + p * 32;
            int off = r * 128 + cpc * 16;
            int sw = off ^ ((off >> 3) & 0x70);
            cp16(sb + sw,         Aa + (size_t)(bm + r) * Kd + k0 + cpc * 8);
            cp16(sb + TILEB + sw, Bw + (size_t)(bn + r) * Kd + k0 + cpc * 8);
        }
        CP_COMMIT();
    }

    const int lrow = (lane & 7) + ((lane >> 3) & 1) * 8;
    const int lhalf = lane >> 4;

    int stage = 0;
    for (int kc = 0; kc < nchunks; kc++) {
        if (kc + 1 < nchunks) { CP_WAIT(1); } else { CP_WAIT(0); }
        __syncthreads();

        if (kc + 2 < nchunks) {
            const int k0 = (kc + 2) << 6;
            int st2 = stage + 2; if (st2 >= NSTAGE) st2 -= NSTAGE;
            uint32_t sb = smb + st2 * STAGEB;
#pragma unroll
            for (int p = 0; p < 4; p++) {
                int r = cpr + p * 32;
                int off = r * 128 + cpc * 16;
                int sw = off ^ ((off >> 3) & 0x70);
                cp16(sb + sw,         Aa + (size_t)(bm + r) * Kd + k0 + cpc * 8);
                cp16(sb + TILEB + sw, Bw + (size_t)(bn + r) * Kd + k0 + cpc * 8);
            }
            CP_COMMIT();
        }

        uint32_t sb = smb + stage * STAGEB;
#pragma unroll
        for (int ks = 0; ks < 4; ks++) {
            uint32_t af[4][4];
#pragma unroll
            for (int mi = 0; mi < 4; mi++) {
                int row = wm + mi * 16 + lrow;
                int off = row * 128 + (ks * 2 + lhalf) * 16;
                int sw = off ^ ((off >> 3) & 0x70);
                LDSM4(af[mi][0], af[mi][1], af[mi][2], af[mi][3], sb + sw);
            }
            uint32_t bw[4][2];
#pragma unroll
            for (int nj2 = 0; nj2 < 2; nj2++) {
                int row = wn + nj2 * 16 + lrow;
                int off = row * 128 + (ks * 2 + lhalf) * 16;
                int sw = off ^ ((off >> 3) & 0x70);
                uint32_t r0, r1, r2, r3;
                LDSM4(r0, r1, r2, r3, sb + TILEB + sw);
                bw[nj2*2+0][0] = r0; bw[nj2*2+0][1] = r2;
                bw[nj2*2+1][0] = r1; bw[nj2*2+1][1] = r3;
            }
#pragma unroll
            for (int mi = 0; mi < 4; mi++)
#pragma unroll
                for (int nj = 0; nj < 4; nj++)
                    MMA_F16(acc[mi][nj], af[mi], bw[nj]);
        }
        if (++stage >= NSTAGE) stage = 0;
    }

    if (!scram) {
#pragma unroll
        for (int mi = 0; mi < 4; mi++)
#pragma unroll
            for (int nj = 0; nj < 4; nj++) {
                int n = bn + wn + nj * 8 + 2 * (lane & 3);
                float b0 = bias[n], b1 = bias[n + 1];
#pragma unroll
                for (int r = 0; r < 2; r++) {
                    int m = bm + wm + mi * 16 + (lane >> 2) + r * 8;
                    size_t idx = (size_t)m * Nd + n;
                    float v0 = acc[mi][nj][r*2+0] + b0;
                    float v1 = acc[mi][nj][r*2+1] + b1;
                    if (residf) {
                        float2 rr = *(const float2*)(residf + idx);
                        v0 += rr.x; v1 += rr.y;
                    }
                    if (resph) {
                        uint32_t ph = *(const uint32_t*)((const unsigned short*)resph + idx);
                        v0 += __half2float(__ushort_as_half((unsigned short)(ph & 0xffff)));
                        v1 += __half2float(__ushort_as_half((unsigned short)(ph >> 16)));
                    }
                    if (do_gelu) {
                        v0 = 0.5f * v0 * (1.f + erff(v0 * 0.70710678118654752f));
                        v1 = 0.5f * v1 * (1.f + erff(v1 * 0.70710678118654752f));
                    }
                    if (outf) *(float2*)(outf + idx) = make_float2(v0, v1);
                    if (outh) {
                        unsigned short h0 = __half_as_ushort(__float2half_rn(v0));
                        unsigned short h1 = __half_as_ushort(__float2half_rn(v1));
                        *(uint32_t*)((unsigned short*)outh + idx) =
                            (uint32_t)h0 | ((uint32_t)h1 << 16);
                    }
                }
            }
    } else {
        // ------- scramble epilogue: x1.flat[b, (bn+n)*Ll + l] = v + x.flat ------
        __syncthreads();
        float (*tile)[132] = (float(*)[132])smarr;
#pragma unroll
        for (int mi = 0; mi < 4; mi++)
#pragma unroll
            for (int nj = 0; nj < 4; nj++) {
                int nl = wn + nj * 8 + 2 * (lane & 3);
                float b0 = bias[bn + nl], b1 = bias[bn + nl + 1];
#pragma unroll
                for (int r = 0; r < 2; r++) {
                    int ml = wm + mi * 16 + (lane >> 2) + r * 8;
                    size_t idx = (size_t)(bm + ml) * Nd + bn + nl;
                    uint32_t ph = *(const uint32_t*)((const unsigned short*)resph + idx);
                    float v0 = acc[mi][nj][r*2+0] + b0
                             + __half2float(__ushort_as_half((unsigned short)(ph & 0xffff)));
                    float v1 = acc[mi][nj][r*2+1] + b1
                             + __half2float(__ushort_as_half((unsigned short)(ph >> 16)));
                    tile[nl][ml]     = v0;
                    tile[nl + 1][ml] = v1;
                }
            }
        __syncthreads();
        const int b = bm / Ll;
        const int l0 = bm % Ll;
        const int c = tid >> 1;
        const int part = tid & 1;
        size_t base = (size_t)b * Cc * Ll + (size_t)(bn + c) * Ll + l0 + part * 64;
        const float* xb = xin + base;
        float* ob = outf + base;
#pragma unroll
        for (int j = 0; j < 16; j++) {
            float4 t4 = *(const float4*)&tile[c][part * 64 + j * 4];
            float4 x4 = *(const float4*)(xb + j * 4);
            t4.x += x4.x; t4.y += x4.y; t4.z += x4.z; t4.w += x4.w;
            *(float4*)(ob + j * 4) = t4;
        }
    }
}

// -------- column max over L (k = cols 0..511 of fused kv) ----------------------
__global__ void kmax_kernel(const __half* __restrict__ kv,
                            float* __restrict__ cmax)
{
    int b  = blockIdx.x;
    int ch = blockIdx.y * 32 + threadIdx.x;
    float m = -1e30f;
    for (int l = threadIdx.y; l < Ll; l += 8)
        m = fmaxf(m, __half2float(kv[((size_t)b * Ll + l) * 1024 + ch]));
    __shared__ float sm[8][32];
    sm[threadIdx.y][threadIdx.x] = m;
    __syncthreads();
    if (threadIdx.y == 0) {
        for (int i = 1; i < 8; i++) m = fmaxf(m, sm[i][threadIdx.x]);
        cmax[b * Cc + ch] = m;
    }
}

// -------- expk in-place (k half of kv) + column sums (L-split, atomic) ---------
__global__ void kexp_kernel(__half* __restrict__ kv,
                            const float* __restrict__ cmax,
                            float* __restrict__ csum)
{
    int b  = blockIdx.x;
    int ch = blockIdx.y * 32 + threadIdx.x;
    int seg = blockIdx.z;
    const int SEG = Ll / 8;
    float mx = cmax[b * Cc + ch];
    float s = 0.f;
    for (int l = seg * SEG + threadIdx.y; l < (seg + 1) * SEG; l += 8) {
        size_t off = ((size_t)b * Ll + l) * 1024 + ch;
        float e = expf(__half2float(kv[off]) - mx);
        __half h = __float2half_rn(e);
        kv[off] = h;
        s += __half2float(h);
    }
    __shared__ float ss[8][32];
    ss[threadIdx.y][threadIdx.x] = s;
    __syncthreads();
    if (threadIdx.y == 0) {
        for (int i = 1; i < 8; i++) s += ss[i][threadIdx.x];
        atomicAdd(&csum[b * Cc + ch], s);
    }
}

// -------- context partial: pure MAC of expk (k half) x val (v half) ------------
__global__ __launch_bounds__(256) void context_kernel(const __half* __restrict__ kv,
                                                      float* __restrict__ ctx)
{
    int bh = blockIdx.x;
    int b = bh >> 3, h = bh & 7;
    int ch0 = h * 64;
    int seg = blockIdx.y;
    const int SEG = Ll / 8;
    __shared__ float ks[16][64], vs[16][64];
    int tid = threadIdx.x;
    int tx = tid & 15, ty = tid >> 4;
    float acc[4][4];
#pragma unroll
    for (int i = 0; i < 4; i++)
#pragma unroll
        for (int j = 0; j < 4; j++) acc[i][j] = 0.f;

    for (int l0 = seg * SEG; l0 < (seg + 1) * SEG; l0 += 16) {
#pragma unroll
        for (int i = 0; i < 4; i++) {
            int idx = tid + i * 256;
            int r = idx >> 6;
            int c = idx & 63;
            size_t off = ((size_t)b * Ll + l0 + r) * 1024 + ch0 + c;
            ks[r][c] = __half2float(kv[off]);
            vs[r][c] = __half2float(kv[off + 512]);
        }
        __syncthreads();
#pragma unroll
        for (int kk = 0; kk < 16; kk++) {
            float rk[4], rv[4];
#pragma unroll
            for (int i = 0; i < 4; i++) rk[i] = ks[kk][ty*4 + i];
#pragma unroll
            for (int j = 0; j < 4; j++) rv[j] = vs[kk][tx*4 + j];
#pragma unroll
            for (int i = 0; i < 4; i++)
#pragma unroll
                for (int j = 0; j < 4; j++)
                    acc[i][j] += rk[i] * rv[j];
        }
        __syncthreads();
    }
#pragma unroll
    for (int i = 0; i < 4; i++)
#pragma unroll
        for (int j = 0; j < 4; j++)
            atomicAdd(&ctx[((size_t)bh * 64 + ty*4 + i) * 64 + tx*4 + j], acc[i][j]);
}

// -------- ctx fp32 [kc][vc] -> fp16 transposed [vc][kc], with 1/csum[kc] -------
__global__ void ctx_cvt(const float* __restrict__ ctx,
                        const float* __restrict__ csum,
                        __half* __restrict__ ctxT)
{
    int bh = blockIdx.x;
    int b = bh >> 3, h = bh & 7;
    for (int i = threadIdx.x; i < 4096; i += 256) {
        int vc = i >> 6, kc = i & 63;
        float inv = 1.f / csum[b * Cc + h * 64 + kc];
        ctxT[(size_t)bh * 4096 + i] =
            __float2half_rn(ctx[(size_t)bh * 4096 + kc * 64 + vc] * inv);
    }
}

// -------- attend: in-smem q softmax + [128x64] @ ctxT[64x64] via mma -----------
__global__ __launch_bounds__(256) void attend_gemm(const __half* __restrict__ q,
                                                   const __half* __restrict__ ctxT,
                                                   __half* __restrict__ att)
{
    __shared__ __align__(1024) char sm[16384 + 8192];
    const int tid = threadIdx.x;
    const int lane = tid & 31;
    const int wid = tid >> 5;
    const int bh = blockIdx.y;
    const int b = bh >> 3, h = bh & 7;
    const int lt = blockIdx.x * 128;
    const uint32_t smb = smem_u32(sm);

#pragma unroll
    for (int p = 0; p < 4; p++) {
        int idx = tid + p * 256;
        int r = idx >> 3, c16 = idx & 7;
        int off = r * 128 + c16 * 16;
        int sw = off ^ ((off >> 3) & 0x70);
        cp16(smb + sw, q + (size_t)(b * Ll + lt + r) * 512 + h * 64 + c16 * 8);
    }
#pragma unroll
    for (int p = 0; p < 2; p++) {
        int idx = tid + p * 256;
        int r = idx >> 3, c16 = idx & 7;
        int off = r * 128 + c16 * 16;
        int sw = off ^ ((off >> 3) & 0x70);
        cp16(smb + 16384 + sw, ctxT + (size_t)bh * 4096 + r * 64 + c16 * 8);
    }
    CP_COMMIT(); CP_WAIT(0);
    __syncthreads();

    if (tid < 128) {
        float vals[64];
#pragma unroll
        for (int c16 = 0; c16 < 8; c16++) {
            int off = tid * 128 + c16 * 16;
            int sw = off ^ ((off >> 3) & 0x70);
            uint4 u = *(const uint4*)(sm + sw);
            const __half* hp = (const __half*)&u;
#pragma unroll
            for (int t = 0; t < 8; t++) vals[c16*8 + t] = __half2float(hp[t]);
        }
        float m = vals[0];
#pragma unroll
        for (int i = 1; i < 64; i++) m = fmaxf(m, vals[i]);
        float s = 0.f;
#pragma unroll
        for (int i = 0; i < 64; i++) { vals[i] = expf(vals[i] - m); s += vals[i]; }
        float inv = 1.f / s;
#pragma unroll
        for (int c16 = 0; c16 < 8; c16++) {
            int off = tid * 128 + c16 * 16;
            int sw = off ^ ((off >> 3) & 0x70);
            __half hv[8];
#pragma unroll
            for (int t = 0; t < 8; t++) hv[t] = __float2half_rn(vals[c16*8 + t] * inv);
            *(uint4*)(sm + sw) = *(const uint4*)hv;
        }
    }
    __syncthreads();

    const int wm = (wid >> 1) * 32;
    const int wn = (wid & 1) * 32;
    const int lrow = (lane & 7) + ((lane >> 3) & 1) * 8;
    const int lhalf = lane >> 4;
    float acc[2][4][4];
#pragma unroll
    for (int i = 0; i < 2; i++)
#pragma unroll
        for (int j = 0; j < 4; j++)
#pragma unroll
            for (int r = 0; r < 4; r++) acc[i][j][r] = 0.f;

#pragma unroll
    for (int ks = 0; ks < 4; ks++) {
        uint32_t af[2][4];
#pragma unroll
        for (int mi = 0; mi < 2; mi++) {
            int row = wm + mi * 16 + lrow;
            int off = row * 128 + (ks * 2 + lhalf) * 16;
            int sw = off ^ ((off >> 3) & 0x70);
            LDSM4(af[mi][0], af[mi][1], af[mi][2], af[mi][3], smb + sw);
        }
        uint32_t bw[4][2];
#pragma unroll
        for (int nj2 = 0; nj2 < 2; nj2++) {
            int row = wn + nj2 * 16 + lrow;
            int off = row * 128 + (ks * 2 + lhalf) * 16;
            int sw = off ^ ((off >> 3) & 0x70);
            uint32_t r0, r1, r2, r3;
            LDSM4(r0, r1, r2, r3, smb + 16384 + sw);
            bw[nj2*2+0][0] = r0; bw[nj2*2+0][1] = r2;
            bw[nj2*2+1][0] = r1; bw[nj2*2+1][1] = r3;
        }
#pragma unroll
        for (int mi = 0; mi < 2; mi++)
#pragma unroll
            for (int nj = 0; nj < 4; nj++)
                MMA_F16(acc[mi][nj], af[mi], bw[nj]);
    }

#pragma unroll
    for (int mi = 0; mi < 2; mi++)
#pragma unroll
        for (int nj = 0; nj < 4; nj++) {
            int n = wn + nj * 8 + 2 * (lane & 3);
#pragma unroll
            for (int r = 0; r < 2; r++) {
                int m = wm + mi * 16 + (lane >> 2) + r * 8;
                size_t o = (size_t)(b * Ll + lt + m) * 512 + h * 64 + n;
                unsigned short h0 = __half_as_ushort(__float2half_rn(acc[mi][nj][r*2+0]));
                unsigned short h1 = __half_as_ushort(__float2half_rn(acc[mi][nj][r*2+1]));
                *(uint32_t*)((unsigned short*)att + o) = (uint32_t)h0 | ((uint32_t)h1 << 16);
            }
        }
}

// ------------------------------- driver ---------------------------------------
extern "C" void kernel_launch(void* const* d_in, const int* in_sizes, int n_in,
                              void* d_out, int out_size)
{
    const float* x     = (const float*)d_in[0];
    const float* v     = (const float*)d_in[1];
    const float* ln1w  = (const float*)d_in[4];
    const float* ln1b  = (const float*)d_in[5];
    const float* lnvw  = (const float*)d_in[6];
    const float* lnvb  = (const float*)d_in[7];
    const float* ln2w  = (const float*)d_in[8];
    const float* ln2b  = (const float*)d_in[9];
    const float* wq    = (const float*)d_in[10];
    const float* bq    = (const float*)d_in[11];
    const float* wk    = (const float*)d_in[12];
    const float* bk    = (const float*)d_in[13];
    const float* wv    = (const float*)d_in[14];
    const float* bv    = (const float*)d_in[15];
    const float* wr    = (const float*)d_in[16];
    const float* br    = (const float*)d_in[17];
    const float* fc1w  = (const float*)d_in[18];
    const float* fc1b  = (const float*)d_in[19];
    const float* fc2w  = (const float*)d_in[20];
    const float* fc2b  = (const float*)d_in[21];
    float* out = (float*)d_out;

    float *p_ctx, *p_cmax, *p_csum, *p_bkv;
    __half *p_q16, *p_kv16, *p_xn, *p_vn, *p_att, *p_h, *p_ctxT;
    __half *p_wq, *p_wkv, *p_wr, *p_f1, *p_f2;
    cudaGetSymbolAddress((void**)&p_ctx, g_ctx);
    cudaGetSymbolAddress((void**)&p_ctxT, g_ctxT);
    cudaGetSymbolAddress((void**)&p_cmax, g_cmax);
    cudaGetSymbolAddress((void**)&p_csum, g_csum);
    cudaGetSymbolAddress((void**)&p_bkv, g_bkv);
    cudaGetSymbolAddress((void**)&p_q16, g_q16);
    cudaGetSymbolAddress((void**)&p_kv16, g_kv16);
    cudaGetSymbolAddress((void**)&p_xn,  g_xn);
    cudaGetSymbolAddress((void**)&p_vn,  g_vn);
    cudaGetSymbolAddress((void**)&p_att, g_att);
    cudaGetSymbolAddress((void**)&p_h,   g_h);
    cudaGetSymbolAddress((void**)&p_wq,  g_wq16);
    cudaGetSymbolAddress((void**)&p_wkv, g_wkv16);
    cudaGetSymbolAddress((void**)&p_wr,  g_wr16);
    cudaGetSymbolAddress((void**)&p_f1,  g_f116);
    cudaGetSymbolAddress((void**)&p_f2,  g_f216);

    cudaFuncSetAttribute(gemm_mma, cudaFuncAttributeMaxDynamicSharedMemorySize, SMEM_SZ);

    dim3 g512(Cc / 128, Mm / 128);     // (4, 576)
    dim3 g1024(1024 / 128, Mm / 128);  // (8, 576)
    dim3 g2048(HID / 128, Mm / 128);   // (16, 576)

    convert_kernel<<<(Cc*Cc + 255)/256, 256>>>(wq, p_wq, Cc*Cc);
    convert_kernel<<<(Cc*Cc + 255)/256, 256>>>(wk, p_wkv, Cc*Cc);
    convert_kernel<<<(Cc*Cc + 255)/256, 256>>>(wv, p_wkv + Cc*Cc, Cc*Cc);
    convert_kernel<<<(Cc*Cc + 255)/256, 256>>>(wr, p_wr, Cc*Cc);
    convert_kernel<<<(HID*Cc + 255)/256, 256>>>(fc1w, p_f1, HID*Cc);
    convert_kernel<<<(Cc*HID + 255)/256, 256>>>(fc2w, p_f2, Cc*HID);
    concat_bias<<<4, 256>>>(bk, bv, p_bkv);
    ln_half<<<Mm / 8, 256>>>(x, ln1w, ln1b, p_xn);
    ln_half<<<Mm / 8, 256>>>(v, lnvw, lnvb, p_vn);

    // projections: q (fp16 out), fused k|v (fp16 out, Nd=1024)
    gemm_mma<<<g512, 256, SMEM_SZ>>>(p_xn, p_wq, bq, nullptr, nullptr,
                                     nullptr, p_q16, nullptr, Cc, Cc, 0, 0);
    gemm_mma<<<g1024, 256, SMEM_SZ>>>(p_vn, p_wkv, p_bkv, nullptr, nullptr,
                                      nullptr, p_kv16, nullptr, 1024, Cc, 0, 0);

    // attention core: max -> expk(in-place)+sum -> context MAC -> normalize
    kmax_kernel<<<dim3(Bb, Cc / 32), dim3(32, 8)>>>(p_kv16, p_cmax);
    cudaMemsetAsync(p_csum, 0, (size_t)Bb*Cc*sizeof(float));
    kexp_kernel<<<dim3(Bb, Cc / 32, 8), dim3(32, 8)>>>(p_kv16, p_cmax, p_csum);
    cudaMemsetAsync(p_ctx, 0, (size_t)Bb*HEADS*64*64*sizeof(float));
    context_kernel<<<dim3(Bb * HEADS, 8), 256>>>(p_kv16, p_ctx);
    ctx_cvt<<<Bb * HEADS, 256>>>(p_ctx, p_csum, p_ctxT);
    attend_gemm<<<dim3(Ll / 128, Bb * HEADS), 256>>>(p_q16, p_ctxT, p_att);

    // reprojection + scramble + shortcut fused -> x1 in d_out
    gemm_mma<<<g512, 256, SMEM_SZ>>>(p_att, p_wr, br, nullptr, p_xn,
                                     out, nullptr, x, Cc, Cc, 0, 1);

    // LN2 -> fp16 (reuse xn buffer)
    ln_half<<<Mm / 8, 256>>>(out, ln2w, ln2b, p_xn);

    // MLP: fc1 (+exact GELU, fp16 out), fc2 (+residual from d_out)
    gemm_mma<<<g2048, 256, SMEM_SZ>>>(p_xn, p_f1, fc1b, nullptr, nullptr,
                                      nullptr, p_h, nullptr, HID, Cc, 1, 0);
    gemm_mma<<<g512, 256, SMEM_SZ>>>(p_h, p_f2, fc2b, out, nullptr,
                                     out, nullptr, nullptr, Cc, HID, 0, 0);
}

// round 9
// speedup vs baseline: 7.1937x; 1.0521x over previous
#include <cuda_runtime.h>
#include <cuda_fp16.h>
#include <math.h>
#include <stdint.h>

#define Bb 8
#define Ll 9216
#define Cc 512
#define Mm (Bb*Ll)          // 73728
#define HEADS 8
#define HID 2048

// ---------------- scratch (device globals; no runtime allocation) -------------
__device__ __align__(16) __half g_q16[(size_t)Mm*Cc];
__device__ __align__(16) __half g_kv16[(size_t)Mm*1024];    // k | val fused
__device__ __align__(16) __half g_xn[(size_t)Mm*Cc];
__device__ __align__(16) __half g_vn[(size_t)Mm*Cc];
__device__ __align__(16) __half g_att[(size_t)Mm*Cc];
__device__ __align__(16) __half g_h [(size_t)Mm*HID];
__device__ __align__(16) __half g_wq16[Cc*Cc];
__device__ __align__(16) __half g_wkv16[2*Cc*Cc];           // wk | wv fused
__device__ __align__(16) __half g_wr16[Cc*Cc];
__device__ __align__(16) __half g_f116[HID*Cc];
__device__ __align__(16) __half g_f216[Cc*HID];
__device__ float g_bkv[1024];
__device__ float g_ctx[Bb*HEADS*64*64];
__device__ __align__(16) __half g_ctxT[Bb*HEADS*64*64];
__device__ float g_cmax[Bb*Cc];
__device__ float g_csum[Bb*Cc];

// ---------------- small helpers ----------------
__device__ __forceinline__ uint32_t smem_u32(const void* p) {
    return (uint32_t)__cvta_generic_to_shared(p);
}
__device__ __forceinline__ void cp16(uint32_t dst, const void* src) {
    asm volatile("cp.async.cg.shared.global [%0], [%1], 16;" :: "r"(dst), "l"(src));
}
#define CP_COMMIT() asm volatile("cp.async.commit_group;" ::: "memory")
#define CP_WAIT(N)  asm volatile("cp.async.wait_group %0;" :: "n"(N) : "memory")

#define LDSM4(r0, r1, r2, r3, addr) \
    asm volatile("ldmatrix.sync.aligned.m8n8.x4.shared.b16 {%0,%1,%2,%3}, [%4];" \
                 : "=r"(r0), "=r"(r1), "=r"(r2), "=r"(r3) : "r"(addr))

#define LDSM4T(r0, r1, r2, r3, addr) \
    asm volatile("ldmatrix.sync.aligned.m8n8.x4.trans.shared.b16 {%0,%1,%2,%3}, [%4];" \
                 : "=r"(r0), "=r"(r1), "=r"(r2), "=r"(r3) : "r"(addr))

#define MMA_F16(d, a, b) \
    asm volatile("mma.sync.aligned.m16n8k16.row.col.f32.f16.f16.f32 " \
                 "{%0,%1,%2,%3}, {%4,%5,%6,%7}, {%8,%9}, {%0,%1,%2,%3};" \
                 : "+f"((d)[0]), "+f"((d)[1]), "+f"((d)[2]), "+f"((d)[3]) \
                 : "r"((a)[0]), "r"((a)[1]), "r"((a)[2]), "r"((a)[3]), \
                   "r"((b)[0]), "r"((b)[1]))

// ---------------- LayerNorm -> fp16 output ------------------------------------
__global__ __launch_bounds__(256) void ln_half(const float* __restrict__ x,
                                               const float* __restrict__ w,
                                               const float* __restrict__ b,
                                               __half* __restrict__ y)
{
    int row = blockIdx.x * 8 + (threadIdx.x >> 5);
    int lane = threadIdx.x & 31;
    const float* xr = x + (size_t)row * Cc;
    float4 v[4];
    float s = 0.f, s2 = 0.f;
#pragma unroll
    for (int i = 0; i < 4; i++) {
        v[i] = *(const float4*)(xr + lane * 4 + i * 128);
        s  += v[i].x + v[i].y + v[i].z + v[i].w;
        s2 += v[i].x*v[i].x + v[i].y*v[i].y + v[i].z*v[i].z + v[i].w*v[i].w;
    }
#pragma unroll
    for (int o = 16; o; o >>= 1) {
        s  += __shfl_xor_sync(0xffffffffu, s,  o);
        s2 += __shfl_xor_sync(0xffffffffu, s2, o);
    }
    float mean = s * (1.f/512.f);
    float var  = s2 * (1.f/512.f) - mean*mean;
    float rstd = rsqrtf(var + 1e-5f);
#pragma unroll
    for (int i = 0; i < 4; i++) {
        int c = lane * 4 + i * 128;
        float4 wv = *(const float4*)(w + c);
        float4 bv = *(const float4*)(b + c);
        ushort4 sh;
        sh.x = __half_as_ushort(__float2half_rn((v[i].x - mean) * rstd * wv.x + bv.x));
        sh.y = __half_as_ushort(__float2half_rn((v[i].y - mean) * rstd * wv.y + bv.y));
        sh.z = __half_as_ushort(__float2half_rn((v[i].z - mean) * rstd * wv.z + bv.z));
        sh.w = __half_as_ushort(__float2half_rn((v[i].w - mean) * rstd * wv.w + bv.w));
        *(ushort4*)(y + (size_t)row * Cc + c) = sh;
    }
}

// ---------------- weight fp32 -> fp16 ; bias concat ----------------------------
__global__ void convert_kernel(const float* __restrict__ w,
                               __half* __restrict__ o, int n)
{
    int i = blockIdx.x * 256 + threadIdx.x;
    if (i < n) o[i] = __float2half_rn(w[i]);
}
__global__ void concat_bias(const float* __restrict__ bk,
                            const float* __restrict__ bv,
                            float* __restrict__ o)
{
    int i = blockIdx.x * 256 + threadIdx.x;
    if (i < 512) o[i] = bk[i];
    else if (i < 1024) o[i] = bv[i - 512];
}

// ------------- fp16 mma.sync GEMM, 3-stage cp.async pipeline -------------------
#define TILEB 16384
#define STAGEB (2*TILEB)
#define NSTAGE 3
#define SMEM_SZ (NSTAGE*STAGEB)   // 98304; also >= 128*132*4 for scram tile

__global__ __launch_bounds__(256, 2) void gemm_mma(
    const __half* __restrict__ Aa,
    const __half* __restrict__ Bw,
    const float* __restrict__ bias,
    const float* __restrict__ residf,
    const __half* __restrict__ resph,
    float* __restrict__ outf,
    __half* __restrict__ outh,
    const float* __restrict__ xin,   // scramble-mode shortcut input
    int Nd, int Kd, int do_gelu, int scram)
{
    extern __shared__ __align__(1024) char smarr[];
    const int tid = threadIdx.x;
    const int lane = tid & 31;
    const int wid = tid >> 5;
    const int bm = blockIdx.y * 128;
    const int bn = blockIdx.x * 128;
    const int wm = (wid >> 2) * 64;
    const int wn = (wid & 3) * 32;
    const uint32_t smb = smem_u32(smarr);

    const int cpc = tid & 7;
    const int cpr = tid >> 3;

    float acc[4][4][4];
#pragma unroll
    for (int i = 0; i < 4; i++)
#pragma unroll
        for (int j = 0; j < 4; j++)
#pragma unroll
            for (int r = 0; r < 4; r++) acc[i][j][r] = 0.f;

    const int nchunks = Kd >> 6;

#pragma unroll
    for (int st = 0; st < 2; st++) {
        const int k0 = st << 6;
        uint32_t sb = smb + st * STAGEB;
#pragma unroll
        for (int p = 0; p < 4; p++) {
            int r = cpr + p * 32;
            int off = r * 128 + cpc * 16;
            int sw = off ^ ((off >> 3) & 0x70);
            cp16(sb + sw,         Aa + (size_t)(bm + r) * Kd + k0 + cpc * 8);
            cp16(sb + TILEB + sw, Bw + (size_t)(bn + r) * Kd + k0 + cpc * 8);
        }
        CP_COMMIT();
    }

    const int lrow = (lane & 7) + ((lane >> 3) & 1) * 8;
    const int lhalf = lane >> 4;

    int stage = 0;
    for (int kc = 0; kc < nchunks; kc++) {
        if (kc + 1 < nchunks) { CP_WAIT(1); } else { CP_WAIT(0); }
        __syncthreads();

        if (kc + 2 < nchunks) {
            const int k0 = (kc + 2) << 6;
            int st2 = stage + 2; if (st2 >= NSTAGE) st2 -= NSTAGE;
            uint32_t sb = smb + st2 * STAGEB;
#pragma unroll
            for (int p = 0; p < 4; p++) {
                int r = cpr + p * 32;
                int off = r * 128 + cpc * 16;
                int sw = off ^ ((off >> 3) & 0x70);
                cp16(sb + sw,         Aa + (size_t)(bm + r) * Kd + k0 + cpc * 8);
                cp16(sb + TILEB + sw, Bw + (size_t)(bn + r) * Kd + k0 + cpc * 8);
            }
            CP_COMMIT();
        }

        uint32_t sb = smb + stage * STAGEB;
#pragma unroll
        for (int ks = 0; ks < 4; ks++) {
            uint32_t af[4][4];
#pragma unroll
            for (int mi = 0; mi < 4; mi++) {
                int row = wm + mi * 16 + lrow;
                int off = row * 128 + (ks * 2 + lhalf) * 16;
                int sw = off ^ ((off >> 3) & 0x70);
                LDSM4(af[mi][0], af[mi][1], af[mi][2], af[mi][3], sb + sw);
            }
            uint32_t bw[4][2];
#pragma unroll
            for (int nj2 = 0; nj2 < 2; nj2++) {
                int row = wn + nj2 * 16 + lrow;
                int off = row * 128 + (ks * 2 + lhalf) * 16;
                int sw = off ^ ((off >> 3) & 0x70);
                uint32_t r0, r1, r2, r3;
                LDSM4(r0, r1, r2, r3, sb + TILEB + sw);
                bw[nj2*2+0][0] = r0; bw[nj2*2+0][1] = r2;
                bw[nj2*2+1][0] = r1; bw[nj2*2+1][1] = r3;
            }
#pragma unroll
            for (int mi = 0; mi < 4; mi++)
#pragma unroll
                for (int nj = 0; nj < 4; nj++)
                    MMA_F16(acc[mi][nj], af[mi], bw[nj]);
        }
        if (++stage >= NSTAGE) stage = 0;
    }

    if (!scram) {
#pragma unroll
        for (int mi = 0; mi < 4; mi++)
#pragma unroll
            for (int nj = 0; nj < 4; nj++) {
                int n = bn + wn + nj * 8 + 2 * (lane & 3);
                float b0 = bias[n], b1 = bias[n + 1];
#pragma unroll
                for (int r = 0; r < 2; r++) {
                    int m = bm + wm + mi * 16 + (lane >> 2) + r * 8;
                    size_t idx = (size_t)m * Nd + n;
                    float v0 = acc[mi][nj][r*2+0] + b0;
                    float v1 = acc[mi][nj][r*2+1] + b1;
                    if (residf) {
                        float2 rr = *(const float2*)(residf + idx);
                        v0 += rr.x; v1 += rr.y;
                    }
                    if (resph) {
                        uint32_t ph = *(const uint32_t*)((const unsigned short*)resph + idx);
                        v0 += __half2float(__ushort_as_half((unsigned short)(ph & 0xffff)));
                        v1 += __half2float(__ushort_as_half((unsigned short)(ph >> 16)));
                    }
                    if (do_gelu) {
                        v0 = 0.5f * v0 * (1.f + erff(v0 * 0.70710678118654752f));
                        v1 = 0.5f * v1 * (1.f + erff(v1 * 0.70710678118654752f));
                    }
                    if (outf) *(float2*)(outf + idx) = make_float2(v0, v1);
                    if (outh) {
                        unsigned short h0 = __half_as_ushort(__float2half_rn(v0));
                        unsigned short h1 = __half_as_ushort(__float2half_rn(v1));
                        *(uint32_t*)((unsigned short*)outh + idx) =
                            (uint32_t)h0 | ((uint32_t)h1 << 16);
                    }
                }
            }
    } else {
        // ------- scramble epilogue: x1.flat[b, (bn+n)*Ll + l] = v + x.flat ------
        __syncthreads();
        float (*tile)[132] = (float(*)[132])smarr;
#pragma unroll
        for (int mi = 0; mi < 4; mi++)
#pragma unroll
            for (int nj = 0; nj < 4; nj++) {
                int nl = wn + nj * 8 + 2 * (lane & 3);
                float b0 = bias[bn + nl], b1 = bias[bn + nl + 1];
#pragma unroll
                for (int r = 0; r < 2; r++) {
                    int ml = wm + mi * 16 + (lane >> 2) + r * 8;
                    size_t idx = (size_t)(bm + ml) * Nd + bn + nl;
                    uint32_t ph = *(const uint32_t*)((const unsigned short*)resph + idx);
                    float v0 = acc[mi][nj][r*2+0] + b0
                             + __half2float(__ushort_as_half((unsigned short)(ph & 0xffff)));
                    float v1 = acc[mi][nj][r*2+1] + b1
                             + __half2float(__ushort_as_half((unsigned short)(ph >> 16)));
                    tile[nl][ml]     = v0;
                    tile[nl + 1][ml] = v1;
                }
            }
        __syncthreads();
        const int b = bm / Ll;
        const int l0 = bm % Ll;
        const int c = tid >> 1;
        const int part = tid & 1;
        size_t base = (size_t)b * Cc * Ll + (size_t)(bn + c) * Ll + l0 + part * 64;
        const float* xb = xin + base;
        float* ob = outf + base;
#pragma unroll
        for (int j = 0; j < 16; j++) {
            float4 t4 = *(const float4*)&tile[c][part * 64 + j * 4];
            float4 x4 = *(const float4*)(xb + j * 4);
            t4.x += x4.x; t4.y += x4.y; t4.z += x4.z; t4.w += x4.w;
            *(float4*)(ob + j * 4) = t4;
        }
    }
}

// -------- column max over L (k = cols 0..511 of fused kv) ----------------------
__global__ void kmax_kernel(const __half* __restrict__ kv,
                            float* __restrict__ cmax)
{
    int b  = blockIdx.x;
    int ch = blockIdx.y * 32 + threadIdx.x;
    float m = -1e30f;
    for (int l = threadIdx.y; l < Ll; l += 8)
        m = fmaxf(m, __half2float(kv[((size_t)b * Ll + l) * 1024 + ch]));
    __shared__ float sm[8][32];
    sm[threadIdx.y][threadIdx.x] = m;
    __syncthreads();
    if (threadIdx.y == 0) {
        for (int i = 1; i < 8; i++) m = fmaxf(m, sm[i][threadIdx.x]);
        cmax[b * Cc + ch] = m;
    }
}

// -------- context via HMMA: exp in-load, csum partials, trans ldmatrix ---------
// C[kc][vc] += sum_l expk[l][kc] * v[l][vc]   (per (b,h), L-split over 8 segs)
__global__ __launch_bounds__(256) void context_hmma(const __half* __restrict__ kv,
                                                    const float* __restrict__ cmax,
                                                    float* __restrict__ csum,
                                                    float* __restrict__ ctx)
{
    __shared__ __align__(1024) char sm[16384 + 256];
    const int bh = blockIdx.x;
    const int b = bh >> 3, h = bh & 7;
    const int ch0 = h * 64;
    const int seg = blockIdx.y;
    const int SEG = Ll / 8;            // 1152
    const int tid = threadIdx.x;
    const int lane = tid & 31;
    const int wid = tid >> 5;
    const uint32_t smb = smem_u32(sm);
    float* ssum = (float*)(sm + 16384);
    if (tid < 64) ssum[tid] = 0.f;

    const int ckc = tid & 7;           // this thread's 16B chunk (8 kc's)
    float mx[8];
#pragma unroll
    for (int j = 0; j < 8; j++) mx[j] = cmax[b * Cc + ch0 + ckc * 8 + j];
    float facc[8];
#pragma unroll
    for (int j = 0; j < 8; j++) facc[j] = 0.f;

    const int wm_kc = (wid >> 1) * 16;
    const int wn_vc = (wid & 1) * 32;
    float accc[4][4];
#pragma unroll
    for (int i = 0; i < 4; i++)
#pragma unroll
        for (int r = 0; r < 4; r++) accc[i][r] = 0.f;

    for (int l0 = seg * SEG; l0 < (seg + 1) * SEG; l0 += 64) {
        __syncthreads();
#pragma unroll
        for (int p = 0; p < 2; p++) {
            int idx = tid + p * 256;
            int r = idx >> 3;
            size_t goff = ((size_t)(b * Ll) + l0 + r) * 1024 + ch0 + ckc * 8;
            uint4 u = *(const uint4*)(kv + goff);
            const __half* hp = (const __half*)&u;
            __half eo[8];
#pragma unroll
            for (int j = 0; j < 8; j++) {
                float e = expf(__half2float(hp[j]) - mx[j]);
                __half hh = __float2half_rn(e);
                eo[j] = hh;
                facc[j] += __half2float(hh);
            }
            int off = r * 128 + ckc * 16;
            int sw = off ^ ((off >> 3) & 0x70);
            *(uint4*)(sm + sw) = *(const uint4*)eo;
            *(uint4*)(sm + 8192 + sw) = *(const uint4*)(kv + goff + 512);
        }
        __syncthreads();

#pragma unroll
        for (int ks = 0; ks < 4; ks++) {
            int row_l = ks * 16 + (lane & 7) + (lane >> 4) * 8;
            int hsel = (lane >> 3) & 1;
            uint32_t af[4];
            {
                int off = row_l * 128 + (wm_kc + hsel * 8) * 2;
                int sw = off ^ ((off >> 3) & 0x70);
                LDSM4T(af[0], af[1], af[2], af[3], smb + sw);
            }
            uint32_t bw[4][2];
#pragma unroll
            for (int nj2 = 0; nj2 < 2; nj2++) {
                int off = row_l * 128 + (wn_vc + nj2 * 16 + hsel * 8) * 2;
                int sw = off ^ ((off >> 3) & 0x70);
                uint32_t r0, r1, r2, r3;
                LDSM4T(r0, r1, r2, r3, smb + 8192 + sw);
                bw[nj2*2+0][0] = r0; bw[nj2*2+0][1] = r2;
                bw[nj2*2+1][0] = r1; bw[nj2*2+1][1] = r3;
            }
#pragma unroll
            for (int nj = 0; nj < 4; nj++)
                MMA_F16(accc[nj], af, bw[nj]);
        }
    }

    // csum: shared partials -> global
#pragma unroll
    for (int j = 0; j < 8; j++) atomicAdd(&ssum[ckc * 8 + j], facc[j]);
    __syncthreads();
    if (tid < 64) atomicAdd(&csum[b * Cc + ch0 + tid], ssum[tid]);

    // ctx atomics
#pragma unroll
    for (int nj = 0; nj < 4; nj++) {
        int vc = wn_vc + nj * 8 + 2 * (lane & 3);
#pragma unroll
        for (int r = 0; r < 2; r++) {
            int kc = wm_kc + (lane >> 2) + r * 8;
            atomicAdd(&ctx[(size_t)bh * 4096 + kc * 64 + vc],     accc[nj][r*2+0]);
            atomicAdd(&ctx[(size_t)bh * 4096 + kc * 64 + vc + 1], accc[nj][r*2+1]);
        }
    }
}

// -------- ctx fp32 [kc][vc] -> fp16 transposed [vc][kc], with 1/csum[kc] -------
__global__ void ctx_cvt(const float* __restrict__ ctx,
                        const float* __restrict__ csum,
                        __half* __restrict__ ctxT)
{
    int bh = blockIdx.x;
    int b = bh >> 3, h = bh & 7;
    for (int i = threadIdx.x; i < 4096; i += 256) {
        int vc = i >> 6, kc = i & 63;
        float inv = 1.f / csum[b * Cc + h * 64 + kc];
        ctxT[(size_t)bh * 4096 + i] =
            __float2half_rn(ctx[(size_t)bh * 4096 + kc * 64 + vc] * inv);
    }
}

// -------- attend: in-smem q softmax + [128x64] @ ctxT[64x64] via mma -----------
__global__ __launch_bounds__(256) void attend_gemm(const __half* __restrict__ q,
                                                   const __half* __restrict__ ctxT,
                                                   __half* __restrict__ att)
{
    __shared__ __align__(1024) char sm[16384 + 8192];
    const int tid = threadIdx.x;
    const int lane = tid & 31;
    const int wid = tid >> 5;
    const int bh = blockIdx.y;
    const int b = bh >> 3, h = bh & 7;
    const int lt = blockIdx.x * 128;
    const uint32_t smb = smem_u32(sm);

#pragma unroll
    for (int p = 0; p < 4; p++) {
        int idx = tid + p * 256;
        int r = idx >> 3, c16 = idx & 7;
        int off = r * 128 + c16 * 16;
        int sw = off ^ ((off >> 3) & 0x70);
        cp16(smb + sw, q + (size_t)(b * Ll + lt + r) * 512 + h * 64 + c16 * 8);
    }
#pragma unroll
    for (int p = 0; p < 2; p++) {
        int idx = tid + p * 256;
        int r = idx >> 3, c16 = idx & 7;
        int off = r * 128 + c16 * 16;
        int sw = off ^ ((off >> 3) & 0x70);
        cp16(smb + 16384 + sw, ctxT + (size_t)bh * 4096 + r * 64 + c16 * 8);
    }
    CP_COMMIT(); CP_WAIT(0);
    __syncthreads();

    if (tid < 128) {
        float vals[64];
#pragma unroll
        for (int c16 = 0; c16 < 8; c16++) {
            int off = tid * 128 + c16 * 16;
            int sw = off ^ ((off >> 3) & 0x70);
            uint4 u = *(const uint4*)(sm + sw);
            const __half* hp = (const __half*)&u;
#pragma unroll
            for (int t = 0; t < 8; t++) vals[c16*8 + t] = __half2float(hp[t]);
        }
        float m = vals[0];
#pragma unroll
        for (int i = 1; i < 64; i++) m = fmaxf(m, vals[i]);
        float s = 0.f;
#pragma unroll
        for (int i = 0; i < 64; i++) { vals[i] = expf(vals[i] - m); s += vals[i]; }
        float inv = 1.f / s;
#pragma unroll
        for (int c16 = 0; c16 < 8; c16++) {
            int off = tid * 128 + c16 * 16;
            int sw = off ^ ((off >> 3) & 0x70);
            __half hv[8];
#pragma unroll
            for (int t = 0; t < 8; t++) hv[t] = __float2half_rn(vals[c16*8 + t] * inv);
            *(uint4*)(sm + sw) = *(const uint4*)hv;
        }
    }
    __syncthreads();

    const int wm = (wid >> 1) * 32;
    const int wn = (wid & 1) * 32;
    const int lrow = (lane & 7) + ((lane >> 3) & 1) * 8;
    const int lhalf = lane >> 4;
    float acc[2][4][4];
#pragma unroll
    for (int i = 0; i < 2; i++)
#pragma unroll
        for (int j = 0; j < 4; j++)
#pragma unroll
            for (int r = 0; r < 4; r++) acc[i][j][r] = 0.f;

#pragma unroll
    for (int ks = 0; ks < 4; ks++) {
        uint32_t af[2][4];
#pragma unroll
        for (int mi = 0; mi < 2; mi++) {
            int row = wm + mi * 16 + lrow;
            int off = row * 128 + (ks * 2 + lhalf) * 16;
            int sw = off ^ ((off >> 3) & 0x70);
            LDSM4(af[mi][0], af[mi][1], af[mi][2], af[mi][3], smb + sw);
        }
        uint32_t bw[4][2];
#pragma unroll
        for (int nj2 = 0; nj2 < 2; nj2++) {
            int row = wn + nj2 * 16 + lrow;
            int off = row * 128 + (ks * 2 + lhalf) * 16;
            int sw = off ^ ((off >> 3) & 0x70);
            uint32_t r0, r1, r2, r3;
            LDSM4(r0, r1, r2, r3, smb + 16384 + sw);
            bw[nj2*2+0][0] = r0; bw[nj2*2+0][1] = r2;
            bw[nj2*2+1][0] = r1; bw[nj2*2+1][1] = r3;
        }
#pragma unroll
        for (int mi = 0; mi < 2; mi++)
#pragma unroll
            for (int nj = 0; nj < 4; nj++)
                MMA_F16(acc[mi][nj], af[mi], bw[nj]);
    }

#pragma unroll
    for (int mi = 0; mi < 2; mi++)
#pragma unroll
        for (int nj = 0; nj < 4; nj++) {
            int n = wn + nj * 8 + 2 * (lane & 3);
#pragma unroll
            for (int r = 0; r < 2; r++) {
                int m = wm + mi * 16 + (lane >> 2) + r * 8;
                size_t o = (size_t)(b * Ll + lt + m) * 512 + h * 64 + n;
                unsigned short h0 = __half_as_ushort(__float2half_rn(acc[mi][nj][r*2+0]));
                unsigned short h1 = __half_as_ushort(__float2half_rn(acc[mi][nj][r*2+1]));
                *(uint32_t*)((unsigned short*)att + o) = (uint32_t)h0 | ((uint32_t)h1 << 16);
            }
        }
}

// ------------------------------- driver ---------------------------------------
extern "C" void kernel_launch(void* const* d_in, const int* in_sizes, int n_in,
                              void* d_out, int out_size)
{
    const float* x     = (const float*)d_in[0];
    const float* v     = (const float*)d_in[1];
    const float* ln1w  = (const float*)d_in[4];
    const float* ln1b  = (const float*)d_in[5];
    const float* lnvw  = (const float*)d_in[6];
    const float* lnvb  = (const float*)d_in[7];
    const float* ln2w  = (const float*)d_in[8];
    const float* ln2b  = (const float*)d_in[9];
    const float* wq    = (const float*)d_in[10];
    const float* bq    = (const float*)d_in[11];
    const float* wk    = (const float*)d_in[12];
    const float* bk    = (const float*)d_in[13];
    const float* wv    = (const float*)d_in[14];
    const float* bv    = (const float*)d_in[15];
    const float* wr    = (const float*)d_in[16];
    const float* br    = (const float*)d_in[17];
    const float* fc1w  = (const float*)d_in[18];
    const float* fc1b  = (const float*)d_in[19];
    const float* fc2w  = (const float*)d_in[20];
    const float* fc2b  = (const float*)d_in[21];
    float* out = (float*)d_out;

    float *p_ctx, *p_cmax, *p_csum, *p_bkv;
    __half *p_q16, *p_kv16, *p_xn, *p_vn, *p_att, *p_h, *p_ctxT;
    __half *p_wq, *p_wkv, *p_wr, *p_f1, *p_f2;
    cudaGetSymbolAddress((void**)&p_ctx, g_ctx);
    cudaGetSymbolAddress((void**)&p_ctxT, g_ctxT);
    cudaGetSymbolAddress((void**)&p_cmax, g_cmax);
    cudaGetSymbolAddress((void**)&p_csum, g_csum);
    cudaGetSymbolAddress((void**)&p_bkv, g_bkv);
    cudaGetSymbolAddress((void**)&p_q16, g_q16);
    cudaGetSymbolAddress((void**)&p_kv16, g_kv16);
    cudaGetSymbolAddress((void**)&p_xn,  g_xn);
    cudaGetSymbolAddress((void**)&p_vn,  g_vn);
    cudaGetSymbolAddress((void**)&p_att, g_att);
    cudaGetSymbolAddress((void**)&p_h,   g_h);
    cudaGetSymbolAddress((void**)&p_wq,  g_wq16);
    cudaGetSymbolAddress((void**)&p_wkv, g_wkv16);
    cudaGetSymbolAddress((void**)&p_wr,  g_wr16);
    cudaGetSymbolAddress((void**)&p_f1,  g_f116);
    cudaGetSymbolAddress((void**)&p_f2,  g_f216);

    cudaFuncSetAttribute(gemm_mma, cudaFuncAttributeMaxDynamicSharedMemorySize, SMEM_SZ);

    dim3 g512(Cc / 128, Mm / 128);     // (4, 576)
    dim3 g1024(1024 / 128, Mm / 128);  // (8, 576)
    dim3 g2048(HID / 128, Mm / 128);   // (16, 576)

    // ordered so the q-projection gemm is the 6th launch (ncu -s 5 -c 1)
    convert_kernel<<<(Cc*Cc + 255)/256, 256>>>(wq, p_wq, Cc*Cc);              // 1
    ln_half<<<Mm / 8, 256>>>(x, ln1w, ln1b, p_xn);                            // 2
    convert_kernel<<<(Cc*Cc + 255)/256, 256>>>(wk, p_wkv, Cc*Cc);             // 3
    convert_kernel<<<(Cc*Cc + 255)/256, 256>>>(wv, p_wkv + Cc*Cc, Cc*Cc);     // 4
    concat_bias<<<4, 256>>>(bk, bv, p_bkv);                                   // 5
    gemm_mma<<<g512, 256, SMEM_SZ>>>(p_xn, p_wq, bq, nullptr, nullptr,        // 6 (profiled)
                                     nullptr, p_q16, nullptr, Cc, Cc, 0, 0);
    ln_half<<<Mm / 8, 256>>>(v, lnvw, lnvb, p_vn);
    gemm_mma<<<g1024, 256, SMEM_SZ>>>(p_vn, p_wkv, p_bkv, nullptr, nullptr,
                                      nullptr, p_kv16, nullptr, 1024, Cc, 0, 0);
    convert_kernel<<<(Cc*Cc + 255)/256, 256>>>(wr, p_wr, Cc*Cc);
    convert_kernel<<<(HID*Cc + 255)/256, 256>>>(fc1w, p_f1, HID*Cc);
    convert_kernel<<<(Cc*HID + 255)/256, 256>>>(fc2w, p_f2, Cc*HID);

    // attention core: max -> context(HMMA, exp in-load, csum) -> normalize -> attend
    kmax_kernel<<<dim3(Bb, Cc / 32), dim3(32, 8)>>>(p_kv16, p_cmax);
    cudaMemsetAsync(p_csum, 0, (size_t)Bb*Cc*sizeof(float));
    cudaMemsetAsync(p_ctx, 0, (size_t)Bb*HEADS*64*64*sizeof(float));
    context_hmma<<<dim3(Bb * HEADS, 8), 256>>>(p_kv16, p_cmax, p_csum, p_ctx);
    ctx_cvt<<<Bb * HEADS, 256>>>(p_ctx, p_csum, p_ctxT);
    attend_gemm<<<dim3(Ll / 128, Bb * HEADS), 256>>>(p_q16, p_ctxT, p_att);

    // reprojection + scramble + shortcut fused -> x1 in d_out
    gemm_mma<<<g512, 256, SMEM_SZ>>>(p_att, p_wr, br, nullptr, p_xn,
                                     out, nullptr, x, Cc, Cc, 0, 1);

    // LN2 -> fp16 (reuse xn buffer)
    ln_half<<<Mm / 8, 256>>>(out, ln2w, ln2b, p_xn);

    // MLP: fc1 (+exact GELU, fp16 out), fc2 (+residual from d_out)
    gemm_mma<<<g2048, 256, SMEM_SZ>>>(p_xn, p_f1, fc1b, nullptr, nullptr,
                                      nullptr, p_h, nullptr, HID, Cc, 1, 0);
    gemm_mma<<<g512, 256, SMEM_SZ>>>(p_h, p_f2, fc2b, out, nullptr,
                                     out, nullptr, nullptr, Cc, HID, 0, 0);
}

// round 12
// speedup vs baseline: 7.5776x; 1.0534x over previous
#include <cuda_runtime.h>
#include <cuda_fp16.h>
#include <math.h>
#include <stdint.h>

#define Bb 8
#define Ll 9216
#define Cc 512
#define Mm (Bb*Ll)          // 73728
#define HEADS 8
#define HID 2048

// ---------------- scratch (device globals; no runtime allocation) -------------
__device__ __align__(16) __half g_q16[(size_t)Mm*Cc];
__device__ __align__(16) __half g_kv16[(size_t)Mm*1024];    // k | val fused
__device__ __align__(16) __half g_xn[(size_t)Mm*Cc];
__device__ __align__(16) __half g_vn[(size_t)Mm*Cc];
__device__ __align__(16) __half g_att[(size_t)Mm*Cc];
__device__ __align__(16) __half g_h [(size_t)Mm*HID];
__device__ __align__(16) __half g_wq16[Cc*Cc];
__device__ __align__(16) __half g_wkv16[2*Cc*Cc];           // wk | wv fused
__device__ __align__(16) __half g_wr16[Cc*Cc];
__device__ __align__(16) __half g_f116[HID*Cc];
__device__ __align__(16) __half g_f216[Cc*HID];
__device__ float g_bkv[1024];
__device__ float g_acc[Bb*HEADS*64*64 + Bb*Cc];             // ctx | csum (one memset)
__device__ __align__(16) __half g_ctxT[Bb*HEADS*64*64];
__device__ unsigned g_cmaxe[Bb*Cc];                         // encoded fp32 column max

// ---------------- small helpers ----------------
__device__ __forceinline__ uint32_t smem_u32(const void* p) {
    return (uint32_t)__cvta_generic_to_shared(p);
}
__device__ __forceinline__ void cp16(uint32_t dst, const void* src) {
    asm volatile("cp.async.cg.shared.global [%0], [%1], 16;" :: "r"(dst), "l"(src));
}
#define CP_COMMIT() asm volatile("cp.async.commit_group;" ::: "memory")
#define CP_WAIT(N)  asm volatile("cp.async.wait_group %0;" :: "n"(N) : "memory")

#define LDSM4(r0, r1, r2, r3, addr) \
    asm volatile("ldmatrix.sync.aligned.m8n8.x4.shared.b16 {%0,%1,%2,%3}, [%4];" \
                 : "=r"(r0), "=r"(r1), "=r"(r2), "=r"(r3) : "r"(addr))

#define LDSM4T(r0, r1, r2, r3, addr) \
    asm volatile("ldmatrix.sync.aligned.m8n8.x4.trans.shared.b16 {%0,%1,%2,%3}, [%4];" \
                 : "=r"(r0), "=r"(r1), "=r"(r2), "=r"(r3) : "r"(addr))

#define MMA_F16(d, a, b) \
    asm volatile("mma.sync.aligned.m16n8k16.row.col.f32.f16.f16.f32 " \
                 "{%0,%1,%2,%3}, {%4,%5,%6,%7}, {%8,%9}, {%0,%1,%2,%3};" \
                 : "+f"((d)[0]), "+f"((d)[1]), "+f"((d)[2]), "+f"((d)[3]) \
                 : "r"((a)[0]), "r"((a)[1]), "r"((a)[2]), "r"((a)[3]), \
                   "r"((b)[0]), "r"((b)[1]))

// order-preserving float<->uint map for atomicMax
__device__ __forceinline__ unsigned enc_f(float f) {
    unsigned u = __float_as_uint(f);
    return (u & 0x80000000u) ? ~u : (u | 0x80000000u);
}
__device__ __forceinline__ float dec_f(unsigned u) {
    u = (u & 0x80000000u) ? (u & 0x7FFFFFFFu) : ~u;
    return __uint_as_float(u);
}

// ---------------- dual LayerNorm (x->xn, v->vn) -> fp16 ------------------------
__global__ __launch_bounds__(256) void ln_dual(const float* __restrict__ xa,
                                               const float* __restrict__ xb,
                                               const float* __restrict__ wa,
                                               const float* __restrict__ ba,
                                               const float* __restrict__ wb,
                                               const float* __restrict__ bb,
                                               __half* __restrict__ ya,
                                               __half* __restrict__ yb)
{
    const float* x = blockIdx.y ? xb : xa;
    const float* w = blockIdx.y ? wb : wa;
    const float* b = blockIdx.y ? bb : ba;
    __half* y = blockIdx.y ? yb : ya;
    int row = blockIdx.x * 8 + (threadIdx.x >> 5);
    int lane = threadIdx.x & 31;
    const float* xr = x + (size_t)row * Cc;
    float4 v[4];
    float s = 0.f, s2 = 0.f;
#pragma unroll
    for (int i = 0; i < 4; i++) {
        v[i] = *(const float4*)(xr + lane * 4 + i * 128);
        s  += v[i].x + v[i].y + v[i].z + v[i].w;
        s2 += v[i].x*v[i].x + v[i].y*v[i].y + v[i].z*v[i].z + v[i].w*v[i].w;
    }
#pragma unroll
    for (int o = 16; o; o >>= 1) {
        s  += __shfl_xor_sync(0xffffffffu, s,  o);
        s2 += __shfl_xor_sync(0xffffffffu, s2, o);
    }
    float mean = s * (1.f/512.f);
    float var  = s2 * (1.f/512.f) - mean*mean;
    float rstd = rsqrtf(var + 1e-5f);
#pragma unroll
    for (int i = 0; i < 4; i++) {
        int c = lane * 4 + i * 128;
        float4 wv = *(const float4*)(w + c);
        float4 bv = *(const float4*)(b + c);
        ushort4 sh;
        sh.x = __half_as_ushort(__float2half_rn((v[i].x - mean) * rstd * wv.x + bv.x));
        sh.y = __half_as_ushort(__float2half_rn((v[i].y - mean) * rstd * wv.y + bv.y));
        sh.z = __half_as_ushort(__float2half_rn((v[i].z - mean) * rstd * wv.z + bv.z));
        sh.w = __half_as_ushort(__float2half_rn((v[i].w - mean) * rstd * wv.w + bv.w));
        *(ushort4*)(y + (size_t)row * Cc + c) = sh;
    }
}

// ---------------- single LayerNorm (LN2) -> fp16 -------------------------------
__global__ __launch_bounds__(256) void ln_half(const float* __restrict__ x,
                                               const float* __restrict__ w,
                                               const float* __restrict__ b,
                                               __half* __restrict__ y)
{
    int row = blockIdx.x * 8 + (threadIdx.x >> 5);
    int lane = threadIdx.x & 31;
    const float* xr = x + (size_t)row * Cc;
    float4 v[4];
    float s = 0.f, s2 = 0.f;
#pragma unroll
    for (int i = 0; i < 4; i++) {
        v[i] = *(const float4*)(xr + lane * 4 + i * 128);
        s  += v[i].x + v[i].y + v[i].z + v[i].w;
        s2 += v[i].x*v[i].x + v[i].y*v[i].y + v[i].z*v[i].z + v[i].w*v[i].w;
    }
#pragma unroll
    for (int o = 16; o; o >>= 1) {
        s  += __shfl_xor_sync(0xffffffffu, s,  o);
        s2 += __shfl_xor_sync(0xffffffffu, s2, o);
    }
    float mean = s * (1.f/512.f);
    float var  = s2 * (1.f/512.f) - mean*mean;
    float rstd = rsqrtf(var + 1e-5f);
#pragma unroll
    for (int i = 0; i < 4; i++) {
        int c = lane * 4 + i * 128;
        float4 wv = *(const float4*)(w + c);
        float4 bv = *(const float4*)(b + c);
        ushort4 sh;
        sh.x = __half_as_ushort(__float2half_rn((v[i].x - mean) * rstd * wv.x + bv.x));
        sh.y = __half_as_ushort(__float2half_rn((v[i].y - mean) * rstd * wv.y + bv.y));
        sh.z = __half_as_ushort(__float2half_rn((v[i].z - mean) * rstd * wv.z + bv.z));
        sh.w = __half_as_ushort(__float2half_rn((v[i].w - mean) * rstd * wv.w + bv.w));
        *(ushort4*)(y + (size_t)row * Cc + c) = sh;
    }
}

// ---------------- all weight converts + bias concat in ONE launch --------------
#define WSZ (Cc*Cc)              // 262144
#define FSZ (HID*Cc)             // 1048576
__global__ void convert_all(const float* __restrict__ wq, const float* __restrict__ wk,
                            const float* __restrict__ wv, const float* __restrict__ wr,
                            const float* __restrict__ f1, const float* __restrict__ f2,
                            const float* __restrict__ bk, const float* __restrict__ bv,
                            __half* __restrict__ owq, __half* __restrict__ owkv,
                            __half* __restrict__ owr, __half* __restrict__ of1,
                            __half* __restrict__ of2, float* __restrict__ obkv)
{
    size_t i = (size_t)blockIdx.x * 256 + threadIdx.x;
    if (i < WSZ)                owq[i] = __float2half_rn(wq[i]);
    else if (i < 2*WSZ)         owkv[i - WSZ] = __float2half_rn(wk[i - WSZ]);
    else if (i < 3*WSZ)         owkv[i - WSZ] = __float2half_rn(wv[i - 2*WSZ]);
    else if (i < 4*WSZ)         owr[i - 3*WSZ] = __float2half_rn(wr[i - 3*WSZ]);
    else if (i < 4*WSZ + FSZ)   of1[i - 4*WSZ] = __float2half_rn(f1[i - 4*WSZ]);
    else if (i < 4*WSZ + 2*FSZ) of2[i - 4*WSZ - FSZ] = __float2half_rn(f2[i - 4*WSZ - FSZ]);
    else {
        size_t j = i - 4*WSZ - 2*FSZ;
        if (j < 512)       obkv[j] = bk[j];
        else if (j < 1024) obkv[j] = bv[j - 512];
    }
}

// ------------- fp16 mma.sync GEMM, 3-stage cp.async pipeline -------------------
#define TILEB 16384
#define STAGEB (2*TILEB)
#define NSTAGE 3
#define SMEM_SZ (NSTAGE*STAGEB)   // 98304; also >= 128*132*4 for scram tile

__global__ __launch_bounds__(256, 2) void gemm_mma(
    const __half* __restrict__ Aa,
    const __half* __restrict__ Bw,
    const float* __restrict__ bias,
    const float* __restrict__ residf,
    const __half* __restrict__ resph,
    float* __restrict__ outf,
    __half* __restrict__ outh,
    const float* __restrict__ xin,   // scramble-mode shortcut input
    unsigned* __restrict__ kmaxenc,  // fused column-max output (kv proj only)
    int Nd, int Kd, int do_gelu, int scram)
{
    extern __shared__ __align__(1024) char smarr[];
    const int tid = threadIdx.x;
    const int lane = tid & 31;
    const int wid = tid >> 5;
    const int bm = blockIdx.y * 128;
    const int bn = blockIdx.x * 128;
    const int wm = (wid >> 2) * 64;
    const int wn = (wid & 3) * 32;
    const uint32_t smb = smem_u32(smarr);

    const int cpc = tid & 7;
    const int cpr = tid >> 3;

    float acc[4][4][4];
#pragma unroll
    for (int i = 0; i < 4; i++)
#pragma unroll
        for (int j = 0; j < 4; j++)
#pragma unroll
            for (int r = 0; r < 4; r++) acc[i][j][r] = 0.f;

    const int nchunks = Kd >> 6;

#pragma unroll
    for (int st = 0; st < 2; st++) {
        const int k0 = st << 6;
        uint32_t sb = smb + st * STAGEB;
#pragma unroll
        for (int p = 0; p < 4; p++) {
            int r = cpr + p * 32;
            int off = r * 128 + cpc * 16;
            int sw = off ^ ((off >> 3) & 0x70);
            cp16(sb + sw,         Aa + (size_t)(bm + r) * Kd + k0 + cpc * 8);
            cp16(sb + TILEB + sw, Bw + (size_t)(bn + r) * Kd + k0 + cpc * 8);
        }
        CP_COMMIT();
    }

    const int lrow = (lane & 7) + ((lane >> 3) & 1) * 8;
    const int lhalf = lane >> 4;

    int stage = 0;
    for (int kc = 0; kc < nchunks; kc++) {
        if (kc + 1 < nchunks) { CP_WAIT(1); } else { CP_WAIT(0); }
        __syncthreads();

        if (kc + 2 < nchunks) {
            const int k0 = (kc + 2) << 6;
            int st2 = stage + 2; if (st2 >= NSTAGE) st2 -= NSTAGE;
            uint32_t sb = smb + st2 * STAGEB;
#pragma unroll
            for (int p = 0; p < 4; p++) {
                int r = cpr + p * 32;
                int off = r * 128 + cpc * 16;
                int sw = off ^ ((off >> 3) & 0x70);
                cp16(sb + sw,         Aa + (size_t)(bm + r) * Kd + k0 + cpc * 8);
                cp16(sb + TILEB + sw, Bw + (size_t)(bn + r) * Kd + k0 + cpc * 8);
            }
            CP_COMMIT();
        }

        uint32_t sb = smb + stage * STAGEB;
#pragma unroll
        for (int ks = 0; ks < 4; ks++) {
            uint32_t af[4][4];
#pragma unroll
            for (int mi = 0; mi < 4; mi++) {
                int row = wm + mi * 16 + lrow;
                int off = row * 128 + (ks * 2 + lhalf) * 16;
                int sw = off ^ ((off >> 3) & 0x70);
                LDSM4(af[mi][0], af[mi][1], af[mi][2], af[mi][3], sb + sw);
            }
            uint32_t bw[4][2];
#pragma unroll
            for (int nj2 = 0; nj2 < 2; nj2++) {
                int row = wn + nj2 * 16 + lrow;
                int off = row * 128 + (ks * 2 + lhalf) * 16;
                int sw = off ^ ((off >> 3) & 0x70);
                uint32_t r0, r1, r2, r3;
                LDSM4(r0, r1, r2, r3, sb + TILEB + sw);
                bw[nj2*2+0][0] = r0; bw[nj2*2+0][1] = r2;
                bw[nj2*2+1][0] = r1; bw[nj2*2+1][1] = r3;
            }
#pragma unroll
            for (int mi = 0; mi < 4; mi++)
#pragma unroll
                for (int nj = 0; nj < 4; nj++)
                    MMA_F16(acc[mi][nj], af[mi], bw[nj]);
        }
        if (++stage >= NSTAGE) stage = 0;
    }

    if (!scram) {
        float colmax[4][2];
#pragma unroll
        for (int nj = 0; nj < 4; nj++) { colmax[nj][0] = -1e30f; colmax[nj][1] = -1e30f; }
#pragma unroll
        for (int mi = 0; mi < 4; mi++)
#pragma unroll
            for (int nj = 0; nj < 4; nj++) {
                int n = bn + wn + nj * 8 + 2 * (lane & 3);
                float b0 = bias[n], b1 = bias[n + 1];
#pragma unroll
                for (int r = 0; r < 2; r++) {
                    int m = bm + wm + mi * 16 + (lane >> 2) + r * 8;
                    size_t idx = (size_t)m * Nd + n;
                    float v0 = acc[mi][nj][r*2+0] + b0;
                    float v1 = acc[mi][nj][r*2+1] + b1;
                    if (residf) {
                        float2 rr = *(const float2*)(residf + idx);
                        v0 += rr.x; v1 += rr.y;
                    }
                    if (resph) {
                        uint32_t ph = *(const uint32_t*)((const unsigned short*)resph + idx);
                        v0 += __half2float(__ushort_as_half((unsigned short)(ph & 0xffff)));
                        v1 += __half2float(__ushort_as_half((unsigned short)(ph >> 16)));
                    }
                    colmax[nj][0] = fmaxf(colmax[nj][0], v0);
                    colmax[nj][1] = fmaxf(colmax[nj][1], v1);
                    if (do_gelu) {
                        v0 = 0.5f * v0 * (1.f + erff(v0 * 0.70710678118654752f));
                        v1 = 0.5f * v1 * (1.f + erff(v1 * 0.70710678118654752f));
                    }
                    if (outf) *(float2*)(outf + idx) = make_float2(v0, v1);
                    if (outh) {
                        unsigned short h0 = __half_as_ushort(__float2half_rn(v0));
                        unsigned short h1 = __half_as_ushort(__float2half_rn(v1));
                        *(uint32_t*)((unsigned short*)outh + idx) =
                            (uint32_t)h0 | ((uint32_t)h1 << 16);
                    }
                }
            }
        // fused column-max for k channels (kv projection: only k-half blocks)
        if (kmaxenc && bn < 512) {
            int b = bm / Ll;
#pragma unroll
            for (int nj = 0; nj < 4; nj++) {
                float m0 = colmax[nj][0], m1 = colmax[nj][1];
#pragma unroll
                for (int o = 4; o < 32; o <<= 1) {
                    m0 = fmaxf(m0, __shfl_xor_sync(0xffffffffu, m0, o));
                    m1 = fmaxf(m1, __shfl_xor_sync(0xffffffffu, m1, o));
                }
                if (lane < 4) {
                    int n = bn + wn + nj * 8 + 2 * lane;
                    atomicMax(&kmaxenc[b * 512 + n],     enc_f(m0));
                    atomicMax(&kmaxenc[b * 512 + n + 1], enc_f(m1));
                }
            }
        }
    } else {
        // ------- scramble epilogue: x1.flat[b, (bn+n)*Ll + l] = v + x.flat ------
        __syncthreads();
        float (*tile)[132] = (float(*)[132])smarr;
#pragma unroll
        for (int mi = 0; mi < 4; mi++)
#pragma unroll
            for (int nj = 0; nj < 4; nj++) {
                int nl = wn + nj * 8 + 2 * (lane & 3);
                float b0 = bias[bn + nl], b1 = bias[bn + nl + 1];
#pragma unroll
                for (int r = 0; r < 2; r++) {
                    int ml = wm + mi * 16 + (lane >> 2) + r * 8;
                    size_t idx = (size_t)(bm + ml) * Nd + bn + nl;
                    uint32_t ph = *(const uint32_t*)((const unsigned short*)resph + idx);
                    float v0 = acc[mi][nj][r*2+0] + b0
                             + __half2float(__ushort_as_half((unsigned short)(ph & 0xffff)));
                    float v1 = acc[mi][nj][r*2+1] + b1
                             + __half2float(__ushort_as_half((unsigned short)(ph >> 16)));
                    tile[nl][ml]     = v0;
                    tile[nl + 1][ml] = v1;
                }
            }
        __syncthreads();
        const int b = bm / Ll;
        const int l0 = bm % Ll;
        const int c = tid >> 1;
        const int part = tid & 1;
        size_t base = (size_t)b * Cc * Ll + (size_t)(bn + c) * Ll + l0 + part * 64;
        const float* xb = xin + base;
        float* ob = outf + base;
#pragma unroll
        for (int j = 0; j < 16; j++) {
            float4 t4 = *(const float4*)&tile[c][part * 64 + j * 4];
            float4 x4 = *(const float4*)(xb + j * 4);
            t4.x += x4.x; t4.y += x4.y; t4.z += x4.z; t4.w += x4.w;
            *(float4*)(ob + j * 4) = t4;
        }
    }
}

// -------- context via HMMA: exp in-load, csum partials, trans ldmatrix ---------
__global__ __launch_bounds__(256) void context_hmma(const __half* __restrict__ kv,
                                                    const unsigned* __restrict__ cmaxe,
                                                    float* __restrict__ csum,
                                                    float* __restrict__ ctx)
{
    __shared__ __align__(1024) char sm[16384 + 256];
    const int bh = blockIdx.x;
    const int b = bh >> 3, h = bh & 7;
    const int ch0 = h * 64;
    const int seg = blockIdx.y;
    const int SEG = Ll / 8;            // 1152
    const int tid = threadIdx.x;
    const int lane = tid & 31;
    const int wid = tid >> 5;
    const uint32_t smb = smem_u32(sm);
    float* ssum = (float*)(sm + 16384);
    if (tid < 64) ssum[tid] = 0.f;

    const int ckc = tid & 7;
    float mx[8];
#pragma unroll
    for (int j = 0; j < 8; j++) mx[j] = dec_f(cmaxe[b * Cc + ch0 + ckc * 8 + j]);
    float facc[8];
#pragma unroll
    for (int j = 0; j < 8; j++) facc[j] = 0.f;

    const int wm_kc = (wid >> 1) * 16;
    const int wn_vc = (wid & 1) * 32;
    float accc[4][4];
#pragma unroll
    for (int i = 0; i < 4; i++)
#pragma unroll
        for (int r = 0; r < 4; r++) accc[i][r] = 0.f;

    for (int l0 = seg * SEG; l0 < (seg + 1) * SEG; l0 += 64) {
        __syncthreads();
#pragma unroll
        for (int p = 0; p < 2; p++) {
            int idx = tid + p * 256;
            int r = idx >> 3;
            size_t goff = ((size_t)(b * Ll) + l0 + r) * 1024 + ch0 + ckc * 8;
            uint4 u = *(const uint4*)(kv + goff);
            const __half* hp = (const __half*)&u;
            __half eo[8];
#pragma unroll
            for (int j = 0; j < 8; j++) {
                float e = expf(__half2float(hp[j]) - mx[j]);
                __half hh = __float2half_rn(e);
                eo[j] = hh;
                facc[j] += __half2float(hh);
            }
            int off = r * 128 + ckc * 16;
            int sw = off ^ ((off >> 3) & 0x70);
            *(uint4*)(sm + sw) = *(const uint4*)eo;
            *(uint4*)(sm + 8192 + sw) = *(const uint4*)(kv + goff + 512);
        }
        __syncthreads();

#pragma unroll
        for (int ks = 0; ks < 4; ks++) {
            int row_l = ks * 16 + (lane & 7) + (lane >> 4) * 8;
            int hsel = (lane >> 3) & 1;
            uint32_t af[4];
            {
                int off = row_l * 128 + (wm_kc + hsel * 8) * 2;
                int sw = off ^ ((off >> 3) & 0x70);
                LDSM4T(af[0], af[1], af[2], af[3], smb + sw);
            }
            uint32_t bw[4][2];
#pragma unroll
            for (int nj2 = 0; nj2 < 2; nj2++) {
                int off = row_l * 128 + (wn_vc + nj2 * 16 + hsel * 8) * 2;
                int sw = off ^ ((off >> 3) & 0x70);
                uint32_t r0, r1, r2, r3;
                LDSM4T(r0, r1, r2, r3, smb + 8192 + sw);
                bw[nj2*2+0][0] = r0; bw[nj2*2+0][1] = r2;
                bw[nj2*2+1][0] = r1; bw[nj2*2+1][1] = r3;
            }
#pragma unroll
            for (int nj = 0; nj < 4; nj++)
                MMA_F16(accc[nj], af, bw[nj]);
        }
    }

#pragma unroll
    for (int j = 0; j < 8; j++) atomicAdd(&ssum[ckc * 8 + j], facc[j]);
    __syncthreads();
    if (tid < 64) atomicAdd(&csum[b * Cc + ch0 + tid], ssum[tid]);

#pragma unroll
    for (int nj = 0; nj < 4; nj++) {
        int vc = wn_vc + nj * 8 + 2 * (lane & 3);
#pragma unroll
        for (int r = 0; r < 2; r++) {
            int kc = wm_kc + (lane >> 2) + r * 8;
            atomicAdd(&ctx[(size_t)bh * 4096 + kc * 64 + vc],     accc[nj][r*2+0]);
            atomicAdd(&ctx[(size_t)bh * 4096 + kc * 64 + vc + 1], accc[nj][r*2+1]);
        }
    }
}

// -------- ctx fp32 [kc][vc] -> fp16 transposed [vc][kc], with 1/csum[kc] -------
__global__ void ctx_cvt(const float* __restrict__ ctx,
                        const float* __restrict__ csum,
                        __half* __restrict__ ctxT)
{
    int bh = blockIdx.x;
    int b = bh >> 3, h = bh & 7;
    for (int i = threadIdx.x; i < 4096; i += 256) {
        int vc = i >> 6, kc = i & 63;
        float inv = 1.f / csum[b * Cc + h * 64 + kc];
        ctxT[(size_t)bh * 4096 + i] =
            __float2half_rn(ctx[(size_t)bh * 4096 + kc * 64 + vc] * inv);
    }
}

// -------- attend: in-smem q softmax + [128x64] @ ctxT[64x64] via mma -----------
__global__ __launch_bounds__(256) void attend_gemm(const __half* __restrict__ q,
                                                   const __half* __restrict__ ctxT,
                                                   __half* __restrict__ att)
{
    __shared__ __align__(1024) char sm[16384 + 8192];
    const int tid = threadIdx.x;
    const int lane = tid & 31;
    const int wid = tid >> 5;
    const int bh = blockIdx.y;
    const int b = bh >> 3, h = bh & 7;
    const int lt = blockIdx.x * 128;
    const uint32_t smb = smem_u32(sm);

#pragma unroll
    for (int p = 0; p < 4; p++) {
        int idx = tid + p * 256;
        int r = idx >> 3, c16 = idx & 7;
        int off = r * 128 + c16 * 16;
        int sw = off ^ ((off >> 3) & 0x70);
        cp16(smb + sw, q + (size_t)(b * Ll + lt + r) * 512 + h * 64 + c16 * 8);
    }
#pragma unroll
    for (int p = 0; p < 2; p++) {
        int idx = tid + p * 256;
        int r = idx >> 3, c16 = idx & 7;
        int off = r * 128 + c16 * 16;
        int sw = off ^ ((off >> 3) & 0x70);
        cp16(smb + 16384 + sw, ctxT + (size_t)bh * 4096 + r * 64 + c16 * 8);
    }
    CP_COMMIT(); CP_WAIT(0);
    __syncthreads();

    if (tid < 128) {
        float vals[64];
#pragma unroll
        for (int c16 = 0; c16 < 8; c16++) {
            int off = tid * 128 + c16 * 16;
            int sw = off ^ ((off >> 3) & 0x70);
            uint4 u = *(const uint4*)(sm + sw);
            const __half* hp = (const __half*)&u;
#pragma unroll
            for (int t = 0; t < 8; t++) vals[c16*8 + t] = __half2float(hp[t]);
        }
        float m = vals[0];
#pragma unroll
        for (int i = 1; i < 64; i++) m = fmaxf(m, vals[i]);
        float s = 0.f;
#pragma unroll
        for (int i = 0; i < 64; i++) { vals[i] = expf(vals[i] - m); s += vals[i]; }
        float inv = 1.f / s;
#pragma unroll
        for (int c16 = 0; c16 < 8; c16++) {
            int off = tid * 128 + c16 * 16;
            int sw = off ^ ((off >> 3) & 0x70);
            __half hv[8];
#pragma unroll
            for (int t = 0; t < 8; t++) hv[t] = __float2half_rn(vals[c16*8 + t] * inv);
            *(uint4*)(sm + sw) = *(const uint4*)hv;
        }
    }
    __syncthreads();

    const int wm = (wid >> 1) * 32;
    const int wn = (wid & 1) * 32;
    const int lrow = (lane & 7) + ((lane >> 3) & 1) * 8;
    const int lhalf = lane >> 4;
    float acc[2][4][4];
#pragma unroll
    for (int i = 0; i < 2; i++)
#pragma unroll
        for (int j = 0; j < 4; j++)
#pragma unroll
            for (int r = 0; r < 4; r++) acc[i][j][r] = 0.f;

#pragma unroll
    for (int ks = 0; ks < 4; ks++) {
        uint32_t af[2][4];
#pragma unroll
        for (int mi = 0; mi < 2; mi++) {
            int row = wm + mi * 16 + lrow;
            int off = row * 128 + (ks * 2 + lhalf) * 16;
            int sw = off ^ ((off >> 3) & 0x70);
            LDSM4(af[mi][0], af[mi][1], af[mi][2], af[mi][3], smb + sw);
        }
        uint32_t bw[4][2];
#pragma unroll
        for (int nj2 = 0; nj2 < 2; nj2++) {
            int row = wn + nj2 * 16 + lrow;
            int off = row * 128 + (ks * 2 + lhalf) * 16;
            int sw = off ^ ((off >> 3) & 0x70);
            uint32_t r0, r1, r2, r3;
            LDSM4(r0, r1, r2, r3, smb + 16384 + sw);
            bw[nj2*2+0][0] = r0; bw[nj2*2+0][1] = r2;
            bw[nj2*2+1][0] = r1; bw[nj2*2+1][1] = r3;
        }
#pragma unroll
        for (int mi = 0; mi < 2; mi++)
#pragma unroll
            for (int nj = 0; nj < 4; nj++)
                MMA_F16(acc[mi][nj], af[mi], bw[nj]);
    }

#pragma unroll
    for (int mi = 0; mi < 2; mi++)
#pragma unroll
        for (int nj = 0; nj < 4; nj++) {
            int n = wn + nj * 8 + 2 * (lane & 3);
#pragma unroll
            for (int r = 0; r < 2; r++) {
                int m = wm + mi * 16 + (lane >> 2) + r * 8;
                size_t o = (size_t)(b * Ll + lt + m) * 512 + h * 64 + n;
                unsigned short h0 = __half_as_ushort(__float2half_rn(acc[mi][nj][r*2+0]));
                unsigned short h1 = __half_as_ushort(__float2half_rn(acc[mi][nj][r*2+1]));
                *(uint32_t*)((unsigned short*)att + o) = (uint32_t)h0 | ((uint32_t)h1 << 16);
            }
        }
}

// ------------------------------- driver ---------------------------------------
extern "C" void kernel_launch(void* const* d_in, const int* in_sizes, int n_in,
                              void* d_out, int out_size)
{
    const float* x     = (const float*)d_in[0];
    const float* v     = (const float*)d_in[1];
    const float* ln1w  = (const float*)d_in[4];
    const float* ln1b  = (const float*)d_in[5];
    const float* lnvw  = (const float*)d_in[6];
    const float* lnvb  = (const float*)d_in[7];
    const float* ln2w  = (const float*)d_in[8];
    const float* ln2b  = (const float*)d_in[9];
    const float* wq    = (const float*)d_in[10];
    const float* bq    = (const float*)d_in[11];
    const float* wk    = (const float*)d_in[12];
    const float* bk    = (const float*)d_in[13];
    const float* wv    = (const float*)d_in[14];
    const float* bv    = (const float*)d_in[15];
    const float* wr    = (const float*)d_in[16];
    const float* br    = (const float*)d_in[17];
    const float* fc1w  = (const float*)d_in[18];
    const float* fc1b  = (const float*)d_in[19];
    const float* fc2w  = (const float*)d_in[20];
    const float* fc2b  = (const float*)d_in[21];
    float* out = (float*)d_out;

    float *p_acc, *p_bkv;
    unsigned* p_cmaxe;
    __half *p_q16, *p_kv16, *p_xn, *p_vn, *p_att, *p_h, *p_ctxT;
    __half *p_wq, *p_wkv, *p_wr, *p_f1, *p_f2;
    cudaGetSymbolAddress((void**)&p_acc, g_acc);
    cudaGetSymbolAddress((void**)&p_ctxT, g_ctxT);
    cudaGetSymbolAddress((void**)&p_cmaxe, g_cmaxe);
    cudaGetSymbolAddress((void**)&p_bkv, g_bkv);
    cudaGetSymbolAddress((void**)&p_q16, g_q16);
    cudaGetSymbolAddress((void**)&p_kv16, g_kv16);
    cudaGetSymbolAddress((void**)&p_xn,  g_xn);
    cudaGetSymbolAddress((void**)&p_vn,  g_vn);
    cudaGetSymbolAddress((void**)&p_att, g_att);
    cudaGetSymbolAddress((void**)&p_h,   g_h);
    cudaGetSymbolAddress((void**)&p_wq,  g_wq16);
    cudaGetSymbolAddress((void**)&p_wkv, g_wkv16);
    cudaGetSymbolAddress((void**)&p_wr,  g_wr16);
    cudaGetSymbolAddress((void**)&p_f1,  g_f116);
    cudaGetSymbolAddress((void**)&p_f2,  g_f216);
    float* p_ctx  = p_acc;
    float* p_csum = p_acc + Bb*HEADS*64*64;

    cudaFuncSetAttribute(gemm_mma, cudaFuncAttributeMaxDynamicSharedMemorySize, SMEM_SZ);

    dim3 g512(Cc / 128, Mm / 128);     // (4, 576)
    dim3 g1024(1024 / 128, Mm / 128);  // (8, 576)
    dim3 g2048(HID / 128, Mm / 128);   // (16, 576)

    // prologue: one convert launch + one dual-LN launch + zeroing
    convert_all<<<(4*WSZ + 2*FSZ + 1024 + 255)/256, 256>>>(
        wq, wk, wv, wr, fc1w, fc2w, bk, bv,
        p_wq, p_wkv, p_wr, p_f1, p_f2, p_bkv);
    ln_dual<<<dim3(Mm / 8, 2), 256>>>(x, v, ln1w, ln1b, lnvw, lnvb, p_xn, p_vn);
    cudaMemsetAsync(p_cmaxe, 0, (size_t)Bb*Cc*sizeof(unsigned));
    cudaMemsetAsync(p_acc, 0, (size_t)(Bb*HEADS*64*64 + Bb*Cc)*sizeof(float));

    // projections: q (fp16 out), fused k|v (fp16 out + fused column max)
    gemm_mma<<<g512, 256, SMEM_SZ>>>(p_xn, p_wq, bq, nullptr, nullptr,
                                     nullptr, p_q16, nullptr, nullptr, Cc, Cc, 0, 0);
    gemm_mma<<<g1024, 256, SMEM_SZ>>>(p_vn, p_wkv, p_bkv, nullptr, nullptr,
                                      nullptr, p_kv16, nullptr, p_cmaxe, 1024, Cc, 0, 0);

    // attention core: context(HMMA, exp in-load, csum) -> normalize -> attend
    context_hmma<<<dim3(Bb * HEADS, 8), 256>>>(p_kv16, p_cmaxe, p_csum, p_ctx);
    ctx_cvt<<<Bb * HEADS, 256>>>(p_ctx, p_csum, p_ctxT);
    attend_gemm<<<dim3(Ll / 128, Bb * HEADS), 256>>>(p_q16, p_ctxT, p_att);

    // reprojection + scramble + shortcut fused -> x1 in d_out
    gemm_mma<<<g512, 256, SMEM_SZ>>>(p_att, p_wr, br, nullptr, p_xn,
                                     out, nullptr, x, nullptr, Cc, Cc, 0, 1);

    // LN2 -> fp16 (reuse xn buffer)
    ln_half<<<Mm / 8, 256>>>(out, ln2w, ln2b, p_xn);

    // MLP: fc1 (+exact GELU, fp16 out), fc2 (+residual from d_out)
    gemm_mma<<<g2048, 256, SMEM_SZ>>>(p_xn, p_f1, fc1b, nullptr, nullptr,
                                      nullptr, p_h, nullptr, nullptr, HID, Cc, 1, 0);
    gemm_mma<<<g512, 256, SMEM_SZ>>>(p_h, p_f2, fc2b, out, nullptr,
                                     out, nullptr, nullptr, nullptr, Cc, HID, 0, 0);
}

// round 13
// speedup vs baseline: 7.7673x; 1.0250x over previous
#include <cuda_runtime.h>
#include <cuda_fp16.h>
#include <math.h>
#include <stdint.h>

#define Bb 8
#define Ll 9216
#define Cc 512
#define Mm (Bb*Ll)          // 73728
#define HEADS 8
#define HID 2048

// ---------------- scratch (device globals; no runtime allocation) -------------
__device__ __align__(16) __half g_q16[(size_t)Mm*Cc];
__device__ __align__(16) __half g_kv16[(size_t)Mm*1024];    // k | val fused
__device__ __align__(16) __half g_xn[(size_t)Mm*Cc];
__device__ __align__(16) __half g_vn[(size_t)Mm*Cc];
__device__ __align__(16) __half g_att[(size_t)Mm*Cc];
__device__ __align__(16) __half g_h [(size_t)Mm*HID];
__device__ __align__(16) __half g_wq16[Cc*Cc];
__device__ __align__(16) __half g_wkv16[2*Cc*Cc];           // wk | wv fused
__device__ __align__(16) __half g_wr16[Cc*Cc];
__device__ __align__(16) __half g_f116[HID*Cc];
__device__ __align__(16) __half g_f216[Cc*HID];
__device__ float g_bkv[1024];
__device__ float g_acc[Bb*HEADS*64*64 + Bb*Cc];             // ctx | csum (one memset)
__device__ __align__(16) __half g_ctxT[Bb*HEADS*64*64];
__device__ unsigned g_cmaxe[Bb*Cc];                         // encoded fp32 column max

// ---------------- small helpers ----------------
__device__ __forceinline__ uint32_t smem_u32(const void* p) {
    return (uint32_t)__cvta_generic_to_shared(p);
}
__device__ __forceinline__ void cp16(uint32_t dst, const void* src) {
    asm volatile("cp.async.cg.shared.global [%0], [%1], 16;" :: "r"(dst), "l"(src));
}
#define CP_COMMIT() asm volatile("cp.async.commit_group;" ::: "memory")
#define CP_WAIT(N)  asm volatile("cp.async.wait_group %0;" :: "n"(N) : "memory")

#define LDSM4(r0, r1, r2, r3, addr) \
    asm volatile("ldmatrix.sync.aligned.m8n8.x4.shared.b16 {%0,%1,%2,%3}, [%4];" \
                 : "=r"(r0), "=r"(r1), "=r"(r2), "=r"(r3) : "r"(addr))

#define LDSM4T(r0, r1, r2, r3, addr) \
    asm volatile("ldmatrix.sync.aligned.m8n8.x4.trans.shared.b16 {%0,%1,%2,%3}, [%4];" \
                 : "=r"(r0), "=r"(r1), "=r"(r2), "=r"(r3) : "r"(addr))

#define MMA_F16(d, a, b) \
    asm volatile("mma.sync.aligned.m16n8k16.row.col.f32.f16.f16.f32 " \
                 "{%0,%1,%2,%3}, {%4,%5,%6,%7}, {%8,%9}, {%0,%1,%2,%3};" \
                 : "+f"((d)[0]), "+f"((d)[1]), "+f"((d)[2]), "+f"((d)[3]) \
                 : "r"((a)[0]), "r"((a)[1]), "r"((a)[2]), "r"((a)[3]), \
                   "r"((b)[0]), "r"((b)[1]))

// order-preserving float<->uint map for atomicMax
__device__ __forceinline__ unsigned enc_f(float f) {
    unsigned u = __float_as_uint(f);
    return (u & 0x80000000u) ? ~u : (u | 0x80000000u);
}
__device__ __forceinline__ float dec_f(unsigned u) {
    u = (u & 0x80000000u) ? (u & 0x7FFFFFFFu) : ~u;
    return __uint_as_float(u);
}

// ---------------- dual LayerNorm (x->xn, v->vn) -> fp16 ------------------------
__global__ __launch_bounds__(256) void ln_dual(const float* __restrict__ xa,
                                               const float* __restrict__ xb,
                                               const float* __restrict__ wa,
                                               const float* __restrict__ ba,
                                               const float* __restrict__ wb,
                                               const float* __restrict__ bb,
                                               __half* __restrict__ ya,
                                               __half* __restrict__ yb)
{
    const float* x = blockIdx.y ? xb : xa;
    const float* w = blockIdx.y ? wb : wa;
    const float* b = blockIdx.y ? bb : ba;
    __half* y = blockIdx.y ? yb : ya;
    int row = blockIdx.x * 8 + (threadIdx.x >> 5);
    int lane = threadIdx.x & 31;
    const float* xr = x + (size_t)row * Cc;
    float4 v[4];
    float s = 0.f, s2 = 0.f;
#pragma unroll
    for (int i = 0; i < 4; i++) {
        v[i] = *(const float4*)(xr + lane * 4 + i * 128);
        s  += v[i].x + v[i].y + v[i].z + v[i].w;
        s2 += v[i].x*v[i].x + v[i].y*v[i].y + v[i].z*v[i].z + v[i].w*v[i].w;
    }
#pragma unroll
    for (int o = 16; o; o >>= 1) {
        s  += __shfl_xor_sync(0xffffffffu, s,  o);
        s2 += __shfl_xor_sync(0xffffffffu, s2, o);
    }
    float mean = s * (1.f/512.f);
    float var  = s2 * (1.f/512.f) - mean*mean;
    float rstd = rsqrtf(var + 1e-5f);
#pragma unroll
    for (int i = 0; i < 4; i++) {
        int c = lane * 4 + i * 128;
        float4 wv = *(const float4*)(w + c);
        float4 bv = *(const float4*)(b + c);
        ushort4 sh;
        sh.x = __half_as_ushort(__float2half_rn((v[i].x - mean) * rstd * wv.x + bv.x));
        sh.y = __half_as_ushort(__float2half_rn((v[i].y - mean) * rstd * wv.y + bv.y));
        sh.z = __half_as_ushort(__float2half_rn((v[i].z - mean) * rstd * wv.z + bv.z));
        sh.w = __half_as_ushort(__float2half_rn((v[i].w - mean) * rstd * wv.w + bv.w));
        *(ushort4*)(y + (size_t)row * Cc + c) = sh;
    }
}

// ---------------- single LayerNorm (LN2) -> fp16 -------------------------------
__global__ __launch_bounds__(256) void ln_half(const float* __restrict__ x,
                                               const float* __restrict__ w,
                                               const float* __restrict__ b,
                                               __half* __restrict__ y)
{
    int row = blockIdx.x * 8 + (threadIdx.x >> 5);
    int lane = threadIdx.x & 31;
    const float* xr = x + (size_t)row * Cc;
    float4 v[4];
    float s = 0.f, s2 = 0.f;
#pragma unroll
    for (int i = 0; i < 4; i++) {
        v[i] = *(const float4*)(xr + lane * 4 + i * 128);
        s  += v[i].x + v[i].y + v[i].z + v[i].w;
        s2 += v[i].x*v[i].x + v[i].y*v[i].y + v[i].z*v[i].z + v[i].w*v[i].w;
    }
#pragma unroll
    for (int o = 16; o; o >>= 1) {
        s  += __shfl_xor_sync(0xffffffffu, s,  o);
        s2 += __shfl_xor_sync(0xffffffffu, s2, o);
    }
    float mean = s * (1.f/512.f);
    float var  = s2 * (1.f/512.f) - mean*mean;
    float rstd = rsqrtf(var + 1e-5f);
#pragma unroll
    for (int i = 0; i < 4; i++) {
        int c = lane * 4 + i * 128;
        float4 wv = *(const float4*)(w + c);
        float4 bv = *(const float4*)(b + c);
        ushort4 sh;
        sh.x = __half_as_ushort(__float2half_rn((v[i].x - mean) * rstd * wv.x + bv.x));
        sh.y = __half_as_ushort(__float2half_rn((v[i].y - mean) * rstd * wv.y + bv.y));
        sh.z = __half_as_ushort(__float2half_rn((v[i].z - mean) * rstd * wv.z + bv.z));
        sh.w = __half_as_ushort(__float2half_rn((v[i].w - mean) * rstd * wv.w + bv.w));
        *(ushort4*)(y + (size_t)row * Cc + c) = sh;
    }
}

// ---------------- all weight converts + bias concat in ONE launch --------------
#define WSZ (Cc*Cc)              // 262144
#define FSZ (HID*Cc)             // 1048576
__global__ void convert_all(const float* __restrict__ wq, const float* __restrict__ wk,
                            const float* __restrict__ wv, const float* __restrict__ wr,
                            const float* __restrict__ f1, const float* __restrict__ f2,
                            const float* __restrict__ bk, const float* __restrict__ bv,
                            __half* __restrict__ owq, __half* __restrict__ owkv,
                            __half* __restrict__ owr, __half* __restrict__ of1,
                            __half* __restrict__ of2, float* __restrict__ obkv)
{
    size_t i = (size_t)blockIdx.x * 256 + threadIdx.x;
    if (i < WSZ)                owq[i] = __float2half_rn(wq[i]);
    else if (i < 2*WSZ)         owkv[i - WSZ] = __float2half_rn(wk[i - WSZ]);
    else if (i < 3*WSZ)         owkv[i - WSZ] = __float2half_rn(wv[i - 2*WSZ]);
    else if (i < 4*WSZ)         owr[i - 3*WSZ] = __float2half_rn(wr[i - 3*WSZ]);
    else if (i < 4*WSZ + FSZ)   of1[i - 4*WSZ] = __float2half_rn(f1[i - 4*WSZ]);
    else if (i < 4*WSZ + 2*FSZ) of2[i - 4*WSZ - FSZ] = __float2half_rn(f2[i - 4*WSZ - FSZ]);
    else {
        size_t j = i - 4*WSZ - 2*FSZ;
        if (j < 512)       obkv[j] = bk[j];
        else if (j < 1024) obkv[j] = bv[j - 512];
    }
}

// ------------- fp16 mma.sync GEMM, 3-stage cp.async, hoisted addressing --------
#define TILEB 16384
#define STAGEB (2*TILEB)
#define NSTAGE 3
#define SMEM_SZ (NSTAGE*STAGEB)   // 98304; also >= 128*132*4 for scram tile

__global__ __launch_bounds__(256, 2) void gemm_mma(
    const __half* __restrict__ Aa,
    const __half* __restrict__ Bw,
    const float* __restrict__ bias,
    const float* __restrict__ residf,
    const __half* __restrict__ resph,
    float* __restrict__ outf,
    __half* __restrict__ outh,
    const float* __restrict__ xin,   // scramble-mode shortcut input
    unsigned* __restrict__ kmaxenc,  // fused column-max output (kv proj only)
    int Nd, int Kd, int do_gelu, int scram)
{
    extern __shared__ __align__(1024) char smarr[];
    const int tid = threadIdx.x;
    const int lane = tid & 31;
    const int wid = tid >> 5;
    const int bm = blockIdx.y * 128;
    const int bn = blockIdx.x * 128;
    const int wm = (wid >> 2) * 64;
    const int wn = (wid & 3) * 32;
    const uint32_t smb = smem_u32(smarr);

    const int cpc = tid & 7;
    const int cpr = tid >> 3;

    float acc[4][4][4];
#pragma unroll
    for (int i = 0; i < 4; i++)
#pragma unroll
        for (int j = 0; j < 4; j++)
#pragma unroll
            for (int r = 0; r < 4; r++) acc[i][j][r] = 0.f;

    const int nchunks = Kd >> 6;

    // hoisted addressing (mask identity: row&7 == lane&7 for all frag rows)
    const int lrow  = (lane & 7) + ((lane >> 3) & 1) * 8;
    const int lhalf = lane >> 4;
    const uint32_t amask = (uint32_t)(lane & 7) << 4;
    uint32_t xterm[4];
#pragma unroll
    for (int ks = 0; ks < 4; ks++)
        xterm[ks] = (uint32_t)((ks * 2 + lhalf) * 16) ^ amask;
    const uint32_t aoff = (uint32_t)(wm + lrow) * 128;           // A row base in tile
    const uint32_t boff = TILEB + (uint32_t)(wn + lrow) * 128;   // B row base in tile
    const uint32_t cpbase = (uint32_t)cpr * 128
                          + ((uint32_t)(cpc * 16) ^ ((uint32_t)(cpr & 7) << 4));
    const __half* gA = Aa + (size_t)(bm + cpr) * Kd + cpc * 8;
    const __half* gB = Bw + (size_t)(bn + cpr) * Kd + cpc * 8;
    const int pstride = 32 * Kd;     // elements per 32-row step

    // ---- prologue: stages 0,1
#pragma unroll
    for (int st = 0; st < 2; st++) {
        uint32_t sb = smb + st * STAGEB + cpbase;
#pragma unroll
        for (int p = 0; p < 4; p++) {
            cp16(sb + p * 4096,         gA + (size_t)p * pstride);
            cp16(sb + TILEB + p * 4096, gB + (size_t)p * pstride);
        }
        CP_COMMIT();
        gA += 64; gB += 64;
    }

    int stage = 0;
    for (int kc = 0; kc < nchunks; kc++) {
        if (kc + 1 < nchunks) { CP_WAIT(1); } else { CP_WAIT(0); }
        __syncthreads();

        if (kc + 2 < nchunks) {
            int st2 = stage + 2; if (st2 >= NSTAGE) st2 -= NSTAGE;
            uint32_t sb = smb + st2 * STAGEB + cpbase;
#pragma unroll
            for (int p = 0; p < 4; p++) {
                cp16(sb + p * 4096,         gA + (size_t)p * pstride);
                cp16(sb + TILEB + p * 4096, gB + (size_t)p * pstride);
            }
            CP_COMMIT();
            gA += 64; gB += 64;
        }

        const uint32_t sb = smb + stage * STAGEB;
        const uint32_t sbA = sb + aoff;
        const uint32_t sbB = sb + boff;
#pragma unroll
        for (int ks = 0; ks < 4; ks++) {
            const uint32_t xt = xterm[ks];
            uint32_t af[4][4];
#pragma unroll
            for (int mi = 0; mi < 4; mi++)
                LDSM4(af[mi][0], af[mi][1], af[mi][2], af[mi][3],
                      sbA + mi * 2048 + xt);
            uint32_t bw[4][2];
#pragma unroll
            for (int nj2 = 0; nj2 < 2; nj2++) {
                uint32_t r0, r1, r2, r3;
                LDSM4(r0, r1, r2, r3, sbB + nj2 * 2048 + xt);
                bw[nj2*2+0][0] = r0; bw[nj2*2+0][1] = r2;
                bw[nj2*2+1][0] = r1; bw[nj2*2+1][1] = r3;
            }
#pragma unroll
            for (int mi = 0; mi < 4; mi++)
#pragma unroll
                for (int nj = 0; nj < 4; nj++)
                    MMA_F16(acc[mi][nj], af[mi], bw[nj]);
        }
        if (++stage >= NSTAGE) stage = 0;
    }

    if (!scram) {
        float colmax[4][2];
#pragma unroll
        for (int nj = 0; nj < 4; nj++) { colmax[nj][0] = -1e30f; colmax[nj][1] = -1e30f; }
#pragma unroll
        for (int mi = 0; mi < 4; mi++)
#pragma unroll
            for (int nj = 0; nj < 4; nj++) {
                int n = bn + wn + nj * 8 + 2 * (lane & 3);
                float b0 = bias[n], b1 = bias[n + 1];
#pragma unroll
                for (int r = 0; r < 2; r++) {
                    int m = bm + wm + mi * 16 + (lane >> 2) + r * 8;
                    size_t idx = (size_t)m * Nd + n;
                    float v0 = acc[mi][nj][r*2+0] + b0;
                    float v1 = acc[mi][nj][r*2+1] + b1;
                    if (residf) {
                        float2 rr = *(const float2*)(residf + idx);
                        v0 += rr.x; v1 += rr.y;
                    }
                    if (resph) {
                        uint32_t ph = *(const uint32_t*)((const unsigned short*)resph + idx);
                        v0 += __half2float(__ushort_as_half((unsigned short)(ph & 0xffff)));
                        v1 += __half2float(__ushort_as_half((unsigned short)(ph >> 16)));
                    }
                    colmax[nj][0] = fmaxf(colmax[nj][0], v0);
                    colmax[nj][1] = fmaxf(colmax[nj][1], v1);
                    if (do_gelu) {
                        v0 = 0.5f * v0 * (1.f + erff(v0 * 0.70710678118654752f));
                        v1 = 0.5f * v1 * (1.f + erff(v1 * 0.70710678118654752f));
                    }
                    if (outf) *(float2*)(outf + idx) = make_float2(v0, v1);
                    if (outh) {
                        unsigned short h0 = __half_as_ushort(__float2half_rn(v0));
                        unsigned short h1 = __half_as_ushort(__float2half_rn(v1));
                        *(uint32_t*)((unsigned short*)outh + idx) =
                            (uint32_t)h0 | ((uint32_t)h1 << 16);
                    }
                }
            }
        // fused column-max for k channels (kv projection: only k-half blocks)
        if (kmaxenc && bn < 512) {
            int b = bm / Ll;
#pragma unroll
            for (int nj = 0; nj < 4; nj++) {
                float m0 = colmax[nj][0], m1 = colmax[nj][1];
#pragma unroll
                for (int o = 4; o < 32; o <<= 1) {
                    m0 = fmaxf(m0, __shfl_xor_sync(0xffffffffu, m0, o));
                    m1 = fmaxf(m1, __shfl_xor_sync(0xffffffffu, m1, o));
                }
                if (lane < 4) {
                    int n = bn + wn + nj * 8 + 2 * lane;
                    atomicMax(&kmaxenc[b * 512 + n],     enc_f(m0));
                    atomicMax(&kmaxenc[b * 512 + n + 1], enc_f(m1));
                }
            }
        }
    } else {
        // ------- scramble epilogue: x1.flat[b, (bn+n)*Ll + l] = v + x.flat ------
        __syncthreads();
        float (*tile)[132] = (float(*)[132])smarr;
#pragma unroll
        for (int mi = 0; mi < 4; mi++)
#pragma unroll
            for (int nj = 0; nj < 4; nj++) {
                int nl = wn + nj * 8 + 2 * (lane & 3);
                float b0 = bias[bn + nl], b1 = bias[bn + nl + 1];
#pragma unroll
                for (int r = 0; r < 2; r++) {
                    int ml = wm + mi * 16 + (lane >> 2) + r * 8;
                    size_t idx = (size_t)(bm + ml) * Nd + bn + nl;
                    uint32_t ph = *(const uint32_t*)((const unsigned short*)resph + idx);
                    float v0 = acc[mi][nj][r*2+0] + b0
                             + __half2float(__ushort_as_half((unsigned short)(ph & 0xffff)));
                    float v1 = acc[mi][nj][r*2+1] + b1
                             + __half2float(__ushort_as_half((unsigned short)(ph >> 16)));
                    tile[nl][ml]     = v0;
                    tile[nl + 1][ml] = v1;
                }
            }
        __syncthreads();
        const int b = bm / Ll;
        const int l0 = bm % Ll;
        const int c = tid >> 1;
        const int part = tid & 1;
        size_t base = (size_t)b * Cc * Ll + (size_t)(bn + c) * Ll + l0 + part * 64;
        const float* xb = xin + base;
        float* ob = outf + base;
#pragma unroll
        for (int j = 0; j < 16; j++) {
            float4 t4 = *(const float4*)&tile[c][part * 64 + j * 4];
            float4 x4 = *(const float4*)(xb + j * 4);
            t4.x += x4.x; t4.y += x4.y; t4.z += x4.z; t4.w += x4.w;
            *(float4*)(ob + j * 4) = t4;
        }
    }
}

// -------- context via HMMA: exp in-load, csum partials, trans ldmatrix ---------
__global__ __launch_bounds__(256) void context_hmma(const __half* __restrict__ kv,
                                                    const unsigned* __restrict__ cmaxe,
                                                    float* __restrict__ csum,
                                                    float* __restrict__ ctx)
{
    __shared__ __align__(1024) char sm[16384 + 256];
    const int bh = blockIdx.x;
    const int b = bh >> 3, h = bh & 7;
    const int ch0 = h * 64;
    const int seg = blockIdx.y;
    const int SEG = Ll / 8;            // 1152
    const int tid = threadIdx.x;
    const int lane = tid & 31;
    const int wid = tid >> 5;
    const uint32_t smb = smem_u32(sm);
    float* ssum = (float*)(sm + 16384);
    if (tid < 64) ssum[tid] = 0.f;

    const int ckc = tid & 7;
    float mx[8];
#pragma unroll
    for (int j = 0; j < 8; j++) mx[j] = dec_f(cmaxe[b * Cc + ch0 + ckc * 8 + j]);
    float facc[8];
#pragma unroll
    for (int j = 0; j < 8; j++) facc[j] = 0.f;

    const int wm_kc = (wid >> 1) * 16;
    const int wn_vc = (wid & 1) * 32;
    float accc[4][4];
#pragma unroll
    for (int i = 0; i < 4; i++)
#pragma unroll
        for (int r = 0; r < 4; r++) accc[i][r] = 0.f;

    for (int l0 = seg * SEG; l0 < (seg + 1) * SEG; l0 += 64) {
        __syncthreads();
#pragma unroll
        for (int p = 0; p < 2; p++) {
            int idx = tid + p * 256;
            int r = idx >> 3;
            size_t goff = ((size_t)(b * Ll) + l0 + r) * 1024 + ch0 + ckc * 8;
            uint4 u = *(const uint4*)(kv + goff);
            const __half* hp = (const __half*)&u;
            __half eo[8];
#pragma unroll
            for (int j = 0; j < 8; j++) {
                float e = expf(__half2float(hp[j]) - mx[j]);
                __half hh = __float2half_rn(e);
                eo[j] = hh;
                facc[j] += __half2float(hh);
            }
            int off = r * 128 + ckc * 16;
            int sw = off ^ ((off >> 3) & 0x70);
            *(uint4*)(sm + sw) = *(const uint4*)eo;
            *(uint4*)(sm + 8192 + sw) = *(const uint4*)(kv + goff + 512);
        }
        __syncthreads();

#pragma unroll
        for (int ks = 0; ks < 4; ks++) {
            int row_l = ks * 16 + (lane & 7) + (lane >> 4) * 8;
            int hsel = (lane >> 3) & 1;
            uint32_t af[4];
            {
                int off = row_l * 128 + (wm_kc + hsel * 8) * 2;
                int sw = off ^ ((off >> 3) & 0x70);
                LDSM4T(af[0], af[1], af[2], af[3], smb + sw);
            }
            uint32_t bw[4][2];
#pragma unroll
            for (int nj2 = 0; nj2 < 2; nj2++) {
                int off = row_l * 128 + (wn_vc + nj2 * 16 + hsel * 8) * 2;
                int sw = off ^ ((off >> 3) & 0x70);
                uint32_t r0, r1, r2, r3;
                LDSM4T(r0, r1, r2, r3, smb + 8192 + sw);
                bw[nj2*2+0][0] = r0; bw[nj2*2+0][1] = r2;
                bw[nj2*2+1][0] = r1; bw[nj2*2+1][1] = r3;
            }
#pragma unroll
            for (int nj = 0; nj < 4; nj++)
                MMA_F16(accc[nj], af, bw[nj]);
        }
    }

#pragma unroll
    for (int j = 0; j < 8; j++) atomicAdd(&ssum[ckc * 8 + j], facc[j]);
    __syncthreads();
    if (tid < 64) atomicAdd(&csum[b * Cc + ch0 + tid], ssum[tid]);

#pragma unroll
    for (int nj = 0; nj < 4; nj++) {
        int vc = wn_vc + nj * 8 + 2 * (lane & 3);
#pragma unroll
        for (int r = 0; r < 2; r++) {
            int kc = wm_kc + (lane >> 2) + r * 8;
            atomicAdd(&ctx[(size_t)bh * 4096 + kc * 64 + vc],     accc[nj][r*2+0]);
            atomicAdd(&ctx[(size_t)bh * 4096 + kc * 64 + vc + 1], accc[nj][r*2+1]);
        }
    }
}

// -------- ctx fp32 [kc][vc] -> fp16 transposed [vc][kc], with 1/csum[kc] -------
__global__ void ctx_cvt(const float* __restrict__ ctx,
                        const float* __restrict__ csum,
                        __half* __restrict__ ctxT)
{
    int bh = blockIdx.x;
    int b = bh >> 3, h = bh & 7;
    for (int i = threadIdx.x; i < 4096; i += 256) {
        int vc = i >> 6, kc = i & 63;
        float inv = 1.f / csum[b * Cc + h * 64 + kc];
        ctxT[(size_t)bh * 4096 + i] =
            __float2half_rn(ctx[(size_t)bh * 4096 + kc * 64 + vc] * inv);
    }
}

// -------- attend: in-smem q softmax + [128x64] @ ctxT[64x64] via mma -----------
__global__ __launch_bounds__(256) void attend_gemm(const __half* __restrict__ q,
                                                   const __half* __restrict__ ctxT,
                                                   __half* __restrict__ att)
{
    __shared__ __align__(1024) char sm[16384 + 8192];
    const int tid = threadIdx.x;
    const int lane = tid & 31;
    const int wid = tid >> 5;
    const int bh = blockIdx.y;
    const int b = bh >> 3, h = bh & 7;
    const int lt = blockIdx.x * 128;
    const uint32_t smb = smem_u32(sm);

#pragma unroll
    for (int p = 0; p < 4; p++) {
        int idx = tid + p * 256;
        int r = idx >> 3, c16 = idx & 7;
        int off = r * 128 + c16 * 16;
        int sw = off ^ ((off >> 3) & 0x70);
        cp16(smb + sw, q + (size_t)(b * Ll + lt + r) * 512 + h * 64 + c16 * 8);
    }
#pragma unroll
    for (int p = 0; p < 2; p++) {
        int idx = tid + p * 256;
        int r = idx >> 3, c16 = idx & 7;
        int off = r * 128 + c16 * 16;
        int sw = off ^ ((off >> 3) & 0x70);
        cp16(smb + 16384 + sw, ctxT + (size_t)bh * 4096 + r * 64 + c16 * 8);
    }
    CP_COMMIT(); CP_WAIT(0);
    __syncthreads();

    if (tid < 128) {
        float vals[64];
#pragma unroll
        for (int c16 = 0; c16 < 8; c16++) {
            int off = tid * 128 + c16 * 16;
            int sw = off ^ ((off >> 3) & 0x70);
            uint4 u = *(const uint4*)(sm + sw);
            const __half* hp = (const __half*)&u;
#pragma unroll
            for (int t = 0; t < 8; t++) vals[c16*8 + t] = __half2float(hp[t]);
        }
        float m = vals[0];
#pragma unroll
        for (int i = 1; i < 64; i++) m = fmaxf(m, vals[i]);
        float s = 0.f;
#pragma unroll
        for (int i = 0; i < 64; i++) { vals[i] = expf(vals[i] - m); s += vals[i]; }
        float inv = 1.f / s;
#pragma unroll
        for (int c16 = 0; c16 < 8; c16++) {
            int off = tid * 128 + c16 * 16;
            int sw = off ^ ((off >> 3) & 0x70);
            __half hv[8];
#pragma unroll
            for (int t = 0; t < 8; t++) hv[t] = __float2half_rn(vals[c16*8 + t] * inv);
            *(uint4*)(sm + sw) = *(const uint4*)hv;
        }
    }
    __syncthreads();

    const int wm = (wid >> 1) * 32;
    const int wn = (wid & 1) * 32;
    const int lrow = (lane & 7) + ((lane >> 3) & 1) * 8;
    const int lhalf = lane >> 4;
    float acc[2][4][4];
#pragma unroll
    for (int i = 0; i < 2; i++)
#pragma unroll
        for (int j = 0; j < 4; j++)
#pragma unroll
            for (int r = 0; r < 4; r++) acc[i][j][r] = 0.f;

#pragma unroll
    for (int ks = 0; ks < 4; ks++) {
        uint32_t af[2][4];
#pragma unroll
        for (int mi = 0; mi < 2; mi++) {
            int row = wm + mi * 16 + lrow;
            int off = row * 128 + (ks * 2 + lhalf) * 16;
            int sw = off ^ ((off >> 3) & 0x70);
            LDSM4(af[mi][0], af[mi][1], af[mi][2], af[mi][3], smb + sw);
        }
        uint32_t bw[4][2];
#pragma unroll
        for (int nj2 = 0; nj2 < 2; nj2++) {
            int row = wn + nj2 * 16 + lrow;
            int off = row * 128 + (ks * 2 + lhalf) * 16;
            int sw = off ^ ((off >> 3) & 0x70);
            uint32_t r0, r1, r2, r3;
            LDSM4(r0, r1, r2, r3, smb + 16384 + sw);
            bw[nj2*2+0][0] = r0; bw[nj2*2+0][1] = r2;
            bw[nj2*2+1][0] = r1; bw[nj2*2+1][1] = r3;
        }
#pragma unroll
        for (int mi = 0; mi < 2; mi++)
#pragma unroll
            for (int nj = 0; nj < 4; nj++)
                MMA_F16(acc[mi][nj], af[mi], bw[nj]);
    }

#pragma unroll
    for (int mi = 0; mi < 2; mi++)
#pragma unroll
        for (int nj = 0; nj < 4; nj++) {
            int n = wn + nj * 8 + 2 * (lane & 3);
#pragma unroll
            for (int r = 0; r < 2; r++) {
                int m = wm + mi * 16 + (lane >> 2) + r * 8;
                size_t o = (size_t)(b * Ll + lt + m) * 512 + h * 64 + n;
                unsigned short h0 = __half_as_ushort(__float2half_rn(acc[mi][nj][r*2+0]));
                unsigned short h1 = __half_as_ushort(__float2half_rn(acc[mi][nj][r*2+1]));
                *(uint32_t*)((unsigned short*)att + o) = (uint32_t)h0 | ((uint32_t)h1 << 16);
            }
        }
}

// ------------------------------- driver ---------------------------------------
extern "C" void kernel_launch(void* const* d_in, const int* in_sizes, int n_in,
                              void* d_out, int out_size)
{
    const float* x     = (const float*)d_in[0];
    const float* v     = (const float*)d_in[1];
    const float* ln1w  = (const float*)d_in[4];
    const float* ln1b  = (const float*)d_in[5];
    const float* lnvw  = (const float*)d_in[6];
    const float* lnvb  = (const float*)d_in[7];
    const float* ln2w  = (const float*)d_in[8];
    const float* ln2b  = (const float*)d_in[9];
    const float* wq    = (const float*)d_in[10];
    const float* bq    = (const float*)d_in[11];
    const float* wk    = (const float*)d_in[12];
    const float* bk    = (const float*)d_in[13];
    const float* wv    = (const float*)d_in[14];
    const float* bv    = (const float*)d_in[15];
    const float* wr    = (const float*)d_in[16];
    const float* br    = (const float*)d_in[17];
    const float* fc1w  = (const float*)d_in[18];
    const float* fc1b  = (const float*)d_in[19];
    const float* fc2w  = (const float*)d_in[20];
    const float* fc2b  = (const float*)d_in[21];
    float* out = (float*)d_out;

    float *p_acc, *p_bkv;
    unsigned* p_cmaxe;
    __half *p_q16, *p_kv16, *p_xn, *p_vn, *p_att, *p_h, *p_ctxT;
    __half *p_wq, *p_wkv, *p_wr, *p_f1, *p_f2;
    cudaGetSymbolAddress((void**)&p_acc, g_acc);
    cudaGetSymbolAddress((void**)&p_ctxT, g_ctxT);
    cudaGetSymbolAddress((void**)&p_cmaxe, g_cmaxe);
    cudaGetSymbolAddress((void**)&p_bkv, g_bkv);
    cudaGetSymbolAddress((void**)&p_q16, g_q16);
    cudaGetSymbolAddress((void**)&p_kv16, g_kv16);
    cudaGetSymbolAddress((void**)&p_xn,  g_xn);
    cudaGetSymbolAddress((void**)&p_vn,  g_vn);
    cudaGetSymbolAddress((void**)&p_att, g_att);
    cudaGetSymbolAddress((void**)&p_h,   g_h);
    cudaGetSymbolAddress((void**)&p_wq,  g_wq16);
    cudaGetSymbolAddress((void**)&p_wkv, g_wkv16);
    cudaGetSymbolAddress((void**)&p_wr,  g_wr16);
    cudaGetSymbolAddress((void**)&p_f1,  g_f116);
    cudaGetSymbolAddress((void**)&p_f2,  g_f216);
    float* p_ctx  = p_acc;
    float* p_csum = p_acc + Bb*HEADS*64*64;

    cudaFuncSetAttribute(gemm_mma, cudaFuncAttributeMaxDynamicSharedMemorySize, SMEM_SZ);

    dim3 g512(Cc / 128, Mm / 128);     // (4, 576)
    dim3 g1024(1024 / 128, Mm / 128);  // (8, 576)
    dim3 g2048(HID / 128, Mm / 128);   // (16, 576)

    // prologue: one convert launch + one dual-LN launch + zeroing
    convert_all<<<(4*WSZ + 2*FSZ + 1024 + 255)/256, 256>>>(
        wq, wk, wv, wr, fc1w, fc2w, bk, bv,
        p_wq, p_wkv, p_wr, p_f1, p_f2, p_bkv);
    ln_dual<<<dim3(Mm / 8, 2), 256>>>(x, v, ln1w, ln1b, lnvw, lnvb, p_xn, p_vn);
    cudaMemsetAsync(p_cmaxe, 0, (size_t)Bb*Cc*sizeof(unsigned));
    cudaMemsetAsync(p_acc, 0, (size_t)(Bb*HEADS*64*64 + Bb*Cc)*sizeof(float));

    // projections: q (fp16 out), fused k|v (fp16 out + fused column max)
    gemm_mma<<<g512, 256, SMEM_SZ>>>(p_xn, p_wq, bq, nullptr, nullptr,
                                     nullptr, p_q16, nullptr, nullptr, Cc, Cc, 0, 0);
    gemm_mma<<<g1024, 256, SMEM_SZ>>>(p_vn, p_wkv, p_bkv, nullptr, nullptr,
                                      nullptr, p_kv16, nullptr, p_cmaxe, 1024, Cc, 0, 0);

    // attention core: context(HMMA, exp in-load, csum) -> normalize -> attend
    context_hmma<<<dim3(Bb * HEADS, 8), 256>>>(p_kv16, p_cmaxe, p_csum, p_ctx);
    ctx_cvt<<<Bb * HEADS, 256>>>(p_ctx, p_csum, p_ctxT);
    attend_gemm<<<dim3(Ll / 128, Bb * HEADS), 256>>>(p_q16, p_ctxT, p_att);

    // reprojection + scramble + shortcut fused -> x1 in d_out
    gemm_mma<<<g512, 256, SMEM_SZ>>>(p_att, p_wr, br, nullptr, p_xn,
                                     out, nullptr, x, nullptr, Cc, Cc, 0, 1);

    // LN2 -> fp16 (reuse xn buffer)
    ln_half<<<Mm / 8, 256>>>(out, ln2w, ln2b, p_xn);

    // MLP: fc1 (+exact GELU, fp16 out), fc2 (+residual from d_out)
    gemm_mma<<<g2048, 256, SMEM_SZ>>>(p_xn, p_f1, fc1b, nullptr, nullptr,
                                      nullptr, p_h, nullptr, nullptr, HID, Cc, 1, 0);
    gemm_mma<<<g512, 256, SMEM_SZ>>>(p_h, p_f2, fc2b, out, nullptr,
                                     out, nullptr, nullptr, nullptr, Cc, HID, 0, 0);
}

// round 15
// speedup vs baseline: 7.9837x; 1.0279x over previous
#include <cuda_runtime.h>
#include <cuda_fp16.h>
#include <math.h>
#include <stdint.h>

#define Bb 8
#define Ll 9216
#define Cc 512
#define Mm (Bb*Ll)          // 73728
#define HEADS 8
#define HID 2048

// ---------------- scratch (device globals; no runtime allocation) -------------
__device__ __align__(16) __half g_q16[(size_t)Mm*Cc];
__device__ __align__(16) __half g_kv16[(size_t)Mm*1024];    // k | val fused
__device__ __align__(16) __half g_xn[(size_t)Mm*Cc];
__device__ __align__(16) __half g_vn[(size_t)Mm*Cc];
__device__ __align__(16) __half g_att[(size_t)Mm*Cc];
__device__ __align__(16) __half g_h [(size_t)Mm*HID];
__device__ __align__(16) __half g_wq16[Cc*Cc];
__device__ __align__(16) __half g_wkv16[2*Cc*Cc];           // wk | wv fused
__device__ __align__(16) __half g_wr16[Cc*Cc];
__device__ __align__(16) __half g_f116[HID*Cc];
__device__ __align__(16) __half g_f216[Cc*HID];
__device__ float g_bkv[1024];
__device__ float g_acc[Bb*HEADS*64*64 + Bb*Cc];             // ctx | csum (one memset)
__device__ __align__(16) __half g_ctxT[Bb*HEADS*64*64];
__device__ unsigned g_cmaxe[Bb*Cc];                         // encoded fp32 column max

// ---------------- small helpers ----------------
__device__ __forceinline__ uint32_t smem_u32(const void* p) {
    return (uint32_t)__cvta_generic_to_shared(p);
}
__device__ __forceinline__ void cp16(uint32_t dst, const void* src) {
    asm volatile("cp.async.cg.shared.global [%0], [%1], 16;" :: "r"(dst), "l"(src));
}
#define CP_COMMIT() asm volatile("cp.async.commit_group;" ::: "memory")
#define CP_WAIT(N)  asm volatile("cp.async.wait_group %0;" :: "n"(N) : "memory")

#define LDSM4(r0, r1, r2, r3, addr) \
    asm volatile("ldmatrix.sync.aligned.m8n8.x4.shared.b16 {%0,%1,%2,%3}, [%4];" \
                 : "=r"(r0), "=r"(r1), "=r"(r2), "=r"(r3) : "r"(addr))

#define LDSM4T(r0, r1, r2, r3, addr) \
    asm volatile("ldmatrix.sync.aligned.m8n8.x4.trans.shared.b16 {%0,%1,%2,%3}, [%4];" \
                 : "=r"(r0), "=r"(r1), "=r"(r2), "=r"(r3) : "r"(addr))

#define MMA_F16(d, a, b) \
    asm volatile("mma.sync.aligned.m16n8k16.row.col.f32.f16.f16.f32 " \
                 "{%0,%1,%2,%3}, {%4,%5,%6,%7}, {%8,%9}, {%0,%1,%2,%3};" \
                 : "+f"((d)[0]), "+f"((d)[1]), "+f"((d)[2]), "+f"((d)[3]) \
                 : "r"((a)[0]), "r"((a)[1]), "r"((a)[2]), "r"((a)[3]), \
                   "r"((b)[0]), "r"((b)[1]))

// order-preserving float<->uint map for atomicMax
__device__ __forceinline__ unsigned enc_f(float f) {
    unsigned u = __float_as_uint(f);
    return (u & 0x80000000u) ? ~u : (u | 0x80000000u);
}
__device__ __forceinline__ float dec_f(unsigned u) {
    u = (u & 0x80000000u) ? (u & 0x7FFFFFFFu) : ~u;
    return __uint_as_float(u);
}

// ---------------- dual LayerNorm (x->xn, v->vn) -> fp16 ------------------------
__global__ __launch_bounds__(256) void ln_dual(const float* __restrict__ xa,
                                               const float* __restrict__ xb,
                                               const float* __restrict__ wa,
                                               const float* __restrict__ ba,
                                               const float* __restrict__ wb,
                                               const float* __restrict__ bb,
                                               __half* __restrict__ ya,
                                               __half* __restrict__ yb)
{
    const float* x = blockIdx.y ? xb : xa;
    const float* w = blockIdx.y ? wb : wa;
    const float* b = blockIdx.y ? bb : ba;
    __half* y = blockIdx.y ? yb : ya;
    int row = blockIdx.x * 8 + (threadIdx.x >> 5);
    int lane = threadIdx.x & 31;
    const float* xr = x + (size_t)row * Cc;
    float4 v[4];
    float s = 0.f, s2 = 0.f;
#pragma unroll
    for (int i = 0; i < 4; i++) {
        v[i] = *(const float4*)(xr + lane * 4 + i * 128);
        s  += v[i].x + v[i].y + v[i].z + v[i].w;
        s2 += v[i].x*v[i].x + v[i].y*v[i].y + v[i].z*v[i].z + v[i].w*v[i].w;
    }
#pragma unroll
    for (int o = 16; o; o >>= 1) {
        s  += __shfl_xor_sync(0xffffffffu, s,  o);
        s2 += __shfl_xor_sync(0xffffffffu, s2, o);
    }
    float mean = s * (1.f/512.f);
    float var  = s2 * (1.f/512.f) - mean*mean;
    float rstd = rsqrtf(var + 1e-5f);
#pragma unroll
    for (int i = 0; i < 4; i++) {
        int c = lane * 4 + i * 128;
        float4 wv = *(const float4*)(w + c);
        float4 bv = *(const float4*)(b + c);
        ushort4 sh;
        sh.x = __half_as_ushort(__float2half_rn((v[i].x - mean) * rstd * wv.x + bv.x));
        sh.y = __half_as_ushort(__float2half_rn((v[i].y - mean) * rstd * wv.y + bv.y));
        sh.z = __half_as_ushort(__float2half_rn((v[i].z - mean) * rstd * wv.z + bv.z));
        sh.w = __half_as_ushort(__float2half_rn((v[i].w - mean) * rstd * wv.w + bv.w));
        *(ushort4*)(y + (size_t)row * Cc + c) = sh;
    }
}

// ---------------- single LayerNorm (LN2) -> fp16 -------------------------------
__global__ __launch_bounds__(256) void ln_half(const float* __restrict__ x,
                                               const float* __restrict__ w,
                                               const float* __restrict__ b,
                                               __half* __restrict__ y)
{
    int row = blockIdx.x * 8 + (threadIdx.x >> 5);
    int lane = threadIdx.x & 31;
    const float* xr = x + (size_t)row * Cc;
    float4 v[4];
    float s = 0.f, s2 = 0.f;
#pragma unroll
    for (int i = 0; i < 4; i++) {
        v[i] = *(const float4*)(xr + lane * 4 + i * 128);
        s  += v[i].x + v[i].y + v[i].z + v[i].w;
        s2 += v[i].x*v[i].x + v[i].y*v[i].y + v[i].z*v[i].z + v[i].w*v[i].w;
    }
#pragma unroll
    for (int o = 16; o; o >>= 1) {
        s  += __shfl_xor_sync(0xffffffffu, s,  o);
        s2 += __shfl_xor_sync(0xffffffffu, s2, o);
    }
    float mean = s * (1.f/512.f);
    float var  = s2 * (1.f/512.f) - mean*mean;
    float rstd = rsqrtf(var + 1e-5f);
#pragma unroll
    for (int i = 0; i < 4; i++) {
        int c = lane * 4 + i * 128;
        float4 wv = *(const float4*)(w + c);
        float4 bv = *(const float4*)(b + c);
        ushort4 sh;
        sh.x = __half_as_ushort(__float2half_rn((v[i].x - mean) * rstd * wv.x + bv.x));
        sh.y = __half_as_ushort(__float2half_rn((v[i].y - mean) * rstd * wv.y + bv.y));
        sh.z = __half_as_ushort(__float2half_rn((v[i].z - mean) * rstd * wv.z + bv.z));
        sh.w = __half_as_ushort(__float2half_rn((v[i].w - mean) * rstd * wv.w + bv.w));
        *(ushort4*)(y + (size_t)row * Cc + c) = sh;
    }
}

// ---------------- all weight converts + bias concat in ONE launch --------------
#define WSZ (Cc*Cc)              // 262144
#define FSZ (HID*Cc)             // 1048576
__global__ void convert_all(const float* __restrict__ wq, const float* __restrict__ wk,
                            const float* __restrict__ wv, const float* __restrict__ wr,
                            const float* __restrict__ f1, const float* __restrict__ f2,
                            const float* __restrict__ bk, const float* __restrict__ bv,
                            __half* __restrict__ owq, __half* __restrict__ owkv,
                            __half* __restrict__ owr, __half* __restrict__ of1,
                            __half* __restrict__ of2, float* __restrict__ obkv)
{
    size_t i = (size_t)blockIdx.x * 256 + threadIdx.x;
    if (i < WSZ)                owq[i] = __float2half_rn(wq[i]);
    else if (i < 2*WSZ)         owkv[i - WSZ] = __float2half_rn(wk[i - WSZ]);
    else if (i < 3*WSZ)         owkv[i - WSZ] = __float2half_rn(wv[i - 2*WSZ]);
    else if (i < 4*WSZ)         owr[i - 3*WSZ] = __float2half_rn(wr[i - 3*WSZ]);
    else if (i < 4*WSZ + FSZ)   of1[i - 4*WSZ] = __float2half_rn(f1[i - 4*WSZ]);
    else if (i < 4*WSZ + 2*FSZ) of2[i - 4*WSZ - FSZ] = __float2half_rn(f2[i - 4*WSZ - FSZ]);
    else {
        size_t j = i - 4*WSZ - 2*FSZ;
        if (j < 512)       obkv[j] = bk[j];
        else if (j < 1024) obkv[j] = bv[j - 512];
    }
}

// ------------- fp16 mma.sync GEMM, templated K, static addressing --------------
#define TILEB 16384
#define STAGEB (2*TILEB)
#define NSTAGE 3
#define SMEM_SZ (NSTAGE*STAGEB)   // 98304; also >= 128*132*4 for scram tile

template<int KD>
__global__ __launch_bounds__(256, 2) void gemm_mma(
    const __half* __restrict__ Aa,
    const __half* __restrict__ Bw,
    const float* __restrict__ bias,
    const float* __restrict__ residf,
    const __half* __restrict__ resph,
    float* __restrict__ outf,
    __half* __restrict__ outh,
    const float* __restrict__ xin,   // scramble-mode shortcut input
    unsigned* __restrict__ kmaxenc,  // fused column-max output (kv proj only)
    int Nd, int do_gelu, int scram)
{
    extern __shared__ __align__(1024) char smarr[];
    const int tid = threadIdx.x;
    const int lane = tid & 31;
    const int wid = tid >> 5;
    const int bm = blockIdx.y * 128;
    const int bn = blockIdx.x * 128;
    const int wm = (wid >> 2) * 64;
    const int wn = (wid & 3) * 32;
    const uint32_t smb = smem_u32(smarr);

    const int cpc = tid & 7;
    const int cpr = tid >> 3;

    float acc[4][4][4];
#pragma unroll
    for (int i = 0; i < 4; i++)
#pragma unroll
        for (int j = 0; j < 4; j++)
#pragma unroll
            for (int r = 0; r < 4; r++) acc[i][j][r] = 0.f;

    constexpr int nchunks = KD >> 6;
    constexpr int pstride = 32 * KD;

    // hoisted addressing (mask identity: row&7 == lane&7 for all frag rows)
    const int lrow  = (lane & 7) + ((lane >> 3) & 1) * 8;
    const int lhalf = lane >> 4;
    const uint32_t amask = (uint32_t)(lane & 7) << 4;
    uint32_t xterm[4];
#pragma unroll
    for (int ks = 0; ks < 4; ks++)
        xterm[ks] = (uint32_t)((ks * 2 + lhalf) * 16) ^ amask;
    const uint32_t aoff = (uint32_t)(wm + lrow) * 128;
    const uint32_t boff = TILEB + (uint32_t)(wn + lrow) * 128;
    const uint32_t cpbase = (uint32_t)cpr * 128
                          + ((uint32_t)(cpc * 16) ^ ((uint32_t)(cpr & 7) << 4));
    const __half* gA = Aa + (size_t)(bm + cpr) * KD + cpc * 8;
    const __half* gB = Bw + (size_t)(bn + cpr) * KD + cpc * 8;

    // ---- prologue: stages 0,1
#pragma unroll
    for (int st = 0; st < 2; st++) {
        uint32_t sb = smb + st * STAGEB + cpbase;
#pragma unroll
        for (int p = 0; p < 4; p++) {
            cp16(sb + p * 4096,         gA + p * pstride);
            cp16(sb + TILEB + p * 4096, gB + p * pstride);
        }
        CP_COMMIT();
        gA += 64; gB += 64;
    }

    int stage = 0;
#pragma unroll 3
    for (int kc = 0; kc < nchunks; kc++) {
        if (kc + 1 < nchunks) { CP_WAIT(1); } else { CP_WAIT(0); }
        __syncthreads();

        if (kc + 2 < nchunks) {
            int st2 = stage + 2; if (st2 >= NSTAGE) st2 -= NSTAGE;
            uint32_t sb = smb + st2 * STAGEB + cpbase;
#pragma unroll
            for (int p = 0; p < 4; p++) {
                cp16(sb + p * 4096,         gA + p * pstride);
                cp16(sb + TILEB + p * 4096, gB + p * pstride);
            }
            CP_COMMIT();
            gA += 64; gB += 64;
        }

        const uint32_t sb = smb + stage * STAGEB;
        const uint32_t sbA = sb + aoff;
        const uint32_t sbB = sb + boff;
#pragma unroll
        for (int ks = 0; ks < 4; ks++) {
            const uint32_t xt = xterm[ks];
            uint32_t af[4][4];
#pragma unroll
            for (int mi = 0; mi < 4; mi++)
                LDSM4(af[mi][0], af[mi][1], af[mi][2], af[mi][3],
                      sbA + mi * 2048 + xt);
            uint32_t bw[4][2];
#pragma unroll
            for (int nj2 = 0; nj2 < 2; nj2++) {
                uint32_t r0, r1, r2, r3;
                LDSM4(r0, r1, r2, r3, sbB + nj2 * 2048 + xt);
                bw[nj2*2+0][0] = r0; bw[nj2*2+0][1] = r2;
                bw[nj2*2+1][0] = r1; bw[nj2*2+1][1] = r3;
            }
#pragma unroll
            for (int mi = 0; mi < 4; mi++)
#pragma unroll
                for (int nj = 0; nj < 4; nj++)
                    MMA_F16(acc[mi][nj], af[mi], bw[nj]);
        }
        if (++stage >= NSTAGE) stage = 0;
    }

    if (!scram) {
        float colmax[4][2];
#pragma unroll
        for (int nj = 0; nj < 4; nj++) { colmax[nj][0] = -1e30f; colmax[nj][1] = -1e30f; }
#pragma unroll
        for (int mi = 0; mi < 4; mi++)
#pragma unroll
            for (int nj = 0; nj < 4; nj++) {
                int n = bn + wn + nj * 8 + 2 * (lane & 3);
                float b0 = bias[n], b1 = bias[n + 1];
#pragma unroll
                for (int r = 0; r < 2; r++) {
                    int m = bm + wm + mi * 16 + (lane >> 2) + r * 8;
                    size_t idx = (size_t)m * Nd + n;
                    float v0 = acc[mi][nj][r*2+0] + b0;
                    float v1 = acc[mi][nj][r*2+1] + b1;
                    if (residf) {
                        float2 rr = *(const float2*)(residf + idx);
                        v0 += rr.x; v1 += rr.y;
                    }
                    if (resph) {
                        uint32_t ph = *(const uint32_t*)((const unsigned short*)resph + idx);
                        v0 += __half2float(__ushort_as_half((unsigned short)(ph & 0xffff)));
                        v1 += __half2float(__ushort_as_half((unsigned short)(ph >> 16)));
                    }
                    colmax[nj][0] = fmaxf(colmax[nj][0], v0);
                    colmax[nj][1] = fmaxf(colmax[nj][1], v1);
                    if (do_gelu) {
                        v0 = 0.5f * v0 * (1.f + erff(v0 * 0.70710678118654752f));
                        v1 = 0.5f * v1 * (1.f + erff(v1 * 0.70710678118654752f));
                    }
                    if (outf) *(float2*)(outf + idx) = make_float2(v0, v1);
                    if (outh) {
                        unsigned short h0 = __half_as_ushort(__float2half_rn(v0));
                        unsigned short h1 = __half_as_ushort(__float2half_rn(v1));
                        *(uint32_t*)((unsigned short*)outh + idx) =
                            (uint32_t)h0 | ((uint32_t)h1 << 16);
                    }
                }
            }
        if (kmaxenc && bn < 512) {
            int b = bm / Ll;
#pragma unroll
            for (int nj = 0; nj < 4; nj++) {
                float m0 = colmax[nj][0], m1 = colmax[nj][1];
#pragma unroll
                for (int o = 4; o < 32; o <<= 1) {
                    m0 = fmaxf(m0, __shfl_xor_sync(0xffffffffu, m0, o));
                    m1 = fmaxf(m1, __shfl_xor_sync(0xffffffffu, m1, o));
                }
                if (lane < 4) {
                    int n = bn + wn + nj * 8 + 2 * lane;
                    atomicMax(&kmaxenc[b * 512 + n],     enc_f(m0));
                    atomicMax(&kmaxenc[b * 512 + n + 1], enc_f(m1));
                }
            }
        }
    } else {
        // ------- scramble epilogue: x1.flat[b, (bn+n)*Ll + l] = v + x.flat ------
        __syncthreads();
        float (*tile)[132] = (float(*)[132])smarr;
#pragma unroll
        for (int mi = 0; mi < 4; mi++)
#pragma unroll
            for (int nj = 0; nj < 4; nj++) {
                int nl = wn + nj * 8 + 2 * (lane & 3);
                float b0 = bias[bn + nl], b1 = bias[bn + nl + 1];
#pragma unroll
                for (int r = 0; r < 2; r++) {
                    int ml = wm + mi * 16 + (lane >> 2) + r * 8;
                    size_t idx = (size_t)(bm + ml) * Nd + bn + nl;
                    uint32_t ph = *(const uint32_t*)((const unsigned short*)resph + idx);
                    float v0 = acc[mi][nj][r*2+0] + b0
                             + __half2float(__ushort_as_half((unsigned short)(ph & 0xffff)));
                    float v1 = acc[mi][nj][r*2+1] + b1
                             + __half2float(__ushort_as_half((unsigned short)(ph >> 16)));
                    tile[nl][ml]     = v0;
                    tile[nl + 1][ml] = v1;
                }
            }
        __syncthreads();
        const int b = bm / Ll;
        const int l0 = bm % Ll;
        const int c = tid >> 1;
        const int part = tid & 1;
        size_t base = (size_t)b * Cc * Ll + (size_t)(bn + c) * Ll + l0 + part * 64;
        const float* xb = xin + base;
        float* ob = outf + base;
#pragma unroll
        for (int j = 0; j < 16; j++) {
            float4 t4 = *(const float4*)&tile[c][part * 64 + j * 4];
            float4 x4 = *(const float4*)(xb + j * 4);
            t4.x += x4.x; t4.y += x4.y; t4.z += x4.z; t4.w += x4.w;
            *(float4*)(ob + j * 4) = t4;
        }
    }
}

// -------- context via HMMA: exp in-load, csum partials, trans ldmatrix ---------
__global__ __launch_bounds__(256) void context_hmma(const __half* __restrict__ kv,
                                                    const unsigned* __restrict__ cmaxe,
                                                    float* __restrict__ csum,
                                                    float* __restrict__ ctx)
{
    __shared__ __align__(1024) char sm[16384 + 256];
    const int bh = blockIdx.x;
    const int b = bh >> 3, h = bh & 7;
    const int ch0 = h * 64;
    const int seg = blockIdx.y;
    const int SEG = Ll / 8;            // 1152
    const int tid = threadIdx.x;
    const int lane = tid & 31;
    const int wid = tid >> 5;
    const uint32_t smb = smem_u32(sm);
    float* ssum = (float*)(sm + 16384);
    if (tid < 64) ssum[tid] = 0.f;

    const int ckc = tid & 7;
    float mx[8];
#pragma unroll
    for (int j = 0; j < 8; j++) mx[j] = dec_f(cmaxe[b * Cc + ch0 + ckc * 8 + j]);
    float facc[8];
#pragma unroll
    for (int j = 0; j < 8; j++) facc[j] = 0.f;

    const int wm_kc = (wid >> 1) * 16;
    const int wn_vc = (wid & 1) * 32;
    float accc[4][4];
#pragma unroll
    for (int i = 0; i < 4; i++)
#pragma unroll
        for (int r = 0; r < 4; r++) accc[i][r] = 0.f;

    for (int l0 = seg * SEG; l0 < (seg + 1) * SEG; l0 += 64) {
        __syncthreads();
#pragma unroll
        for (int p = 0; p < 2; p++) {
            int idx = tid + p * 256;
            int r = idx >> 3;
            size_t goff = ((size_t)(b * Ll) + l0 + r) * 1024 + ch0 + ckc * 8;
            uint4 u = *(const uint4*)(kv + goff);
            const __half* hp = (const __half*)&u;
            __half eo[8];
#pragma unroll
            for (int j = 0; j < 8; j++) {
                float e = expf(__half2float(hp[j]) - mx[j]);
                __half hh = __float2half_rn(e);
                eo[j] = hh;
                facc[j] += __half2float(hh);
            }
            int off = r * 128 + ckc * 16;
            int sw = off ^ ((off >> 3) & 0x70);
            *(uint4*)(sm + sw) = *(const uint4*)eo;
            *(uint4*)(sm + 8192 + sw) = *(const uint4*)(kv + goff + 512);
        }
        __syncthreads();

#pragma unroll
        for (int ks = 0; ks < 4; ks++) {
            int row_l = ks * 16 + (lane & 7) + (lane >> 4) * 8;
            int hsel = (lane >> 3) & 1;
            uint32_t af[4];
            {
                int off = row_l * 128 + (wm_kc + hsel * 8) * 2;
                int sw = off ^ ((off >> 3) & 0x70);
                LDSM4T(af[0], af[1], af[2], af[3], smb + sw);
            }
            uint32_t bw[4][2];
#pragma unroll
            for (int nj2 = 0; nj2 < 2; nj2++) {
                int off = row_l * 128 + (wn_vc + nj2 * 16 + hsel * 8) * 2;
                int sw = off ^ ((off >> 3) & 0x70);
                uint32_t r0, r1, r2, r3;
                LDSM4T(r0, r1, r2, r3, smb + 8192 + sw);
                bw[nj2*2+0][0] = r0; bw[nj2*2+0][1] = r2;
                bw[nj2*2+1][0] = r1; bw[nj2*2+1][1] = r3;
            }
#pragma unroll
            for (int nj = 0; nj < 4; nj++)
                MMA_F16(accc[nj], af, bw[nj]);
        }
    }

#pragma unroll
    for (int j = 0; j < 8; j++) atomicAdd(&ssum[ckc * 8 + j], facc[j]);
    __syncthreads();
    if (tid < 64) atomicAdd(&csum[b * Cc + ch0 + tid], ssum[tid]);

#pragma unroll
    for (int nj = 0; nj < 4; nj++) {
        int vc = wn_vc + nj * 8 + 2 * (lane & 3);
#pragma unroll
        for (int r = 0; r < 2; r++) {
            int kc = wm_kc + (lane >> 2) + r * 8;
            atomicAdd(&ctx[(size_t)bh * 4096 + kc * 64 + vc],     accc[nj][r*2+0]);
            atomicAdd(&ctx[(size_t)bh * 4096 + kc * 64 + vc + 1], accc[nj][r*2+1]);
        }
    }
}

// -------- ctx fp32 [kc][vc] -> fp16 transposed [vc][kc], with 1/csum[kc] -------
__global__ void ctx_cvt(const float* __restrict__ ctx,
                        const float* __restrict__ csum,
                        __half* __restrict__ ctxT)
{
    int bh = blockIdx.x;
    int b = bh >> 3, h = bh & 7;
    for (int i = threadIdx.x; i < 4096; i += 256) {
        int vc = i >> 6, kc = i & 63;
        float inv = 1.f / csum[b * Cc + h * 64 + kc];
        ctxT[(size_t)bh * 4096 + i] =
            __float2half_rn(ctx[(size_t)bh * 4096 + kc * 64 + vc] * inv);
    }
}

// -------- attend: in-smem q softmax + [128x64] @ ctxT[64x64] via mma -----------
__global__ __launch_bounds__(256) void attend_gemm(const __half* __restrict__ q,
                                                   const __half* __restrict__ ctxT,
                                                   __half* __restrict__ att)
{
    __shared__ __align__(1024) char sm[16384 + 8192];
    const int tid = threadIdx.x;
    const int lane = tid & 31;
    const int wid = tid >> 5;
    const int bh = blockIdx.y;
    const int b = bh >> 3, h = bh & 7;
    const int lt = blockIdx.x * 128;
    const uint32_t smb = smem_u32(sm);

#pragma unroll
    for (int p = 0; p < 4; p++) {
        int idx = tid + p * 256;
        int r = idx >> 3, c16 = idx & 7;
        int off = r * 128 + c16 * 16;
        int sw = off ^ ((off >> 3) & 0x70);
        cp16(smb + sw, q + (size_t)(b * Ll + lt + r) * 512 + h * 64 + c16 * 8);
    }
#pragma unroll
    for (int p = 0; p < 2; p++) {
        int idx = tid + p * 256;
        int r = idx >> 3, c16 = idx & 7;
        int off = r * 128 + c16 * 16;
        int sw = off ^ ((off >> 3) & 0x70);
        cp16(smb + 16384 + sw, ctxT + (size_t)bh * 4096 + r * 64 + c16 * 8);
    }
    CP_COMMIT(); CP_WAIT(0);
    __syncthreads();

    if (tid < 128) {
        float vals[64];
#pragma unroll
        for (int c16 = 0; c16 < 8; c16++) {
            int off = tid * 128 + c16 * 16;
            int sw = off ^ ((off >> 3) & 0x70);
            uint4 u = *(const uint4*)(sm + sw);
            const __half* hp = (const __half*)&u;
#pragma unroll
            for (int t = 0; t < 8; t++) vals[c16*8 + t] = __half2float(hp[t]);
        }
        float m = vals[0];
#pragma unroll
        for (int i = 1; i < 64; i++) m = fmaxf(m, vals[i]);
        float s = 0.f;
#pragma unroll
        for (int i = 0; i < 64; i++) { vals[i] = expf(vals[i] - m); s += vals[i]; }
        float inv = 1.f / s;
#pragma unroll
        for (int c16 = 0; c16 < 8; c16++) {
            int off = tid * 128 + c16 * 16;
            int sw = off ^ ((off >> 3) & 0x70);
            __half hv[8];
#pragma unroll
            for (int t = 0; t < 8; t++) hv[t] = __float2half_rn(vals[c16*8 + t] * inv);
            *(uint4*)(sm + sw) = *(const uint4*)hv;
        }
    }
    __syncthreads();

    const int wm = (wid >> 1) * 32;
    const int wn = (wid & 1) * 32;
    const int lrow = (lane & 7) + ((lane >> 3) & 1) * 8;
    const int lhalf = lane >> 4;
    float acc[2][4][4];
#pragma unroll
    for (int i = 0; i < 2; i++)
#pragma unroll
        for (int j = 0; j < 4; j++)
#pragma unroll
            for (int r = 0; r < 4; r++) acc[i][j][r] = 0.f;

#pragma unroll
    for (int ks = 0; ks < 4; ks++) {
        uint32_t af[2][4];
#pragma unroll
        for (int mi = 0; mi < 2; mi++) {
            int row = wm + mi * 16 + lrow;
            int off = row * 128 + (ks * 2 + lhalf) * 16;
            int sw = off ^ ((off >> 3) & 0x70);
            LDSM4(af[mi][0], af[mi][1], af[mi][2], af[mi][3], smb + sw);
        }
        uint32_t bw[4][2];
#pragma unroll
        for (int nj2 = 0; nj2 < 2; nj2++) {
            int row = wn + nj2 * 16 + lrow;
            int off = row * 128 + (ks * 2 + lhalf) * 16;
            int sw = off ^ ((off >> 3) & 0x70);
            uint32_t r0, r1, r2, r3;
            LDSM4(r0, r1, r2, r3, smb + 16384 + sw);
            bw[nj2*2+0][0] = r0; bw[nj2*2+0][1] = r2;
            bw[nj2*2+1][0] = r1; bw[nj2*2+1][1] = r3;
        }
#pragma unroll
        for (int mi = 0; mi < 2; mi++)
#pragma unroll
            for (int nj = 0; nj < 4; nj++)
                MMA_F16(acc[mi][nj], af[mi], bw[nj]);
    }

#pragma unroll
    for (int mi = 0; mi < 2; mi++)
#pragma unroll
        for (int nj = 0; nj < 4; nj++) {
            int n = wn + nj * 8 + 2 * (lane & 3);
#pragma unroll
            for (int r = 0; r < 2; r++) {
                int m = wm + mi * 16 + (lane >> 2) + r * 8;
                size_t o = (size_t)(b * Ll + lt + m) * 512 + h * 64 + n;
                unsigned short h0 = __half_as_ushort(__float2half_rn(acc[mi][nj][r*2+0]));
                unsigned short h1 = __half_as_ushort(__float2half_rn(acc[mi][nj][r*2+1]));
                *(uint32_t*)((unsigned short*)att + o) = (uint32_t)h0 | ((uint32_t)h1 << 16);
            }
        }
}

// ------------------------------- driver ---------------------------------------
extern "C" void kernel_launch(void* const* d_in, const int* in_sizes, int n_in,
                              void* d_out, int out_size)
{
    const float* x     = (const float*)d_in[0];
    const float* v     = (const float*)d_in[1];
    const float* ln1w  = (const float*)d_in[4];
    const float* ln1b  = (const float*)d_in[5];
    const float* lnvw  = (const float*)d_in[6];
    const float* lnvb  = (const float*)d_in[7];
    const float* ln2w  = (const float*)d_in[8];
    const float* ln2b  = (const float*)d_in[9];
    const float* wq    = (const float*)d_in[10];
    const float* bq    = (const float*)d_in[11];
    const float* wk    = (const float*)d_in[12];
    const float* bk    = (const float*)d_in[13];
    const float* wv    = (const float*)d_in[14];
    const float* bv    = (const float*)d_in[15];
    const float* wr    = (const float*)d_in[16];
    const float* br    = (const float*)d_in[17];
    const float* fc1w  = (const float*)d_in[18];
    const float* fc1b  = (const float*)d_in[19];
    const float* fc2w  = (const float*)d_in[20];
    const float* fc2b  = (const float*)d_in[21];
    float* out = (float*)d_out;

    float *p_acc, *p_bkv;
    unsigned* p_cmaxe;
    __half *p_q16, *p_kv16, *p_xn, *p_vn, *p_att, *p_h, *p_ctxT;
    __half *p_wq, *p_wkv, *p_wr, *p_f1, *p_f2;
    cudaGetSymbolAddress((void**)&p_acc, g_acc);
    cudaGetSymbolAddress((void**)&p_ctxT, g_ctxT);
    cudaGetSymbolAddress((void**)&p_cmaxe, g_cmaxe);
    cudaGetSymbolAddress((void**)&p_bkv, g_bkv);
    cudaGetSymbolAddress((void**)&p_q16, g_q16);
    cudaGetSymbolAddress((void**)&p_kv16, g_kv16);
    cudaGetSymbolAddress((void**)&p_xn,  g_xn);
    cudaGetSymbolAddress((void**)&p_vn,  g_vn);
    cudaGetSymbolAddress((void**)&p_att, g_att);
    cudaGetSymbolAddress((void**)&p_h,   g_h);
    cudaGetSymbolAddress((void**)&p_wq,  g_wq16);
    cudaGetSymbolAddress((void**)&p_wkv, g_wkv16);
    cudaGetSymbolAddress((void**)&p_wr,  g_wr16);
    cudaGetSymbolAddress((void**)&p_f1,  g_f116);
    cudaGetSymbolAddress((void**)&p_f2,  g_f216);
    float* p_ctx  = p_acc;
    float* p_csum = p_acc + Bb*HEADS*64*64;

    cudaFuncSetAttribute(gemm_mma<512>,  cudaFuncAttributeMaxDynamicSharedMemorySize, SMEM_SZ);
    cudaFuncSetAttribute(gemm_mma<2048>, cudaFuncAttributeMaxDynamicSharedMemorySize, SMEM_SZ);

    dim3 g512(Cc / 128, Mm / 128);     // (4, 576)
    dim3 g1024(1024 / 128, Mm / 128);  // (8, 576)
    dim3 g2048(HID / 128, Mm / 128);   // (16, 576)

    // prologue: one convert launch + one dual-LN launch + zeroing
    convert_all<<<(4*WSZ + 2*FSZ + 1024 + 255)/256, 256>>>(
        wq, wk, wv, wr, fc1w, fc2w, bk, bv,
        p_wq, p_wkv, p_wr, p_f1, p_f2, p_bkv);
    ln_dual<<<dim3(Mm / 8, 2), 256>>>(x, v, ln1w, ln1b, lnvw, lnvb, p_xn, p_vn);
    cudaMemsetAsync(p_cmaxe, 0, (size_t)Bb*Cc*sizeof(unsigned));
    cudaMemsetAsync(p_acc, 0, (size_t)(Bb*HEADS*64*64 + Bb*Cc)*sizeof(float));

    // projections: q (fp16 out), fused k|v (fp16 out + fused column max)
    gemm_mma<512><<<g512, 256, SMEM_SZ>>>(p_xn, p_wq, bq, nullptr, nullptr,
                                          nullptr, p_q16, nullptr, nullptr, Cc, 0, 0);
    gemm_mma<512><<<g1024, 256, SMEM_SZ>>>(p_vn, p_wkv, p_bkv, nullptr, nullptr,
                                           nullptr, p_kv16, nullptr, p_cmaxe, 1024, 0, 0);

    // attention core: context(HMMA, exp in-load, csum) -> normalize -> attend
    context_hmma<<<dim3(Bb * HEADS, 8), 256>>>(p_kv16, p_cmaxe, p_csum, p_ctx);
    ctx_cvt<<<Bb * HEADS, 256>>>(p_ctx, p_csum, p_ctxT);
    attend_gemm<<<dim3(Ll / 128, Bb * HEADS), 256>>>(p_q16, p_ctxT, p_att);

    // reprojection + scramble + shortcut fused -> x1 in d_out
    gemm_mma<512><<<g512, 256, SMEM_SZ>>>(p_att, p_wr, br, nullptr, p_xn,
                                          out, nullptr, x, nullptr, Cc, 0, 1);

    // LN2 -> fp16 (reuse xn buffer)
    ln_half<<<Mm / 8, 256>>>(out, ln2w, ln2b, p_xn);

    // MLP: fc1 (+exact GELU, fp16 out), fc2 (+residual from d_out)
    gemm_mma<512><<<g2048, 256, SMEM_SZ>>>(p_xn, p_f1, fc1b, nullptr, nullptr,
                                           nullptr, p_h, nullptr, nullptr, HID, 1, 0);
    gemm_mma<2048><<<g512, 256, SMEM_SZ>>>(p_h, p_f2, fc2b, out, nullptr,
                                           out, nullptr, nullptr, nullptr, Cc, 0, 0);
}